// round 1
// baseline (speedup 1.0000x reference)
#include <cuda_runtime.h>
#include <math.h>

// Problem constants
#define Bq   32
#define Tq   40
#define Pq   12
#define Eq   2048
#define Hq   1024
#define BP   384          // B*P
#define NROWS 15360       // B*T*P
#define GXW  3072         // 3*H

// Scratch (device globals: allocation-free rule)
__device__ float g_X [(size_t)NROWS * Hq];   // embedded+tanh  [B,T,P,H]
__device__ float g_GX[(size_t)NROWS * GXW];  // input gates    [B,T,P,3H]
__device__ float g_H [(size_t)Tq * BP * Hq]; // hiddens        [T,B,P,H]

// ---------------------------------------------------------------------------
// Generic NT SGEMM: C[M,N] = act(A[M,K] @ B[N,K]^T + bias[N])
// BM=BN=128, BK=16, 256 threads, 8x8 per thread. M%128==0, N%128==0, K%16==0.
// ACT: 0 = none, 1 = tanh
// ---------------------------------------------------------------------------
template<int ACT>
__global__ __launch_bounds__(256) void gemm_nt128(
    const float* __restrict__ A, const float* __restrict__ Bm,
    const float* __restrict__ bias, float* __restrict__ C,
    int M, int N, int K)
{
    __shared__ float As[16][132];
    __shared__ float Bs[16][132];

    const int tid = threadIdx.x;
    const int tx  = tid & 15;    // 0..15 -> col group
    const int ty  = tid >> 4;    // 0..15 -> row group

    // loader mapping: each thread loads 8 consecutive K-floats of one row
    const int lr = tid >> 1;          // 0..127
    const int lc = (tid & 1) * 8;     // 0 or 8

    const float* Ap = A  + (size_t)blockIdx.y * 128 * K + (size_t)lr * K + lc;
    const float* Bp = Bm + (size_t)blockIdx.x * 128 * K + (size_t)lr * K + lc;

    float acc[8][8] = {};

    for (int k0 = 0; k0 < K; k0 += 16) {
        float4 a0 = *(const float4*)(Ap + k0);
        float4 a1 = *(const float4*)(Ap + k0 + 4);
        float4 b0 = *(const float4*)(Bp + k0);
        float4 b1 = *(const float4*)(Bp + k0 + 4);

        __syncthreads();   // previous tile fully consumed
        As[lc+0][lr]=a0.x; As[lc+1][lr]=a0.y; As[lc+2][lr]=a0.z; As[lc+3][lr]=a0.w;
        As[lc+4][lr]=a1.x; As[lc+5][lr]=a1.y; As[lc+6][lr]=a1.z; As[lc+7][lr]=a1.w;
        Bs[lc+0][lr]=b0.x; Bs[lc+1][lr]=b0.y; Bs[lc+2][lr]=b0.z; Bs[lc+3][lr]=b0.w;
        Bs[lc+4][lr]=b1.x; Bs[lc+5][lr]=b1.y; Bs[lc+6][lr]=b1.z; Bs[lc+7][lr]=b1.w;
        __syncthreads();

        #pragma unroll
        for (int kk = 0; kk < 16; kk++) {
            float ar[8], br[8];
            *(float4*)(ar)   = *(const float4*)&As[kk][ty*8];
            *(float4*)(ar+4) = *(const float4*)&As[kk][ty*8+4];
            *(float4*)(br)   = *(const float4*)&Bs[kk][tx*8];
            *(float4*)(br+4) = *(const float4*)&Bs[kk][tx*8+4];
            #pragma unroll
            for (int i = 0; i < 8; i++)
                #pragma unroll
                for (int j = 0; j < 8; j++)
                    acc[i][j] = fmaf(ar[i], br[j], acc[i][j]);
        }
    }

    const int row0 = blockIdx.y * 128 + ty * 8;
    const int col0 = blockIdx.x * 128 + tx * 8;
    #pragma unroll
    for (int i = 0; i < 8; i++) {
        #pragma unroll
        for (int j = 0; j < 8; j++) {
            float v = acc[i][j] + bias[col0 + j];
            if (ACT == 1) v = tanhf(v);
            C[(size_t)(row0 + i) * N + (col0 + j)] = v;
        }
    }
}

// ---------------------------------------------------------------------------
// One GRU timestep, fully fused:
//   gh[g] = hprev @ Whh[g]^T    (3 gate GEMMs sharing the A operand)
//   r = sig(xr+hr); z = sig(xz+hz); n = tanh(xn + r*hn)
//   hout = (1-z)*n + z*hprev
// Tile: 64 rows x 64 h-cols, BK=16, 256 threads, 4x4x3 accumulators.
// Grid (16, 6). first==1: h_prev == 0 -> skip the entire K loop.
// ---------------------------------------------------------------------------
__global__ __launch_bounds__(256) void gru_step(
    const float* __restrict__ hprev, const float* __restrict__ Whh,
    const float* __restrict__ gx,    const float* __restrict__ bhh,
    float* __restrict__ hout, int t, int first)
{
    __shared__ float Hs[16][68];
    __shared__ float Ws[3][16][68];

    const int tid  = threadIdx.x;
    const int tx   = tid & 15;   // col group (4 cols)
    const int ty   = tid >> 4;   // row group (4 rows)
    const int row0 = blockIdx.y * 64;
    const int col0 = blockIdx.x * 64;

    float acc[3][4][4] = {};

    if (!first) {
        const int lr = tid >> 2;        // 0..63
        const int lc = (tid & 3) * 4;   // 0,4,8,12
        const float* Hp  = hprev + (size_t)(row0 + lr) * Hq + lc;
        const float* Wp0 = Whh + (size_t)(col0 + lr) * Hq + lc;
        const float* Wp1 = Wp0 + (size_t)Hq * Hq;
        const float* Wp2 = Wp1 + (size_t)Hq * Hq;

        for (int k0 = 0; k0 < Hq; k0 += 16) {
            float4 hv = *(const float4*)(Hp  + k0);
            float4 w0 = *(const float4*)(Wp0 + k0);
            float4 w1 = *(const float4*)(Wp1 + k0);
            float4 w2 = *(const float4*)(Wp2 + k0);

            __syncthreads();
            Hs[lc+0][lr]=hv.x; Hs[lc+1][lr]=hv.y; Hs[lc+2][lr]=hv.z; Hs[lc+3][lr]=hv.w;
            Ws[0][lc+0][lr]=w0.x; Ws[0][lc+1][lr]=w0.y; Ws[0][lc+2][lr]=w0.z; Ws[0][lc+3][lr]=w0.w;
            Ws[1][lc+0][lr]=w1.x; Ws[1][lc+1][lr]=w1.y; Ws[1][lc+2][lr]=w1.z; Ws[1][lc+3][lr]=w1.w;
            Ws[2][lc+0][lr]=w2.x; Ws[2][lc+1][lr]=w2.y; Ws[2][lc+2][lr]=w2.z; Ws[2][lc+3][lr]=w2.w;
            __syncthreads();

            #pragma unroll
            for (int kk = 0; kk < 16; kk++) {
                float a[4], br[4], bz[4], bn[4];
                *(float4*)a  = *(const float4*)&Hs[kk][ty*4];
                *(float4*)br = *(const float4*)&Ws[0][kk][tx*4];
                *(float4*)bz = *(const float4*)&Ws[1][kk][tx*4];
                *(float4*)bn = *(const float4*)&Ws[2][kk][tx*4];
                #pragma unroll
                for (int i = 0; i < 4; i++) {
                    #pragma unroll
                    for (int j = 0; j < 4; j++) {
                        acc[0][i][j] = fmaf(a[i], br[j], acc[0][i][j]);
                        acc[1][i][j] = fmaf(a[i], bz[j], acc[1][i][j]);
                        acc[2][i][j] = fmaf(a[i], bn[j], acc[2][i][j]);
                    }
                }
            }
        }
    }

    // fused gate epilogue
    #pragma unroll
    for (int i = 0; i < 4; i++) {
        const int m  = row0 + ty * 4 + i;          // 0..383 (b*12+p)
        const int bb = m / Pq;
        const int pp = m - bb * Pq;
        const float* gxr = gx + ((size_t)(bb * Tq + t) * Pq + pp) * GXW;
        #pragma unroll
        for (int j = 0; j < 4; j++) {
            const int c = col0 + tx * 4 + j;
            float xr = gxr[c];
            float xz = gxr[c + Hq];
            float xn = gxr[c + 2 * Hq];
            float hr = acc[0][i][j] + bhh[c];
            float hz = acc[1][i][j] + bhh[c + Hq];
            float hn = acc[2][i][j] + bhh[c + 2 * Hq];
            float r  = 1.0f / (1.0f + expf(-(xr + hr)));
            float z  = 1.0f / (1.0f + expf(-(xz + hz)));
            float n  = tanhf(fmaf(r, hn, xn));
            float hp = first ? 0.0f : hprev[(size_t)m * Hq + c];
            hout[(size_t)m * Hq + c] = fmaf(z, hp - n, n);
        }
    }
}

// ---------------------------------------------------------------------------
// Heads: warp-per-row dot products with shfl reductions.
// ---------------------------------------------------------------------------
__global__ __launch_bounds__(256) void action_head(
    const float* __restrict__ hid, const float* __restrict__ Wact,
    const float* __restrict__ bact, float* __restrict__ out)
{
    const int warp = (blockIdx.x * blockDim.x + threadIdx.x) >> 5;
    const int lane = threadIdx.x & 31;
    if (warp >= NROWS) return;
    const int n  = warp;                  // flatten order (b,t,p)
    const int bb = n / (Tq * Pq);
    const int rm = n - bb * (Tq * Pq);
    const int tt = rm / Pq;
    const int pp = rm - tt * Pq;
    const float* h = hid + ((size_t)tt * BP + bb * Pq + pp) * Hq;

    float s[9] = {};
    for (int k = lane; k < Hq; k += 32) {
        const float hv = h[k];
        #pragma unroll
        for (int a = 0; a < 9; a++) s[a] = fmaf(hv, Wact[a * Hq + k], s[a]);
    }
    #pragma unroll
    for (int a = 0; a < 9; a++)
        #pragma unroll
        for (int off = 16; off; off >>= 1)
            s[a] += __shfl_xor_sync(0xFFFFFFFFu, s[a], off);
    if (lane < 9) out[(size_t)n * 9 + lane] = s[lane] + bact[lane];
}

__global__ __launch_bounds__(256) void activity_head(
    const float* __restrict__ hid, const float* __restrict__ Wactv,
    const float* __restrict__ bactv, float* __restrict__ out)
{
    const int warp = (blockIdx.x * blockDim.x + threadIdx.x) >> 5;
    const int lane = threadIdx.x & 31;
    if (warp >= Bq * Tq) return;
    const int bb = warp / Tq;
    const int tt = warp - bb * Tq;
    const float* base = hid + ((size_t)tt * BP + bb * Pq) * Hq;

    float s[8] = {};
    for (int k = lane; k < Hq; k += 32) {
        float mx = base[k];
        #pragma unroll
        for (int p = 1; p < Pq; p++) mx = fmaxf(mx, base[(size_t)p * Hq + k]);
        #pragma unroll
        for (int a = 0; a < 8; a++) s[a] = fmaf(mx, Wactv[a * Hq + k], s[a]);
    }
    #pragma unroll
    for (int a = 0; a < 8; a++)
        #pragma unroll
        for (int off = 16; off; off >>= 1)
            s[a] += __shfl_xor_sync(0xFFFFFFFFu, s[a], off);
    if (lane < 8) out[(size_t)warp * 8 + lane] = s[lane] + bactv[lane];
}

// ---------------------------------------------------------------------------
extern "C" void kernel_launch(void* const* d_in, const int* in_sizes, int n_in,
                              void* d_out, int out_size)
{
    const float* feature = (const float*)d_in[0];
    const float* W_embed = (const float*)d_in[1];
    const float* b_embed = (const float*)d_in[2];
    const float* W_ih    = (const float*)d_in[3];
    const float* W_hh    = (const float*)d_in[4];
    const float* b_ih    = (const float*)d_in[5];
    const float* b_hh    = (const float*)d_in[6];
    const float* W_act   = (const float*)d_in[7];
    const float* b_act   = (const float*)d_in[8];
    const float* W_activ = (const float*)d_in[9];
    const float* b_activ = (const float*)d_in[10];
    float* out = (float*)d_out;

    float *X, *GX, *HID;
    cudaGetSymbolAddress((void**)&X,   g_X);
    cudaGetSymbolAddress((void**)&GX,  g_GX);
    cudaGetSymbolAddress((void**)&HID, g_H);

    // 1) embed: X = tanh(feature @ W_embed^T + b_embed)   [15360,1024]
    gemm_nt128<1><<<dim3(Hq / 128, NROWS / 128), 256>>>(
        feature, W_embed, b_embed, X, NROWS, Hq, Eq);

    // 2) input gates: GX = X @ W_ih^T + b_ih              [15360,3072]
    gemm_nt128<0><<<dim3(GXW / 128, NROWS / 128), 256>>>(
        X, W_ih, b_ih, GX, NROWS, GXW, Hq);

    // 3) recurrence: 40 fused steps
    for (int t = 0; t < Tq; t++) {
        const float* hprev = (t == 0) ? HID : (HID + (size_t)(t - 1) * BP * Hq);
        float* hout = HID + (size_t)t * BP * Hq;
        gru_step<<<dim3(16, 6), 256>>>(hprev, W_hh, GX, b_hh, hout, t, t == 0);
    }

    // 4) heads
    action_head<<<(NROWS * 32 + 255) / 256, 256>>>(HID, W_act, b_act, out);
    activity_head<<<(Bq * Tq * 32 + 255) / 256, 256>>>(
        HID, W_activ, b_activ, out + (size_t)NROWS * 9);
}

// round 3
// speedup vs baseline: 1.5937x; 1.5937x over previous
#include <cuda_runtime.h>
#include <cstdint>
#include <math.h>

// Problem constants
#define Bq   32
#define Tq   40
#define Pq   12
#define Eq   2048
#define Hq   1024
#define BP   384          // B*P
#define NROWS 15360       // B*T*P
#define GXW  3072         // 3*H

// tcgen05 is an 'a'-feature: only present in the sm_103a/sm_100a device pass.
// The harness also runs a plain compute_103 gencode pass; give it a SIMT
// fallback body (never executed at runtime — driver loads the sm_103a cubin).
#if !defined(__CUDA_ARCH__) || defined(__CUDA_ARCH_FEAT_SM103_ALL) || defined(__CUDA_ARCH_FEAT_SM100_ALL)
#define HAS_TCG 1
#else
#define HAS_TCG 0
#endif

// Scratch (device globals: allocation-free rule)
__device__ float g_X [(size_t)NROWS * Hq];   // embedded+tanh  [B,T,P,H]
__device__ float g_GX[(size_t)NROWS * GXW];  // input gates    [B,T,P,3H]
__device__ float g_H [(size_t)Tq * BP * Hq]; // hiddens        [T,B,P,H]

// ===========================================================================
// Minimal sm_103a PTX helpers (guarded)
// ===========================================================================
#if HAS_TCG
__device__ __forceinline__ uint32_t elect_one_pred() {
    uint32_t pred;
    asm volatile(
        "{\n\t.reg .pred p;\n\t"
        "elect.sync _|p, 0xFFFFFFFF;\n\t"
        "selp.b32 %0, 1, 0, p;\n\t}"
        : "=r"(pred));
    return pred;
}
__device__ __forceinline__ uint32_t smem_to_u32(const void* p) {
    uint32_t a;
    asm("{ .reg .u64 t; cvta.to.shared.u64 t, %1; cvt.u32.u64 %0, t; }"
        : "=r"(a) : "l"(p));
    return a;
}
#define MBARRIER_INIT(addr, cnt) \
    asm volatile("mbarrier.init.shared.b64 [%0], %1;" \
        :: "r"((uint32_t)(addr)), "r"((uint32_t)(cnt)) : "memory")

#define MBARRIER_WAIT_PARITY(mbar_smem_addr, phase_parity) do { \
    uint32_t _mbar = (uint32_t)(mbar_smem_addr); \
    uint32_t _parity = (uint32_t)(phase_parity); \
    uint32_t _done; \
    asm volatile( \
        "{\n\t.reg .pred p;\n\t" \
        "mbarrier.try_wait.parity.acquire.cta.shared::cta.b64 p, [%1], %2;\n\t" \
        "selp.b32 %0, 1, 0, p;\n\t}" \
        : "=r"(_done) : "r"(_mbar), "r"(_parity) : "memory"); \
    if (!_done) { \
        asm volatile( \
            "{\n\t.reg .pred P1;\n\t" \
            "WAIT_LOOP_%=:\n\t" \
            "mbarrier.try_wait.parity.acquire.cta.shared::cta.b64 P1, [%0], %1, 0x989680;\n\t" \
            "@P1 bra.uni WAIT_DONE_%=;\n\t" \
            "bra.uni WAIT_LOOP_%=;\n\t" \
            "WAIT_DONE_%=:\n\t}" \
            :: "r"(_mbar), "r"(_parity) : "memory"); \
    } \
} while(0)

#define TCGEN05_ALLOC(smem_result_addr, nCols) \
    asm volatile("tcgen05.alloc.cta_group::1.sync.aligned.shared::cta.b32 [%0], %1;" \
        :: "r"((uint32_t)(smem_result_addr)), "r"((uint32_t)(nCols)) : "memory")
#define TCGEN05_DEALLOC(tmem_addr, nCols) \
    asm volatile("tcgen05.dealloc.cta_group::1.sync.aligned.b32 %0, %1;" \
        :: "r"(tmem_addr), "r"((uint32_t)(nCols)))
#define TCGEN05_RELINQUISH() \
    asm volatile("tcgen05.relinquish_alloc_permit.cta_group::1.sync.aligned;")
#define TCGEN05_COMMIT(mbar_smem_addr) \
    asm volatile("tcgen05.commit.cta_group::1.mbarrier::arrive::one.shared::cluster.b64 [%0];" \
        :: "r"((uint32_t)(mbar_smem_addr)) : "memory")
#define TCGEN05_FENCE_AFTER() \
    asm volatile("tcgen05.fence::after_thread_sync;" ::: "memory")
#define TCGEN05_WAIT_LD() \
    asm volatile("tcgen05.wait::ld.sync.aligned;" ::: "memory")
#define FENCE_PROXY_ASYNC() \
    asm volatile("fence.proxy.async.shared::cta;" ::: "memory")

#define TCGEN05_LD_32X32B_X32(r, tmem_addr) \
    asm volatile( \
        "tcgen05.ld.sync.aligned.32x32b.x32.b32 " \
        "{%0, %1, %2, %3, %4, %5, %6, %7, " \
        " %8, %9, %10, %11, %12, %13, %14, %15, " \
        " %16, %17, %18, %19, %20, %21, %22, %23, " \
        " %24, %25, %26, %27, %28, %29, %30, %31}, [%32];" \
        : "=r"((r)[0]),  "=r"((r)[1]),  "=r"((r)[2]),  "=r"((r)[3]), \
          "=r"((r)[4]),  "=r"((r)[5]),  "=r"((r)[6]),  "=r"((r)[7]), \
          "=r"((r)[8]),  "=r"((r)[9]),  "=r"((r)[10]), "=r"((r)[11]), \
          "=r"((r)[12]), "=r"((r)[13]), "=r"((r)[14]), "=r"((r)[15]), \
          "=r"((r)[16]), "=r"((r)[17]), "=r"((r)[18]), "=r"((r)[19]), \
          "=r"((r)[20]), "=r"((r)[21]), "=r"((r)[22]), "=r"((r)[23]), \
          "=r"((r)[24]), "=r"((r)[25]), "=r"((r)[26]), "=r"((r)[27]), \
          "=r"((r)[28]), "=r"((r)[29]), "=r"((r)[30]), "=r"((r)[31]) \
        : "r"(tmem_addr))

// SMEM descriptor: K-major SW128, LBO=1, SBO=64, version=1 (Blackwell)
__device__ __forceinline__ uint64_t make_desc_sw128(uint32_t base_addr) {
    const uint64_t base =
        (uint64_t(2)  << 61) | (uint64_t(1) << 46) |
        (uint64_t(64) << 32) | (uint64_t(1) << 16);
    return base | ((uint64_t)(base_addr >> 4) & 0x3FFF);
}

__device__ __forceinline__ uint32_t f2tf32(float f) {
    uint32_t r;
    asm("cvt.rna.tf32.f32 %0, %1;" : "=r"(r) : "f"(f));
    return r;
}

// tf32 SS MMA, cta_group::1
__device__ __forceinline__ void mma_tf32_ss(
    uint32_t d_tmem, uint64_t a_desc, uint64_t b_desc,
    uint32_t idesc, uint32_t enable_d)
{
    asm volatile(
        "{\n\t.reg .pred p;\n\t"
        "setp.ne.u32 p, %5, 0;\n\t"
        "tcgen05.mma.cta_group::1.kind::tf32 [%0], %1, %2, %3, "
        "{%4, %4, %4, %4}, p;\n\t}"
        :: "r"(d_tmem), "l"(a_desc), "l"(b_desc), "r"(idesc),
           "r"(0u), "r"(enable_d)
        : "memory");
}
#endif  // HAS_TCG

#define SWZ(o) ((o) ^ ((((uint32_t)(o)) >> 3) & 0x70u))

// ===========================================================================
// tcgen05 tf32 GEMM: C[M,N] = act(A[M,K] @ B[N,K]^T + bias[N])
// CTA tile 128x128, K chunk = 32 floats (one SW128 atom), double-buffered.
// 256 threads. M%128==0, N%128==0, K%32==0. ACT: 0=none, 1=tanh.
// ===========================================================================
// Dynamic smem layout (bytes):
//   [0]      tmem ptr
//   [16,24]  mbar[2]
//   [1024]   A buf0 (16KB), [17408] A buf1, [33792] B buf0, [50176] B buf1
#define TCG_SMEM_BYTES 66560

template<int ACT>
__global__ __launch_bounds__(256) void tc_gemm(
    const float* __restrict__ A, const float* __restrict__ Bm,
    const float* __restrict__ bias, float* __restrict__ C,
    int M, int N, int K)
{
#if HAS_TCG
    extern __shared__ char smem[];
    const uint32_t sb  = smem_to_u32(smem);
    const int tid  = threadIdx.x;
    const int w    = tid >> 5;
    const int lane = tid & 31;
    const int row0 = blockIdx.y * 128;
    const int col0 = blockIdx.x * 128;

    if (w == 0) { TCGEN05_ALLOC(sb, 128); TCGEN05_RELINQUISH(); }
    if (tid == 0) { MBARRIER_INIT(sb + 16, 1); MBARRIER_INIT(sb + 24, 1); }
    __syncthreads();
    uint32_t tmem;
    asm volatile("ld.shared.b32 %0, [%1];" : "=r"(tmem) : "r"(sb));

    // loader mapping: thread -> (row, 16 consecutive K-floats)
    const int lr  = tid >> 1;           // 0..127
    const int lcf = (tid & 1) * 16;     // float offset within 32-float chunk
    const float* Ag = A  + (size_t)(row0 + lr) * K + lcf;
    const float* Bg = Bm + (size_t)(col0 + lr) * K + lcf;

    const uint32_t aoff[2] = {1024u, 17408u};
    const uint32_t boff[2] = {33792u, 50176u};
    int ph[2] = {0, 0};
    const int NC = K / 32;

    const uint32_t idesc = (1u << 4) | (2u << 7) | (2u << 10) |
                           ((128u / 8) << 17) | ((128u / 16) << 24);

    for (int c = 0; c < NC; c++) {
        const int b = c & 1;

        // prefetch gmem into regs (independent of the mbar wait)
        float4 av[4], bv[4];
        #pragma unroll
        for (int j = 0; j < 4; j++) {
            av[j] = *(const float4*)(Ag + (size_t)c * 32 + j * 4);
            bv[j] = *(const float4*)(Bg + (size_t)c * 32 + j * 4);
        }

        if (c >= 2) { MBARRIER_WAIT_PARITY(sb + 16 + 8 * b, ph[b]); ph[b] ^= 1; }

        #pragma unroll
        for (int j = 0; j < 4; j++) {
            uint4 ta, tb;
            ta.x = f2tf32(av[j].x); ta.y = f2tf32(av[j].y);
            ta.z = f2tf32(av[j].z); ta.w = f2tf32(av[j].w);
            tb.x = f2tf32(bv[j].x); tb.y = f2tf32(bv[j].y);
            tb.z = f2tf32(bv[j].z); tb.w = f2tf32(bv[j].w);
            const uint32_t byo = (uint32_t)(lr * 128 + (lcf + j * 4) * 4);
            *(uint4*)(smem + aoff[b] + SWZ(byo)) = ta;
            *(uint4*)(smem + boff[b] + SWZ(byo)) = tb;
        }
        FENCE_PROXY_ASYNC();
        __syncthreads();

        if (w == 0 && elect_one_pred()) {
            const uint64_t ad = make_desc_sw128(sb + aoff[b]);
            const uint64_t bd = make_desc_sw128(sb + boff[b]);
            #pragma unroll
            for (int k = 0; k < 4; k++)   // 4 MMAs of K=8 tf32 (32B) each
                mma_tf32_ss(tmem, ad + k * 2, bd + k * 2, idesc,
                            (c > 0 || k > 0) ? 1u : 0u);
            TCGEN05_COMMIT(sb + 16 + 8 * b);
        }
    }

    {   // final wait for the last chunk's commit (covers all prior MMAs)
        const int b = (NC - 1) & 1;
        MBARRIER_WAIT_PARITY(sb + 16 + 8 * b, ph[b]);
    }
    TCGEN05_FENCE_AFTER();

    // Epilogue: warps 0-3 rows 0..127 / cols 0..63, warps 4-7 same rows cols 64..127.
    // Transpose 32x32 blocks through smem so STG is coalesced (lane <-> col).
    const int rbase = (w & 3) * 32;
    const int csel  = (w >> 2) * 64;
    float* tr = reinterpret_cast<float*>(smem + 1024) + w * (32 * 33);

    #pragma unroll
    for (int half = 0; half < 2; half++) {
        const int cb = csel + half * 32;
        uint32_t regs[32];
        TCGEN05_LD_32X32B_X32(regs, tmem + cb);
        TCGEN05_WAIT_LD();
        __syncwarp();
        #pragma unroll
        for (int cc = 0; cc < 32; cc++)
            tr[lane * 33 + cc] = __uint_as_float(regs[cc]);
        __syncwarp();
        const int col = col0 + cb + lane;
        const float bvs = bias[col];
        #pragma unroll
        for (int r = 0; r < 32; r++) {
            float v = tr[r * 33 + lane] + bvs;
            if (ACT == 1) v = tanhf(v);
            C[(size_t)(row0 + rbase + r) * N + col] = v;
        }
        __syncwarp();
    }

    __syncthreads();
    if (w == 0) TCGEN05_DEALLOC(tmem, 128);
#else
    // Fallback body for the plain compute_103 gencode pass (never executed:
    // the driver loads the sm_103a cubin). Correct but slow SIMT loop.
    const int row0 = blockIdx.y * 128;
    const int col0 = blockIdx.x * 128;
    for (int idx = threadIdx.x; idx < 128 * 128; idx += 256) {
        const int r  = idx >> 7;
        const int cc = idx & 127;
        const float* a = A  + (size_t)(row0 + r)  * K;
        const float* b = Bm + (size_t)(col0 + cc) * K;
        float s = 0.0f;
        for (int k = 0; k < K; k++) s = fmaf(a[k], b[k], s);
        s += bias[col0 + cc];
        if (ACT == 1) s = tanhf(s);
        C[(size_t)(row0 + r) * N + (col0 + cc)] = s;
    }
#endif
}

// ---------------------------------------------------------------------------
// One GRU timestep, fully fused (unchanged — known good).
// ---------------------------------------------------------------------------
__global__ __launch_bounds__(256) void gru_step(
    const float* __restrict__ hprev, const float* __restrict__ Whh,
    const float* __restrict__ gx,    const float* __restrict__ bhh,
    float* __restrict__ hout, int t, int first)
{
    __shared__ float Hs[16][68];
    __shared__ float Ws[3][16][68];

    const int tid  = threadIdx.x;
    const int tx   = tid & 15;
    const int ty   = tid >> 4;
    const int row0 = blockIdx.y * 64;
    const int col0 = blockIdx.x * 64;

    float acc[3][4][4] = {};

    if (!first) {
        const int lr = tid >> 2;
        const int lc = (tid & 3) * 4;
        const float* Hp  = hprev + (size_t)(row0 + lr) * Hq + lc;
        const float* Wp0 = Whh + (size_t)(col0 + lr) * Hq + lc;
        const float* Wp1 = Wp0 + (size_t)Hq * Hq;
        const float* Wp2 = Wp1 + (size_t)Hq * Hq;

        for (int k0 = 0; k0 < Hq; k0 += 16) {
            float4 hv = *(const float4*)(Hp  + k0);
            float4 w0 = *(const float4*)(Wp0 + k0);
            float4 w1 = *(const float4*)(Wp1 + k0);
            float4 w2 = *(const float4*)(Wp2 + k0);

            __syncthreads();
            Hs[lc+0][lr]=hv.x; Hs[lc+1][lr]=hv.y; Hs[lc+2][lr]=hv.z; Hs[lc+3][lr]=hv.w;
            Ws[0][lc+0][lr]=w0.x; Ws[0][lc+1][lr]=w0.y; Ws[0][lc+2][lr]=w0.z; Ws[0][lc+3][lr]=w0.w;
            Ws[1][lc+0][lr]=w1.x; Ws[1][lc+1][lr]=w1.y; Ws[1][lc+2][lr]=w1.z; Ws[1][lc+3][lr]=w1.w;
            Ws[2][lc+0][lr]=w2.x; Ws[2][lc+1][lr]=w2.y; Ws[2][lc+2][lr]=w2.z; Ws[2][lc+3][lr]=w2.w;
            __syncthreads();

            #pragma unroll
            for (int kk = 0; kk < 16; kk++) {
                float a[4], br[4], bz[4], bn[4];
                *(float4*)a  = *(const float4*)&Hs[kk][ty*4];
                *(float4*)br = *(const float4*)&Ws[0][kk][tx*4];
                *(float4*)bz = *(const float4*)&Ws[1][kk][tx*4];
                *(float4*)bn = *(const float4*)&Ws[2][kk][tx*4];
                #pragma unroll
                for (int i = 0; i < 4; i++) {
                    #pragma unroll
                    for (int j = 0; j < 4; j++) {
                        acc[0][i][j] = fmaf(a[i], br[j], acc[0][i][j]);
                        acc[1][i][j] = fmaf(a[i], bz[j], acc[1][i][j]);
                        acc[2][i][j] = fmaf(a[i], bn[j], acc[2][i][j]);
                    }
                }
            }
        }
    }

    #pragma unroll
    for (int i = 0; i < 4; i++) {
        const int m  = row0 + ty * 4 + i;
        const int bb = m / Pq;
        const int pp = m - bb * Pq;
        const float* gxr = gx + ((size_t)(bb * Tq + t) * Pq + pp) * GXW;
        #pragma unroll
        for (int j = 0; j < 4; j++) {
            const int c = col0 + tx * 4 + j;
            float xr = gxr[c];
            float xz = gxr[c + Hq];
            float xn = gxr[c + 2 * Hq];
            float hr = acc[0][i][j] + bhh[c];
            float hz = acc[1][i][j] + bhh[c + Hq];
            float hn = acc[2][i][j] + bhh[c + 2 * Hq];
            float r  = 1.0f / (1.0f + expf(-(xr + hr)));
            float z  = 1.0f / (1.0f + expf(-(xz + hz)));
            float n  = tanhf(fmaf(r, hn, xn));
            float hp = first ? 0.0f : hprev[(size_t)m * Hq + c];
            hout[(size_t)m * Hq + c] = fmaf(z, hp - n, n);
        }
    }
}

// ---------------------------------------------------------------------------
// Heads (unchanged)
// ---------------------------------------------------------------------------
__global__ __launch_bounds__(256) void action_head(
    const float* __restrict__ hid, const float* __restrict__ Wact,
    const float* __restrict__ bact, float* __restrict__ out)
{
    const int warp = (blockIdx.x * blockDim.x + threadIdx.x) >> 5;
    const int lane = threadIdx.x & 31;
    if (warp >= NROWS) return;
    const int n  = warp;
    const int bb = n / (Tq * Pq);
    const int rm = n - bb * (Tq * Pq);
    const int tt = rm / Pq;
    const int pp = rm - tt * Pq;
    const float* h = hid + ((size_t)tt * BP + bb * Pq + pp) * Hq;

    float s[9] = {};
    for (int k = lane; k < Hq; k += 32) {
        const float hv = h[k];
        #pragma unroll
        for (int a = 0; a < 9; a++) s[a] = fmaf(hv, Wact[a * Hq + k], s[a]);
    }
    #pragma unroll
    for (int a = 0; a < 9; a++)
        #pragma unroll
        for (int off = 16; off; off >>= 1)
            s[a] += __shfl_xor_sync(0xFFFFFFFFu, s[a], off);
    if (lane < 9) out[(size_t)n * 9 + lane] = s[lane] + bact[lane];
}

__global__ __launch_bounds__(256) void activity_head(
    const float* __restrict__ hid, const float* __restrict__ Wactv,
    const float* __restrict__ bactv, float* __restrict__ out)
{
    const int warp = (blockIdx.x * blockDim.x + threadIdx.x) >> 5;
    const int lane = threadIdx.x & 31;
    if (warp >= Bq * Tq) return;
    const int bb = warp / Tq;
    const int tt = warp - bb * Tq;
    const float* base = hid + ((size_t)tt * BP + bb * Pq) * Hq;

    float s[8] = {};
    for (int k = lane; k < Hq; k += 32) {
        float mx = base[k];
        #pragma unroll
        for (int p = 1; p < Pq; p++) mx = fmaxf(mx, base[(size_t)p * Hq + k]);
        #pragma unroll
        for (int a = 0; a < 8; a++) s[a] = fmaf(mx, Wactv[a * Hq + k], s[a]);
    }
    #pragma unroll
    for (int a = 0; a < 8; a++)
        #pragma unroll
        for (int off = 16; off; off >>= 1)
            s[a] += __shfl_xor_sync(0xFFFFFFFFu, s[a], off);
    if (lane < 8) out[(size_t)warp * 8 + lane] = s[lane] + bactv[lane];
}

// ---------------------------------------------------------------------------
extern "C" void kernel_launch(void* const* d_in, const int* in_sizes, int n_in,
                              void* d_out, int out_size)
{
    const float* feature = (const float*)d_in[0];
    const float* W_embed = (const float*)d_in[1];
    const float* b_embed = (const float*)d_in[2];
    const float* W_ih    = (const float*)d_in[3];
    const float* W_hh    = (const float*)d_in[4];
    const float* b_ih    = (const float*)d_in[5];
    const float* b_hh    = (const float*)d_in[6];
    const float* W_act   = (const float*)d_in[7];
    const float* b_act   = (const float*)d_in[8];
    const float* W_activ = (const float*)d_in[9];
    const float* b_activ = (const float*)d_in[10];
    float* out = (float*)d_out;

    float *X, *GX, *HID;
    cudaGetSymbolAddress((void**)&X,   g_X);
    cudaGetSymbolAddress((void**)&GX,  g_GX);
    cudaGetSymbolAddress((void**)&HID, g_H);

    cudaFuncSetAttribute(tc_gemm<1>,
        cudaFuncAttributeMaxDynamicSharedMemorySize, TCG_SMEM_BYTES);
    cudaFuncSetAttribute(tc_gemm<0>,
        cudaFuncAttributeMaxDynamicSharedMemorySize, TCG_SMEM_BYTES);

    // 1) embed: X = tanh(feature @ W_embed^T + b_embed)   [15360,1024]
    tc_gemm<1><<<dim3(Hq / 128, NROWS / 128), 256, TCG_SMEM_BYTES>>>(
        feature, W_embed, b_embed, X, NROWS, Hq, Eq);

    // 2) input gates: GX = X @ W_ih^T + b_ih              [15360,3072]
    tc_gemm<0><<<dim3(GXW / 128, NROWS / 128), 256, TCG_SMEM_BYTES>>>(
        X, W_ih, b_ih, GX, NROWS, GXW, Hq);

    // 3) recurrence: 40 fused steps (SIMT, unchanged this round)
    for (int t = 0; t < Tq; t++) {
        const float* hprev = (t == 0) ? HID : (HID + (size_t)(t - 1) * BP * Hq);
        float* hout = HID + (size_t)t * BP * Hq;
        gru_step<<<dim3(16, 6), 256>>>(hprev, W_hh, GX, b_hh, hout, t, t == 0);
    }

    // 4) heads
    action_head<<<(NROWS * 32 + 255) / 256, 256>>>(HID, W_act, b_act, out);
    activity_head<<<(Bq * Tq * 32 + 255) / 256, 256>>>(
        HID, W_activ, b_activ, out + (size_t)NROWS * 9);
}

// round 4
// speedup vs baseline: 2.2302x; 1.3994x over previous
#include <cuda_runtime.h>
#include <cstdint>
#include <math.h>

// Problem constants
#define Bq   32
#define Tq   40
#define Pq   12
#define Eq   2048
#define Hq   1024
#define BP   384          // B*P
#define NROWS 15360       // B*T*P
#define GXW  3072         // 3*H

// tcgen05 is an 'a'-feature: only present in the sm_103a/sm_100a device pass.
// The harness also runs a plain compute_103 gencode pass; give it SIMT
// fallback bodies (never executed — driver loads the sm_103a cubin).
#if !defined(__CUDA_ARCH__) || defined(__CUDA_ARCH_FEAT_SM103_ALL) || defined(__CUDA_ARCH_FEAT_SM100_ALL)
#define HAS_TCG 1
#else
#define HAS_TCG 0
#endif

// Scratch (device globals: allocation-free rule)
__device__ float g_X [(size_t)NROWS * Hq];   // embedded+tanh  [B,T,P,H]
__device__ float g_GX[(size_t)NROWS * GXW];  // input gates    [B,T,P,3H]
__device__ float g_H [(size_t)Tq * BP * Hq]; // hiddens        [T,B,P,H]
// Whh pre-converted to tf32 + pre-swizzled smem images:
// [16 col-tiles][32 K-chunks][192 rows x 128 B] = 12 MB
__device__ float g_Wt[(size_t)16 * 32 * 6144];

#define SWZ(o) ((o) ^ ((((uint32_t)(o)) >> 3) & 0x70u))

__device__ __forceinline__ uint32_t f2tf32(float f) {
    uint32_t r;
    asm("cvt.rna.tf32.f32 %0, %1;" : "=r"(r) : "f"(f));
    return r;
}

// ===========================================================================
// sm_103a PTX helpers (guarded)
// ===========================================================================
#if HAS_TCG
__device__ __forceinline__ uint32_t elect_one_pred() {
    uint32_t pred;
    asm volatile(
        "{\n\t.reg .pred p;\n\t"
        "elect.sync _|p, 0xFFFFFFFF;\n\t"
        "selp.b32 %0, 1, 0, p;\n\t}"
        : "=r"(pred));
    return pred;
}
__device__ __forceinline__ uint32_t smem_to_u32(const void* p) {
    uint32_t a;
    asm("{ .reg .u64 t; cvta.to.shared.u64 t, %1; cvt.u32.u64 %0, t; }"
        : "=r"(a) : "l"(p));
    return a;
}
#define MBARRIER_INIT(addr, cnt) \
    asm volatile("mbarrier.init.shared.b64 [%0], %1;" \
        :: "r"((uint32_t)(addr)), "r"((uint32_t)(cnt)) : "memory")

#define MBARRIER_WAIT_PARITY(mbar_smem_addr, phase_parity) do { \
    uint32_t _mbar = (uint32_t)(mbar_smem_addr); \
    uint32_t _parity = (uint32_t)(phase_parity); \
    uint32_t _done; \
    asm volatile( \
        "{\n\t.reg .pred p;\n\t" \
        "mbarrier.try_wait.parity.acquire.cta.shared::cta.b64 p, [%1], %2;\n\t" \
        "selp.b32 %0, 1, 0, p;\n\t}" \
        : "=r"(_done) : "r"(_mbar), "r"(_parity) : "memory"); \
    if (!_done) { \
        asm volatile( \
            "{\n\t.reg .pred P1;\n\t" \
            "WAIT_LOOP_%=:\n\t" \
            "mbarrier.try_wait.parity.acquire.cta.shared::cta.b64 P1, [%0], %1, 0x989680;\n\t" \
            "@P1 bra.uni WAIT_DONE_%=;\n\t" \
            "bra.uni WAIT_LOOP_%=;\n\t" \
            "WAIT_DONE_%=:\n\t}" \
            :: "r"(_mbar), "r"(_parity) : "memory"); \
    } \
} while(0)

#define TCGEN05_ALLOC(smem_result_addr, nCols) \
    asm volatile("tcgen05.alloc.cta_group::1.sync.aligned.shared::cta.b32 [%0], %1;" \
        :: "r"((uint32_t)(smem_result_addr)), "r"((uint32_t)(nCols)) : "memory")
#define TCGEN05_DEALLOC(tmem_addr, nCols) \
    asm volatile("tcgen05.dealloc.cta_group::1.sync.aligned.b32 %0, %1;" \
        :: "r"(tmem_addr), "r"((uint32_t)(nCols)))
#define TCGEN05_RELINQUISH() \
    asm volatile("tcgen05.relinquish_alloc_permit.cta_group::1.sync.aligned;")
#define TCGEN05_COMMIT(mbar_smem_addr) \
    asm volatile("tcgen05.commit.cta_group::1.mbarrier::arrive::one.shared::cluster.b64 [%0];" \
        :: "r"((uint32_t)(mbar_smem_addr)) : "memory")
#define TCGEN05_FENCE_AFTER() \
    asm volatile("tcgen05.fence::after_thread_sync;" ::: "memory")
#define TCGEN05_WAIT_LD() \
    asm volatile("tcgen05.wait::ld.sync.aligned;" ::: "memory")
#define FENCE_PROXY_ASYNC() \
    asm volatile("fence.proxy.async.shared::cta;" ::: "memory")

#define TCGEN05_LD_32X32B_X32(r, tmem_addr) \
    asm volatile( \
        "tcgen05.ld.sync.aligned.32x32b.x32.b32 " \
        "{%0, %1, %2, %3, %4, %5, %6, %7, " \
        " %8, %9, %10, %11, %12, %13, %14, %15, " \
        " %16, %17, %18, %19, %20, %21, %22, %23, " \
        " %24, %25, %26, %27, %28, %29, %30, %31}, [%32];" \
        : "=r"((r)[0]),  "=r"((r)[1]),  "=r"((r)[2]),  "=r"((r)[3]), \
          "=r"((r)[4]),  "=r"((r)[5]),  "=r"((r)[6]),  "=r"((r)[7]), \
          "=r"((r)[8]),  "=r"((r)[9]),  "=r"((r)[10]), "=r"((r)[11]), \
          "=r"((r)[12]), "=r"((r)[13]), "=r"((r)[14]), "=r"((r)[15]), \
          "=r"((r)[16]), "=r"((r)[17]), "=r"((r)[18]), "=r"((r)[19]), \
          "=r"((r)[20]), "=r"((r)[21]), "=r"((r)[22]), "=r"((r)[23]), \
          "=r"((r)[24]), "=r"((r)[25]), "=r"((r)[26]), "=r"((r)[27]), \
          "=r"((r)[28]), "=r"((r)[29]), "=r"((r)[30]), "=r"((r)[31]) \
        : "r"(tmem_addr))

// SMEM descriptor: K-major SW128, LBO=1, SBO=64, version=1 (Blackwell)
__device__ __forceinline__ uint64_t make_desc_sw128(uint32_t base_addr) {
    const uint64_t base =
        (uint64_t(2)  << 61) | (uint64_t(1) << 46) |
        (uint64_t(64) << 32) | (uint64_t(1) << 16);
    return base | ((uint64_t)(base_addr >> 4) & 0x3FFF);
}

// tf32 SS MMA, cta_group::1
__device__ __forceinline__ void mma_tf32_ss(
    uint32_t d_tmem, uint64_t a_desc, uint64_t b_desc,
    uint32_t idesc, uint32_t enable_d)
{
    asm volatile(
        "{\n\t.reg .pred p;\n\t"
        "setp.ne.u32 p, %5, 0;\n\t"
        "tcgen05.mma.cta_group::1.kind::tf32 [%0], %1, %2, %3, "
        "{%4, %4, %4, %4}, p;\n\t}"
        :: "r"(d_tmem), "l"(a_desc), "l"(b_desc), "r"(idesc),
           "r"(0u), "r"(enable_d)
        : "memory");
}
#endif  // HAS_TCG

__device__ __forceinline__ float sigf(float x) {
    return 1.0f / (1.0f + expf(-x));
}

// ===========================================================================
// tcgen05 tf32 GEMM: C[M,N] = act(A[M,K] @ B[N,K]^T + bias[N]) — unchanged
// ===========================================================================
#define TCG_SMEM_BYTES 66560

template<int ACT>
__global__ __launch_bounds__(256) void tc_gemm(
    const float* __restrict__ A, const float* __restrict__ Bm,
    const float* __restrict__ bias, float* __restrict__ C,
    int M, int N, int K)
{
#if HAS_TCG
    extern __shared__ char smem[];
    const uint32_t sb  = smem_to_u32(smem);
    const int tid  = threadIdx.x;
    const int w    = tid >> 5;
    const int lane = tid & 31;
    const int row0 = blockIdx.y * 128;
    const int col0 = blockIdx.x * 128;

    if (w == 0) { TCGEN05_ALLOC(sb, 128); TCGEN05_RELINQUISH(); }
    if (tid == 0) { MBARRIER_INIT(sb + 16, 1); MBARRIER_INIT(sb + 24, 1); }
    __syncthreads();
    uint32_t tmem;
    asm volatile("ld.shared.b32 %0, [%1];" : "=r"(tmem) : "r"(sb));

    const int lr  = tid >> 1;
    const int lcf = (tid & 1) * 16;
    const float* Ag = A  + (size_t)(row0 + lr) * K + lcf;
    const float* Bg = Bm + (size_t)(col0 + lr) * K + lcf;

    const uint32_t aoff[2] = {1024u, 17408u};
    const uint32_t boff[2] = {33792u, 50176u};
    int ph[2] = {0, 0};
    const int NC = K / 32;

    const uint32_t idesc = (1u << 4) | (2u << 7) | (2u << 10) |
                           ((128u / 8) << 17) | ((128u / 16) << 24);

    for (int c = 0; c < NC; c++) {
        const int b = c & 1;
        float4 av[4], bv[4];
        #pragma unroll
        for (int j = 0; j < 4; j++) {
            av[j] = *(const float4*)(Ag + (size_t)c * 32 + j * 4);
            bv[j] = *(const float4*)(Bg + (size_t)c * 32 + j * 4);
        }
        if (c >= 2) { MBARRIER_WAIT_PARITY(sb + 16 + 8 * b, ph[b]); ph[b] ^= 1; }
        #pragma unroll
        for (int j = 0; j < 4; j++) {
            uint4 ta, tb;
            ta.x = f2tf32(av[j].x); ta.y = f2tf32(av[j].y);
            ta.z = f2tf32(av[j].z); ta.w = f2tf32(av[j].w);
            tb.x = f2tf32(bv[j].x); tb.y = f2tf32(bv[j].y);
            tb.z = f2tf32(bv[j].z); tb.w = f2tf32(bv[j].w);
            const uint32_t byo = (uint32_t)(lr * 128 + (lcf + j * 4) * 4);
            *(uint4*)(smem + aoff[b] + SWZ(byo)) = ta;
            *(uint4*)(smem + boff[b] + SWZ(byo)) = tb;
        }
        FENCE_PROXY_ASYNC();
        __syncthreads();

        if (w == 0 && elect_one_pred()) {
            const uint64_t ad = make_desc_sw128(sb + aoff[b]);
            const uint64_t bd = make_desc_sw128(sb + boff[b]);
            #pragma unroll
            for (int k = 0; k < 4; k++)
                mma_tf32_ss(tmem, ad + k * 2, bd + k * 2, idesc,
                            (c > 0 || k > 0) ? 1u : 0u);
            TCGEN05_COMMIT(sb + 16 + 8 * b);
        }
    }
    {
        const int b = (NC - 1) & 1;
        MBARRIER_WAIT_PARITY(sb + 16 + 8 * b, ph[b]);
    }
    TCGEN05_FENCE_AFTER();

    const int rbase = (w & 3) * 32;
    const int csel  = (w >> 2) * 64;
    float* tr = reinterpret_cast<float*>(smem + 1024) + w * (32 * 33);

    #pragma unroll
    for (int half = 0; half < 2; half++) {
        const int cb = csel + half * 32;
        uint32_t regs[32];
        TCGEN05_LD_32X32B_X32(regs, tmem + cb);
        TCGEN05_WAIT_LD();
        __syncwarp();
        #pragma unroll
        for (int cc = 0; cc < 32; cc++)
            tr[lane * 33 + cc] = __uint_as_float(regs[cc]);
        __syncwarp();
        const int col = col0 + cb + lane;
        const float bvs = bias[col];
        #pragma unroll
        for (int r = 0; r < 32; r++) {
            float v = tr[r * 33 + lane] + bvs;
            if (ACT == 1) v = tanhf(v);
            C[(size_t)(row0 + rbase + r) * N + col] = v;
        }
        __syncwarp();
    }
    __syncthreads();
    if (w == 0) TCGEN05_DEALLOC(tmem, 128);
#else
    const int row0 = blockIdx.y * 128;
    const int col0 = blockIdx.x * 128;
    for (int idx = threadIdx.x; idx < 128 * 128; idx += 256) {
        const int r  = idx >> 7;
        const int cc = idx & 127;
        const float* a = A  + (size_t)(row0 + r)  * K;
        const float* b = Bm + (size_t)(col0 + cc) * K;
        float s = 0.0f;
        for (int k = 0; k < K; k++) s = fmaf(a[k], b[k], s);
        s += bias[col0 + cc];
        if (ACT == 1) s = tanhf(s);
        C[(size_t)(row0 + r) * N + (col0 + cc)] = s;
    }
#endif
}

// ===========================================================================
// whh_prep: convert Whh -> tf32, rearrange into pre-swizzled per-(tile,chunk)
// smem images. Output row layout per image: rows 0..63 = gate r cols
// [tile*64, +64), 64..127 = gate z, 128..191 = gate n; each row = 32 K-floats.
// ===========================================================================
__global__ __launch_bounds__(256) void whh_prep(
    const float* __restrict__ Whh, float* __restrict__ Wt)
{
    const uint32_t stride = gridDim.x * blockDim.x;
    for (uint32_t u = blockIdx.x * blockDim.x + threadIdx.x;
         u < 786432u; u += stride) {               // 16*32*192*8 float4 units
        const uint32_t tc   = u / 1536u;           // tile*32 + chunk
        const uint32_t rem  = u - tc * 1536u;
        const uint32_t row  = rem >> 3;
        const uint32_t q    = rem & 7;
        const uint32_t tile = tc >> 5;
        const uint32_t chunk= tc & 31;
        const uint32_t g    = row >> 6;
        const uint32_t cidx = tile * 64 + (row & 63);
        const float4 v = *(const float4*)(
            Whh + ((size_t)(g * Hq + cidx)) * Hq + chunk * 32 + q * 4);
        uint4 o;
        o.x = f2tf32(v.x); o.y = f2tf32(v.y);
        o.z = f2tf32(v.z); o.w = f2tf32(v.w);
        *(uint4*)((char*)Wt + (size_t)tc * 24576 + SWZ(row * 128 + q * 16)) = o;
    }
}

// ===========================================================================
// gru_t0: first timestep (h_prev = 0  =>  gh = b_hh), pure elementwise.
// ===========================================================================
__global__ __launch_bounds__(256) void gru_t0(
    const float* __restrict__ gx, const float* __restrict__ bhh,
    float* __restrict__ hout)
{
    const int e = blockIdx.x * 256 + threadIdx.x;   // 384*1024 total
    const int m = e >> 10, c = e & 1023;
    const int bb = m / Pq, pp = m - bb * Pq;
    const float* gxr = gx + ((size_t)(bb * Tq) * Pq + pp) * GXW;  // t = 0
    const float r = sigf(gxr[c] + bhh[c]);
    const float z = sigf(gxr[c + Hq] + bhh[c + Hq]);
    const float n = tanhf(fmaf(r, bhh[c + 2 * Hq], gxr[c + 2 * Hq]));
    hout[e] = fmaf(z, -n, n);   // (1-z)*n, h_prev = 0
}

// ===========================================================================
// gru_tc: one GRU timestep on tensor cores.
// CTA: 128 rows x 64 h-cols x 3 gates. Grid (16, 3), 256 threads.
// A = hprev (fp32 -> tf32 cvt at load), B = pre-swizzled tf32 Whh images.
// TMEM: gate g accumulator [128x64] fp32 at col offset g*64 (alloc 256).
// Epilogue: TMEM -> 32x33 smem transpose per warp -> fused gate math ->
// coalesced gx/hprev reads, coalesced hout writes.
// ===========================================================================
#define GRU_BUF   40960                   // 16KB A + 24KB B per chunk
#define GRU_SMEM  (1024 + 2 * GRU_BUF)    // 82944

__global__ __launch_bounds__(256) void gru_tc(
    const float* __restrict__ hprev, const float* __restrict__ Wt,
    const float* __restrict__ gx,    const float* __restrict__ bhh,
    float* __restrict__ hout, int t)
{
#if HAS_TCG
    extern __shared__ char smem[];
    const uint32_t sb  = smem_to_u32(smem);
    const int tid  = threadIdx.x;
    const int w    = tid >> 5;
    const int lane = tid & 31;
    const int row0 = blockIdx.y * 128;     // m base (0..383)
    const int cb   = blockIdx.x * 64;      // h-col base

    if (w == 0) { TCGEN05_ALLOC(sb, 256); TCGEN05_RELINQUISH(); }
    if (tid == 0) { MBARRIER_INIT(sb + 16, 1); MBARRIER_INIT(sb + 24, 1); }
    __syncthreads();
    uint32_t tmem;
    asm volatile("ld.shared.b32 %0, [%1];" : "=r"(tmem) : "r"(sb));

    const uint32_t bufo[2] = {1024u, 1024u + GRU_BUF};
    int ph[2] = {0, 0};
    const uint32_t idesc = (1u << 4) | (2u << 7) | (2u << 10) |
                           ((64u / 8) << 17) | ((128u / 16) << 24);

    const float* Asrc = hprev + (size_t)row0 * Hq;
    const float* Bsrc = Wt + (size_t)blockIdx.x * 32 * 6144;

    // A loader mapping: 1024 float4 units (128 rows x 8), 4 per thread
    for (int c = 0; c < 32; c++) {
        const int b = c & 1;

        float4 av[4], bv[6];
        #pragma unroll
        for (int i = 0; i < 4; i++) {
            const int u = tid + 256 * i;
            av[i] = *(const float4*)(Asrc + (size_t)(u >> 3) * Hq
                                     + c * 32 + (u & 7) * 4);
        }
        const float4* bs = (const float4*)(Bsrc + (size_t)c * 6144);
        #pragma unroll
        for (int i = 0; i < 6; i++) bv[i] = bs[tid + 256 * i];

        if (c >= 2) { MBARRIER_WAIT_PARITY(sb + 16 + 8 * b, ph[b]); ph[b] ^= 1; }

        #pragma unroll
        for (int i = 0; i < 4; i++) {
            const int u = tid + 256 * i;
            uint4 ta;
            ta.x = f2tf32(av[i].x); ta.y = f2tf32(av[i].y);
            ta.z = f2tf32(av[i].z); ta.w = f2tf32(av[i].w);
            *(uint4*)(smem + bufo[b] + SWZ((u >> 3) * 128 + (u & 7) * 16)) = ta;
        }
        #pragma unroll
        for (int i = 0; i < 6; i++)
            *(float4*)(smem + bufo[b] + 16384 + (size_t)(tid + 256 * i) * 16) = bv[i];
        FENCE_PROXY_ASYNC();
        __syncthreads();

        if (w == 0 && elect_one_pred()) {
            const uint64_t ad = make_desc_sw128(sb + bufo[b]);
            #pragma unroll
            for (int k = 0; k < 4; k++) {
                #pragma unroll
                for (int g = 0; g < 3; g++) {
                    const uint64_t bd =
                        make_desc_sw128(sb + bufo[b] + 16384 + g * 8192) + k * 2;
                    mma_tf32_ss(tmem + g * 64, ad + k * 2, bd, idesc,
                                (c > 0 || k > 0) ? 1u : 0u);
                }
            }
            TCGEN05_COMMIT(sb + 16 + 8 * b);
        }
    }
    MBARRIER_WAIT_PARITY(sb + 16 + 8, ph[1]);   // last chunk c=31 -> b=1
    TCGEN05_FENCE_AFTER();
    __syncthreads();

    // ---- fused epilogue ----
    const int r0 = (w & 3) * 32;          // TMEM subpartition rows
    const int c0 = (w >> 2) * 32;         // column half
    float* tr = reinterpret_cast<float*>(smem + 1024) + w * (32 * 33);

    float ga[3][32];
    #pragma unroll
    for (int g = 0; g < 3; g++) {
        uint32_t regs[32];
        TCGEN05_LD_32X32B_X32(regs, tmem + g * 64 + c0);
        TCGEN05_WAIT_LD();
        __syncwarp();
        #pragma unroll
        for (int j = 0; j < 32; j++) tr[lane * 33 + j] = __uint_as_float(regs[j]);
        __syncwarp();
        #pragma unroll
        for (int i = 0; i < 32; i++) ga[g][i] = tr[i * 33 + lane];
        __syncwarp();
    }

    const int c = cb + c0 + lane;
    const float br_ = bhh[c];
    const float bz_ = bhh[c + Hq];
    const float bn_ = bhh[c + 2 * Hq];
    #pragma unroll
    for (int i = 0; i < 32; i++) {
        const int m  = row0 + r0 + i;
        const int bb = m / Pq;
        const int pp = m - bb * Pq;
        const float* gxr = gx + ((size_t)(bb * Tq + t) * Pq + pp) * GXW;
        const float r = sigf(gxr[c] + ga[0][i] + br_);
        const float z = sigf(gxr[c + Hq] + ga[1][i] + bz_);
        const float n = tanhf(fmaf(r, ga[2][i] + bn_, gxr[c + 2 * Hq]));
        const float hp = hprev[(size_t)m * Hq + c];
        hout[(size_t)m * Hq + c] = fmaf(z, hp - n, n);
    }

    __syncthreads();
    if (w == 0) TCGEN05_DEALLOC(tmem, 256);
#else
    // Fallback body (plain compute_103 pass; never executed).
    const int row0 = blockIdx.y * 128;
    const int cb   = blockIdx.x * 64;
    for (int idx = threadIdx.x; idx < 128 * 64; idx += 256) {
        const int m = row0 + (idx >> 6);
        const int c = cb + (idx & 63);
        float acc[3] = {};
        for (int g = 0; g < 3; g++) {
            const float* wr = Wt;  // fallback uses raw Whh layout not available; dummy
            (void)wr;
            acc[g] = 0.0f;
        }
        const int bb = m / Pq, pp = m - bb * Pq;
        const float* gxr = gx + ((size_t)(bb * Tq + t) * Pq + pp) * GXW;
        const float r = sigf(gxr[c] + acc[0] + bhh[c]);
        const float z = sigf(gxr[c + Hq] + acc[1] + bhh[c + Hq]);
        const float n = tanhf(fmaf(r, acc[2] + bhh[c + 2 * Hq], gxr[c + 2 * Hq]));
        const float hp = hprev[(size_t)m * Hq + c];
        hout[(size_t)m * Hq + c] = fmaf(z, hp - n, n);
    }
#endif
}

// ---------------------------------------------------------------------------
// Heads (unchanged)
// ---------------------------------------------------------------------------
__global__ __launch_bounds__(256) void action_head(
    const float* __restrict__ hid, const float* __restrict__ Wact,
    const float* __restrict__ bact, float* __restrict__ out)
{
    const int warp = (blockIdx.x * blockDim.x + threadIdx.x) >> 5;
    const int lane = threadIdx.x & 31;
    if (warp >= NROWS) return;
    const int n  = warp;
    const int bb = n / (Tq * Pq);
    const int rm = n - bb * (Tq * Pq);
    const int tt = rm / Pq;
    const int pp = rm - tt * Pq;
    const float* h = hid + ((size_t)tt * BP + bb * Pq + pp) * Hq;

    float s[9] = {};
    for (int k = lane; k < Hq; k += 32) {
        const float hv = h[k];
        #pragma unroll
        for (int a = 0; a < 9; a++) s[a] = fmaf(hv, Wact[a * Hq + k], s[a]);
    }
    #pragma unroll
    for (int a = 0; a < 9; a++)
        #pragma unroll
        for (int off = 16; off; off >>= 1)
            s[a] += __shfl_xor_sync(0xFFFFFFFFu, s[a], off);
    if (lane < 9) out[(size_t)n * 9 + lane] = s[lane] + bact[lane];
}

__global__ __launch_bounds__(256) void activity_head(
    const float* __restrict__ hid, const float* __restrict__ Wactv,
    const float* __restrict__ bactv, float* __restrict__ out)
{
    const int warp = (blockIdx.x * blockDim.x + threadIdx.x) >> 5;
    const int lane = threadIdx.x & 31;
    if (warp >= Bq * Tq) return;
    const int bb = warp / Tq;
    const int tt = warp - bb * Tq;
    const float* base = hid + ((size_t)tt * BP + bb * Pq) * Hq;

    float s[8] = {};
    for (int k = lane; k < Hq; k += 32) {
        float mx = base[k];
        #pragma unroll
        for (int p = 1; p < Pq; p++) mx = fmaxf(mx, base[(size_t)p * Hq + k]);
        #pragma unroll
        for (int a = 0; a < 8; a++) s[a] = fmaf(mx, Wactv[a * Hq + k], s[a]);
    }
    #pragma unroll
    for (int a = 0; a < 8; a++)
        #pragma unroll
        for (int off = 16; off; off >>= 1)
            s[a] += __shfl_xor_sync(0xFFFFFFFFu, s[a], off);
    if (lane < 8) out[(size_t)warp * 8 + lane] = s[lane] + bactv[lane];
}

// ---------------------------------------------------------------------------
extern "C" void kernel_launch(void* const* d_in, const int* in_sizes, int n_in,
                              void* d_out, int out_size)
{
    const float* feature = (const float*)d_in[0];
    const float* W_embed = (const float*)d_in[1];
    const float* b_embed = (const float*)d_in[2];
    const float* W_ih    = (const float*)d_in[3];
    const float* W_hh    = (const float*)d_in[4];
    const float* b_ih    = (const float*)d_in[5];
    const float* b_hh    = (const float*)d_in[6];
    const float* W_act   = (const float*)d_in[7];
    const float* b_act   = (const float*)d_in[8];
    const float* W_activ = (const float*)d_in[9];
    const float* b_activ = (const float*)d_in[10];
    float* out = (float*)d_out;

    float *X, *GX, *HID, *WT;
    cudaGetSymbolAddress((void**)&X,   g_X);
    cudaGetSymbolAddress((void**)&GX,  g_GX);
    cudaGetSymbolAddress((void**)&HID, g_H);
    cudaGetSymbolAddress((void**)&WT,  g_Wt);

    cudaFuncSetAttribute(tc_gemm<1>,
        cudaFuncAttributeMaxDynamicSharedMemorySize, TCG_SMEM_BYTES);
    cudaFuncSetAttribute(tc_gemm<0>,
        cudaFuncAttributeMaxDynamicSharedMemorySize, TCG_SMEM_BYTES);
    cudaFuncSetAttribute(gru_tc,
        cudaFuncAttributeMaxDynamicSharedMemorySize, GRU_SMEM);

    // 0) Whh -> tf32 pre-swizzled images
    whh_prep<<<768, 256>>>(W_hh, WT);

    // 1) embed: X = tanh(feature @ W_embed^T + b_embed)   [15360,1024]
    tc_gemm<1><<<dim3(Hq / 128, NROWS / 128), 256, TCG_SMEM_BYTES>>>(
        feature, W_embed, b_embed, X, NROWS, Hq, Eq);

    // 2) input gates: GX = X @ W_ih^T + b_ih              [15360,3072]
    tc_gemm<0><<<dim3(GXW / 128, NROWS / 128), 256, TCG_SMEM_BYTES>>>(
        X, W_ih, b_ih, GX, NROWS, GXW, Hq);

    // 3) recurrence
    gru_t0<<<(BP * Hq) / 256, 256>>>(GX, b_hh, HID);
    for (int t = 1; t < Tq; t++) {
        const float* hprev = HID + (size_t)(t - 1) * BP * Hq;
        float* hout = HID + (size_t)t * BP * Hq;
        gru_tc<<<dim3(16, 3), 256, GRU_SMEM>>>(hprev, WT, GX, b_hh, hout, t);
    }

    // 4) heads
    action_head<<<(NROWS * 32 + 255) / 256, 256>>>(HID, W_act, b_act, out);
    activity_head<<<(Bq * Tq * 32 + 255) / 256, 256>>>(
        HID, W_activ, b_activ, out + (size_t)NROWS * 9);
}

// round 6
// speedup vs baseline: 2.3319x; 1.0456x over previous
#include <cuda_runtime.h>
#include <cstdint>
#include <math.h>

// Problem constants
#define Bq   32
#define Tq   40
#define Pq   12
#define Eq   2048
#define Hq   1024
#define BP   384          // B*P
#define NROWS 15360       // B*T*P
#define GXW  3072         // 3*H

// tcgen05 is an 'a'-feature: only in the sm_103a/sm_100a device pass.
#if !defined(__CUDA_ARCH__) || defined(__CUDA_ARCH_FEAT_SM103_ALL) || defined(__CUDA_ARCH_FEAT_SM100_ALL)
#define HAS_TCG 1
#else
#define HAS_TCG 0
#endif

// Scratch (device globals: allocation-free rule)
__device__ float g_X [(size_t)NROWS * Hq];   // embedded+tanh  [B,T,P,H]
__device__ float g_GX[(size_t)NROWS * GXW];  // input gates    [B,T,P,3H]
__device__ float g_H [(size_t)Tq * BP * Hq]; // hiddens        [T,B,P,H]
// Whh tf32 pre-swizzled images: [16 col-tiles][32 K-chunks][192 rows x 128B]
__device__ float g_Wt[(size_t)16 * 32 * 6144];
// h as tf32 pre-swizzled A images, double parity:
// [2][3 rowtiles][32 chunks][128 rows x 32 cols] = 2 x 1.5MB
#define APSZ ((size_t)3 * 32 * 4096)
__device__ float g_Ap[2 * APSZ];

#define SWZ(o) ((o) ^ ((((uint32_t)(o)) >> 3) & 0x70u))

__device__ __forceinline__ uint32_t f2tf32(float f) {
    uint32_t r;
    asm("cvt.rna.tf32.f32 %0, %1;" : "=r"(r) : "f"(f));
    return r;
}
__device__ __forceinline__ float sigf(float x) {
    return 1.0f / (1.0f + expf(-x));
}

// ===========================================================================
// sm_103a PTX helpers (guarded)
// ===========================================================================
#if HAS_TCG
__device__ __forceinline__ uint32_t elect_one_pred() {
    uint32_t pred;
    asm volatile(
        "{\n\t.reg .pred p;\n\t"
        "elect.sync _|p, 0xFFFFFFFF;\n\t"
        "selp.b32 %0, 1, 0, p;\n\t}"
        : "=r"(pred));
    return pred;
}
__device__ __forceinline__ uint32_t smem_to_u32(const void* p) {
    uint32_t a;
    asm("{ .reg .u64 t; cvta.to.shared.u64 t, %1; cvt.u32.u64 %0, t; }"
        : "=r"(a) : "l"(p));
    return a;
}
#define MBARRIER_INIT(addr, cnt) \
    asm volatile("mbarrier.init.shared.b64 [%0], %1;" \
        :: "r"((uint32_t)(addr)), "r"((uint32_t)(cnt)) : "memory")
#define MBARRIER_EXPECT_TX(addr, bytes) \
    asm volatile("mbarrier.arrive.expect_tx.shared.b64 _, [%0], %1;" \
        :: "r"((uint32_t)(addr)), "r"((uint32_t)(bytes)) : "memory")
#define CP_ASYNC_BULK(dst, src, size, mbar) \
    asm volatile("cp.async.bulk.shared::cluster.global.mbarrier::complete_tx::bytes [%0], [%1], %2, [%3];" \
        :: "r"((uint32_t)(dst)), "l"(src), "r"((uint32_t)(size)), "r"((uint32_t)(mbar)) : "memory")

#define MBARRIER_WAIT_PARITY(mbar_smem_addr, phase_parity) do { \
    uint32_t _mbar = (uint32_t)(mbar_smem_addr); \
    uint32_t _parity = (uint32_t)(phase_parity); \
    uint32_t _done; \
    asm volatile( \
        "{\n\t.reg .pred p;\n\t" \
        "mbarrier.try_wait.parity.acquire.cta.shared::cta.b64 p, [%1], %2;\n\t" \
        "selp.b32 %0, 1, 0, p;\n\t}" \
        : "=r"(_done) : "r"(_mbar), "r"(_parity) : "memory"); \
    if (!_done) { \
        asm volatile( \
            "{\n\t.reg .pred P1;\n\t" \
            "WAIT_LOOP_%=:\n\t" \
            "mbarrier.try_wait.parity.acquire.cta.shared::cta.b64 P1, [%0], %1, 0x989680;\n\t" \
            "@P1 bra.uni WAIT_DONE_%=;\n\t" \
            "bra.uni WAIT_LOOP_%=;\n\t" \
            "WAIT_DONE_%=:\n\t}" \
            :: "r"(_mbar), "r"(_parity) : "memory"); \
    } \
} while(0)

#define TCGEN05_ALLOC(smem_result_addr, nCols) \
    asm volatile("tcgen05.alloc.cta_group::1.sync.aligned.shared::cta.b32 [%0], %1;" \
        :: "r"((uint32_t)(smem_result_addr)), "r"((uint32_t)(nCols)) : "memory")
#define TCGEN05_DEALLOC(tmem_addr, nCols) \
    asm volatile("tcgen05.dealloc.cta_group::1.sync.aligned.b32 %0, %1;" \
        :: "r"(tmem_addr), "r"((uint32_t)(nCols)))
#define TCGEN05_RELINQUISH() \
    asm volatile("tcgen05.relinquish_alloc_permit.cta_group::1.sync.aligned;")
#define TCGEN05_COMMIT(mbar_smem_addr) \
    asm volatile("tcgen05.commit.cta_group::1.mbarrier::arrive::one.shared::cluster.b64 [%0];" \
        :: "r"((uint32_t)(mbar_smem_addr)) : "memory")
#define TCGEN05_FENCE_AFTER() \
    asm volatile("tcgen05.fence::after_thread_sync;" ::: "memory")
#define TCGEN05_WAIT_LD() \
    asm volatile("tcgen05.wait::ld.sync.aligned;" ::: "memory")
#define FENCE_PROXY_ASYNC() \
    asm volatile("fence.proxy.async.shared::cta;" ::: "memory")

#define TCGEN05_LD_32X32B_X32(r, tmem_addr) \
    asm volatile( \
        "tcgen05.ld.sync.aligned.32x32b.x32.b32 " \
        "{%0, %1, %2, %3, %4, %5, %6, %7, " \
        " %8, %9, %10, %11, %12, %13, %14, %15, " \
        " %16, %17, %18, %19, %20, %21, %22, %23, " \
        " %24, %25, %26, %27, %28, %29, %30, %31}, [%32];" \
        : "=r"((r)[0]),  "=r"((r)[1]),  "=r"((r)[2]),  "=r"((r)[3]), \
          "=r"((r)[4]),  "=r"((r)[5]),  "=r"((r)[6]),  "=r"((r)[7]), \
          "=r"((r)[8]),  "=r"((r)[9]),  "=r"((r)[10]), "=r"((r)[11]), \
          "=r"((r)[12]), "=r"((r)[13]), "=r"((r)[14]), "=r"((r)[15]), \
          "=r"((r)[16]), "=r"((r)[17]), "=r"((r)[18]), "=r"((r)[19]), \
          "=r"((r)[20]), "=r"((r)[21]), "=r"((r)[22]), "=r"((r)[23]), \
          "=r"((r)[24]), "=r"((r)[25]), "=r"((r)[26]), "=r"((r)[27]), \
          "=r"((r)[28]), "=r"((r)[29]), "=r"((r)[30]), "=r"((r)[31]) \
        : "r"(tmem_addr))

// SMEM descriptor: K-major SW128, LBO=1, SBO=64, version=1 (Blackwell)
__device__ __forceinline__ uint64_t make_desc_sw128(uint32_t base_addr) {
    const uint64_t base =
        (uint64_t(2)  << 61) | (uint64_t(1) << 46) |
        (uint64_t(64) << 32) | (uint64_t(1) << 16);
    return base | ((uint64_t)(base_addr >> 4) & 0x3FFF);
}

// tf32 SS MMA, cta_group::1
__device__ __forceinline__ void mma_tf32_ss(
    uint32_t d_tmem, uint64_t a_desc, uint64_t b_desc,
    uint32_t idesc, uint32_t enable_d)
{
    asm volatile(
        "{\n\t.reg .pred p;\n\t"
        "setp.ne.u32 p, %5, 0;\n\t"
        "tcgen05.mma.cta_group::1.kind::tf32 [%0], %1, %2, %3, "
        "{%4, %4, %4, %4}, p;\n\t}"
        :: "r"(d_tmem), "l"(a_desc), "l"(b_desc), "r"(idesc),
           "r"(0u), "r"(enable_d)
        : "memory");
}
#endif  // HAS_TCG

// ===========================================================================
// tcgen05 tf32 GEMM: C[M,N] = act(A[M,K] @ B[N,K]^T + bias[N]) — known good
// ===========================================================================
#define TCG_SMEM_BYTES 66560

template<int ACT>
__global__ __launch_bounds__(256) void tc_gemm(
    const float* __restrict__ A, const float* __restrict__ Bm,
    const float* __restrict__ bias, float* __restrict__ C,
    int M, int N, int K)
{
#if HAS_TCG
    extern __shared__ char smem[];
    const uint32_t sb  = smem_to_u32(smem);
    const int tid  = threadIdx.x;
    const int w    = tid >> 5;
    const int lane = tid & 31;
    const int row0 = blockIdx.y * 128;
    const int col0 = blockIdx.x * 128;

    if (w == 0) { TCGEN05_ALLOC(sb, 128); TCGEN05_RELINQUISH(); }
    if (tid == 0) { MBARRIER_INIT(sb + 16, 1); MBARRIER_INIT(sb + 24, 1); }
    __syncthreads();
    uint32_t tmem;
    asm volatile("ld.shared.b32 %0, [%1];" : "=r"(tmem) : "r"(sb));

    const int lr  = tid >> 1;
    const int lcf = (tid & 1) * 16;
    const float* Ag = A  + (size_t)(row0 + lr) * K + lcf;
    const float* Bg = Bm + (size_t)(col0 + lr) * K + lcf;

    const uint32_t aoff[2] = {1024u, 17408u};
    const uint32_t boff[2] = {33792u, 50176u};
    int ph[2] = {0, 0};
    const int NC = K / 32;

    const uint32_t idesc = (1u << 4) | (2u << 7) | (2u << 10) |
                           ((128u / 8) << 17) | ((128u / 16) << 24);

    for (int c = 0; c < NC; c++) {
        const int b = c & 1;
        float4 av[4], bv[4];
        #pragma unroll
        for (int j = 0; j < 4; j++) {
            av[j] = *(const float4*)(Ag + (size_t)c * 32 + j * 4);
            bv[j] = *(const float4*)(Bg + (size_t)c * 32 + j * 4);
        }
        if (c >= 2) { MBARRIER_WAIT_PARITY(sb + 16 + 8 * b, ph[b]); ph[b] ^= 1; }
        #pragma unroll
        for (int j = 0; j < 4; j++) {
            uint4 ta, tb;
            ta.x = f2tf32(av[j].x); ta.y = f2tf32(av[j].y);
            ta.z = f2tf32(av[j].z); ta.w = f2tf32(av[j].w);
            tb.x = f2tf32(bv[j].x); tb.y = f2tf32(bv[j].y);
            tb.z = f2tf32(bv[j].z); tb.w = f2tf32(bv[j].w);
            const uint32_t byo = (uint32_t)(lr * 128 + (lcf + j * 4) * 4);
            *(uint4*)(smem + aoff[b] + SWZ(byo)) = ta;
            *(uint4*)(smem + boff[b] + SWZ(byo)) = tb;
        }
        FENCE_PROXY_ASYNC();
        __syncthreads();

        if (w == 0 && elect_one_pred()) {
            const uint64_t ad = make_desc_sw128(sb + aoff[b]);
            const uint64_t bd = make_desc_sw128(sb + boff[b]);
            #pragma unroll
            for (int k = 0; k < 4; k++)
                mma_tf32_ss(tmem, ad + k * 2, bd + k * 2, idesc,
                            (c > 0 || k > 0) ? 1u : 0u);
            TCGEN05_COMMIT(sb + 16 + 8 * b);
        }
    }
    {
        const int b = (NC - 1) & 1;
        MBARRIER_WAIT_PARITY(sb + 16 + 8 * b, ph[b]);
    }
    TCGEN05_FENCE_AFTER();

    const int rbase = (w & 3) * 32;
    const int csel  = (w >> 2) * 64;
    float* tr = reinterpret_cast<float*>(smem + 1024) + w * (32 * 33);

    #pragma unroll
    for (int half = 0; half < 2; half++) {
        const int cb = csel + half * 32;
        uint32_t regs[32];
        TCGEN05_LD_32X32B_X32(regs, tmem + cb);
        TCGEN05_WAIT_LD();
        __syncwarp();
        #pragma unroll
        for (int cc = 0; cc < 32; cc++)
            tr[lane * 33 + cc] = __uint_as_float(regs[cc]);
        __syncwarp();
        const int col = col0 + cb + lane;
        const float bvs = bias[col];
        #pragma unroll
        for (int r = 0; r < 32; r++) {
            float v = tr[r * 33 + lane] + bvs;
            if (ACT == 1) v = tanhf(v);
            C[(size_t)(row0 + rbase + r) * N + col] = v;
        }
        __syncwarp();
    }
    __syncthreads();
    if (w == 0) TCGEN05_DEALLOC(tmem, 128);
#else
    const int row0 = blockIdx.y * 128;
    const int col0 = blockIdx.x * 128;
    for (int idx = threadIdx.x; idx < 128 * 128; idx += 256) {
        const int r  = idx >> 7;
        const int cc = idx & 127;
        const float* a = A  + (size_t)(row0 + r)  * K;
        const float* b = Bm + (size_t)(col0 + cc) * K;
        float s = 0.0f;
        for (int k = 0; k < K; k++) s = fmaf(a[k], b[k], s);
        s += bias[col0 + cc];
        if (ACT == 1) s = tanhf(s);
        C[(size_t)(row0 + r) * N + (col0 + cc)] = s;
    }
#endif
}

// ===========================================================================
// whh_prep: Whh -> tf32, pre-swizzled per-(tile,chunk) images (known good)
// ===========================================================================
__global__ __launch_bounds__(256) void whh_prep(
    const float* __restrict__ Whh, float* __restrict__ Wt)
{
    const uint32_t stride = gridDim.x * blockDim.x;
    for (uint32_t u = blockIdx.x * blockDim.x + threadIdx.x;
         u < 786432u; u += stride) {
        const uint32_t tc   = u / 1536u;
        const uint32_t rem  = u - tc * 1536u;
        const uint32_t row  = rem >> 3;
        const uint32_t q    = rem & 7;
        const uint32_t tile = tc >> 5;
        const uint32_t chunk= tc & 31;
        const uint32_t g    = row >> 6;
        const uint32_t cidx = tile * 64 + (row & 63);
        const float4 v = *(const float4*)(
            Whh + ((size_t)(g * Hq + cidx)) * Hq + chunk * 32 + q * 4);
        uint4 o;
        o.x = f2tf32(v.x); o.y = f2tf32(v.y);
        o.z = f2tf32(v.z); o.w = f2tf32(v.w);
        *(uint4*)((char*)Wt + (size_t)tc * 24576 + SWZ(row * 128 + q * 16)) = o;
    }
}

// ===========================================================================
// gru_t0: first timestep (h_prev = 0), writes HID fp32 + tf32 A-prep images.
// ===========================================================================
__global__ __launch_bounds__(256) void gru_t0(
    const float* __restrict__ gx, const float* __restrict__ bhh,
    float* __restrict__ hout, float* __restrict__ aout)
{
    const int e = blockIdx.x * 256 + threadIdx.x;   // 384*1024 total
    const int m = e >> 10, c = e & 1023;
    const int bb = m / Pq, pp = m - bb * Pq;
    const float* gxr = gx + ((size_t)(bb * Tq) * Pq + pp) * GXW;  // t = 0
    const float r = sigf(gxr[c] + bhh[c]);
    const float z = sigf(gxr[c + Hq] + bhh[c + Hq]);
    const float n = tanhf(fmaf(r, bhh[c + 2 * Hq], gxr[c + 2 * Hq]));
    const float h = fmaf(z, -n, n);
    hout[e] = h;
    *(uint32_t*)((char*)aout + ((size_t)(m >> 7) * 32 + (c >> 5)) * 16384
                 + SWZ((m & 127) * 128 + (c & 31) * 4)) = f2tf32(h);
}

// ===========================================================================
// gru_tc: one GRU timestep, fully async feed.
// CTA: 128 rows x (64 h-cols x 3 gates). Grid (16, 3), 256 threads.
// Operands arrive via cp.async.bulk from PRE-SWIZZLED tf32 gmem images
// (A: g_Ap parity buffer written by previous step; B: g_Wt). tid0 drives a
// 4-stage pipeline (prefetch distance 3) + MMA issue; stage recycling is
// gated on tcgen05.commit completion mbarriers.
// ===========================================================================
#define GRU_STAGE 40960
#define GRU_SMEM  (1024 + 4 * GRU_STAGE)   // 164864

__global__ __launch_bounds__(256) void gru_tc(
    const float* __restrict__ hprev, const float* __restrict__ aprev,
    const float* __restrict__ Wt,    const float* __restrict__ gx,
    const float* __restrict__ bhh,   float* __restrict__ hout,
    float* __restrict__ aout, int t)
{
#if HAS_TCG
    extern __shared__ char smem[];
    const uint32_t sb  = smem_to_u32(smem);
    const int tid  = threadIdx.x;
    const int w    = tid >> 5;
    const int lane = tid & 31;
    const int row0 = blockIdx.y * 128;
    const int cb   = blockIdx.x * 64;

    // mbars: full[s]=sb+16+8s, done[s]=sb+48+8s, final=sb+80
    if (w == 0) { TCGEN05_ALLOC(sb, 256); TCGEN05_RELINQUISH(); }
    if (tid == 0) {
        #pragma unroll
        for (int s = 0; s < 4; s++) {
            MBARRIER_INIT(sb + 16 + 8 * s, 1);
            MBARRIER_INIT(sb + 48 + 8 * s, 1);
        }
        MBARRIER_INIT(sb + 80, 1);
    }
    __syncthreads();
    uint32_t tmem;
    asm volatile("ld.shared.b32 %0, [%1];" : "=r"(tmem) : "r"(sb));

    const uint32_t idesc = (1u << 4) | (2u << 7) | (2u << 10) |
                           ((64u / 8) << 17) | ((128u / 16) << 24);

    if (tid == 0) {
        const char* Asrc = (const char*)aprev + (size_t)blockIdx.y * 32 * 16384;
        const char* Bsrc = (const char*)Wt + (size_t)blockIdx.x * 32 * 24576;

        // prologue: stages 0..2 <- chunks 0..2
        #pragma unroll
        for (int c = 0; c < 3; c++) {
            const uint32_t st = sb + 1024 + c * GRU_STAGE;
            MBARRIER_EXPECT_TX(sb + 16 + 8 * c, GRU_STAGE);
            CP_ASYNC_BULK(st,         Asrc + (size_t)c * 16384, 16384, sb + 16 + 8 * c);
            CP_ASYNC_BULK(st + 16384, Bsrc + (size_t)c * 24576, 24576, sb + 16 + 8 * c);
        }

        int phF[4] = {0, 0, 0, 0}, phD[4] = {0, 0, 0, 0};
        for (int c = 0; c < 32; c++) {
            const int s = c & 3;
            MBARRIER_WAIT_PARITY(sb + 16 + 8 * s, phF[s]); phF[s] ^= 1;
            const uint32_t st = sb + 1024 + s * GRU_STAGE;
            const uint64_t ad = make_desc_sw128(st);
            #pragma unroll
            for (int k = 0; k < 4; k++) {
                #pragma unroll
                for (int g = 0; g < 3; g++) {
                    const uint64_t bd =
                        make_desc_sw128(st + 16384 + g * 8192) + k * 2;
                    mma_tf32_ss(tmem + g * 64, ad + k * 2, bd, idesc,
                                (c > 0 || k > 0) ? 1u : 0u);
                }
            }
            TCGEN05_COMMIT(sb + 48 + 8 * s);

            const int cn = c + 3;
            if (cn < 32) {
                const int s2 = cn & 3;         // == (c-1)&3 for c>=1
                if (c >= 1) {                  // recycle: wait chunk c-1 done
                    MBARRIER_WAIT_PARITY(sb + 48 + 8 * s2, phD[s2]);
                    phD[s2] ^= 1;
                }
                const uint32_t st2 = sb + 1024 + s2 * GRU_STAGE;
                MBARRIER_EXPECT_TX(sb + 16 + 8 * s2, GRU_STAGE);
                CP_ASYNC_BULK(st2,         Asrc + (size_t)cn * 16384, 16384, sb + 16 + 8 * s2);
                CP_ASYNC_BULK(st2 + 16384, Bsrc + (size_t)cn * 24576, 24576, sb + 16 + 8 * s2);
            }
        }
        TCGEN05_COMMIT(sb + 80);   // cumulative: fires when ALL MMAs complete
    }

    MBARRIER_WAIT_PARITY(sb + 80, 0);
    TCGEN05_FENCE_AFTER();
    __syncthreads();

    // ---- fused epilogue ----
    const int r0 = (w & 3) * 32;
    const int c0 = (w >> 2) * 32;
    float* tr = reinterpret_cast<float*>(smem + 1024) + w * (32 * 33);

    float ga[3][32];
    #pragma unroll
    for (int g = 0; g < 3; g++) {
        uint32_t regs[32];
        TCGEN05_LD_32X32B_X32(regs, tmem + g * 64 + c0);
        TCGEN05_WAIT_LD();
        __syncwarp();
        #pragma unroll
        for (int j = 0; j < 32; j++) tr[lane * 33 + j] = __uint_as_float(regs[j]);
        __syncwarp();
        #pragma unroll
        for (int i = 0; i < 32; i++) ga[g][i] = tr[i * 33 + lane];
        __syncwarp();
    }

    const int c = cb + c0 + lane;
    const float br_ = bhh[c];
    const float bz_ = bhh[c + Hq];
    const float bn_ = bhh[c + 2 * Hq];
    char* adst = (char*)aout +
        ((size_t)blockIdx.y * 32 + (2 * blockIdx.x + (w >> 2))) * 16384;
    #pragma unroll
    for (int i = 0; i < 32; i++) {
        const int m  = row0 + r0 + i;
        const int bb = m / Pq;
        const int pp = m - bb * Pq;
        const float* gxr = gx + ((size_t)(bb * Tq + t) * Pq + pp) * GXW;
        const float r = sigf(gxr[c] + ga[0][i] + br_);
        const float z = sigf(gxr[c + Hq] + ga[1][i] + bz_);
        const float n = tanhf(fmaf(r, ga[2][i] + bn_, gxr[c + 2 * Hq]));
        const float hp = hprev[(size_t)m * Hq + c];
        const float h  = fmaf(z, hp - n, n);
        hout[(size_t)m * Hq + c] = h;
        *(uint32_t*)(adst + SWZ((r0 + i) * 128 + lane * 4)) = f2tf32(h);
    }

    __syncthreads();
    if (w == 0) TCGEN05_DEALLOC(tmem, 256);
#else
    // Fallback body (plain compute_103 pass; never executed).
    const int row0 = blockIdx.y * 128;
    const int cb   = blockIdx.x * 64;
    for (int idx = threadIdx.x; idx < 128 * 64; idx += 256) {
        const int m = row0 + (idx >> 6);
        const int c = cb + (idx & 63);
        const int bb = m / Pq, pp = m - bb * Pq;
        const float* gxr = gx + ((size_t)(bb * Tq + t) * Pq + pp) * GXW;
        const float r = sigf(gxr[c] + bhh[c]);
        const float z = sigf(gxr[c + Hq] + bhh[c + Hq]);
        const float n = tanhf(fmaf(r, bhh[c + 2 * Hq], gxr[c + 2 * Hq]));
        const float hp = hprev[(size_t)m * Hq + c];
        hout[(size_t)m * Hq + c] = fmaf(z, hp - n, n);
        (void)aout; (void)aprev; (void)Wt;
    }
#endif
}

// ---------------------------------------------------------------------------
// Heads (unchanged)
// ---------------------------------------------------------------------------
__global__ __launch_bounds__(256) void action_head(
    const float* __restrict__ hid, const float* __restrict__ Wact,
    const float* __restrict__ bact, float* __restrict__ out)
{
    const int warp = (blockIdx.x * blockDim.x + threadIdx.x) >> 5;
    const int lane = threadIdx.x & 31;
    if (warp >= NROWS) return;
    const int n  = warp;
    const int bb = n / (Tq * Pq);
    const int rm = n - bb * (Tq * Pq);
    const int tt = rm / Pq;
    const int pp = rm - tt * Pq;
    const float* h = hid + ((size_t)tt * BP + bb * Pq + pp) * Hq;

    float s[9] = {};
    for (int k = lane; k < Hq; k += 32) {
        const float hv = h[k];
        #pragma unroll
        for (int a = 0; a < 9; a++) s[a] = fmaf(hv, Wact[a * Hq + k], s[a]);
    }
    #pragma unroll
    for (int a = 0; a < 9; a++)
        #pragma unroll
        for (int off = 16; off; off >>= 1)
            s[a] += __shfl_xor_sync(0xFFFFFFFFu, s[a], off);
    if (lane < 9) out[(size_t)n * 9 + lane] = s[lane] + bact[lane];
}

__global__ __launch_bounds__(256) void activity_head(
    const float* __restrict__ hid, const float* __restrict__ Wactv,
    const float* __restrict__ bactv, float* __restrict__ out)
{
    const int warp = (blockIdx.x * blockDim.x + threadIdx.x) >> 5;
    const int lane = threadIdx.x & 31;
    if (warp >= Bq * Tq) return;
    const int bb = warp / Tq;
    const int tt = warp - bb * Tq;
    const float* base = hid + ((size_t)tt * BP + bb * Pq) * Hq;

    float s[8] = {};
    for (int k = lane; k < Hq; k += 32) {
        float mx = base[k];
        #pragma unroll
        for (int p = 1; p < Pq; p++) mx = fmaxf(mx, base[(size_t)p * Hq + k]);
        #pragma unroll
        for (int a = 0; a < 8; a++) s[a] = fmaf(mx, Wactv[a * Hq + k], s[a]);
    }
    #pragma unroll
    for (int a = 0; a < 8; a++)
        #pragma unroll
        for (int off = 16; off; off >>= 1)
            s[a] += __shfl_xor_sync(0xFFFFFFFFu, s[a], off);
    if (lane < 8) out[(size_t)warp * 8 + lane] = s[lane] + bactv[lane];
}

// ---------------------------------------------------------------------------
extern "C" void kernel_launch(void* const* d_in, const int* in_sizes, int n_in,
                              void* d_out, int out_size)
{
    const float* feature = (const float*)d_in[0];
    const float* W_embed = (const float*)d_in[1];
    const float* b_embed = (const float*)d_in[2];
    const float* W_ih    = (const float*)d_in[3];
    const float* W_hh    = (const float*)d_in[4];
    const float* b_ih    = (const float*)d_in[5];
    const float* b_hh    = (const float*)d_in[6];
    const float* W_act   = (const float*)d_in[7];
    const float* b_act   = (const float*)d_in[8];
    const float* W_activ = (const float*)d_in[9];
    const float* b_activ = (const float*)d_in[10];
    float* out = (float*)d_out;

    float *X, *GX, *HID, *WT, *AP;
    cudaGetSymbolAddress((void**)&X,   g_X);
    cudaGetSymbolAddress((void**)&GX,  g_GX);
    cudaGetSymbolAddress((void**)&HID, g_H);
    cudaGetSymbolAddress((void**)&WT,  g_Wt);
    cudaGetSymbolAddress((void**)&AP,  g_Ap);

    cudaFuncSetAttribute(tc_gemm<1>,
        cudaFuncAttributeMaxDynamicSharedMemorySize, TCG_SMEM_BYTES);
    cudaFuncSetAttribute(tc_gemm<0>,
        cudaFuncAttributeMaxDynamicSharedMemorySize, TCG_SMEM_BYTES);
    cudaFuncSetAttribute(gru_tc,
        cudaFuncAttributeMaxDynamicSharedMemorySize, GRU_SMEM);

    // 0) Whh -> tf32 pre-swizzled images
    whh_prep<<<768, 256>>>(W_hh, WT);

    // 1) embed: X = tanh(feature @ W_embed^T + b_embed)   [15360,1024]
    tc_gemm<1><<<dim3(Hq / 128, NROWS / 128), 256, TCG_SMEM_BYTES>>>(
        feature, W_embed, b_embed, X, NROWS, Hq, Eq);

    // 2) input gates: GX = X @ W_ih^T + b_ih              [15360,3072]
    tc_gemm<0><<<dim3(GXW / 128, NROWS / 128), 256, TCG_SMEM_BYTES>>>(
        X, W_ih, b_ih, GX, NROWS, GXW, Hq);

    // 3) recurrence
    gru_t0<<<(BP * Hq) / 256, 256>>>(GX, b_hh, HID, AP);
    for (int t = 1; t < Tq; t++) {
        const float* hprev = HID + (size_t)(t - 1) * BP * Hq;
        float* hout = HID + (size_t)t * BP * Hq;
        const float* aprev = AP + ((size_t)((t - 1) & 1)) * APSZ;
        float* aout        = AP + ((size_t)(t & 1)) * APSZ;
        gru_tc<<<dim3(16, 3), 256, GRU_SMEM>>>(
            hprev, aprev, WT, GX, b_hh, hout, aout, t);
    }

    // 4) heads
    action_head<<<(NROWS * 32 + 255) / 256, 256>>>(HID, W_act, b_act, out);
    activity_head<<<(Bq * Tq * 32 + 255) / 256, 256>>>(
        HID, W_activ, b_activ, out + (size_t)NROWS * 9);
}

// round 9
// speedup vs baseline: 2.5806x; 1.1067x over previous
#include <cuda_runtime.h>
#include <cstdint>
#include <math.h>

// Problem constants
#define Bq   32
#define Tq   40
#define Pq   12
#define Eq   2048
#define Hq   1024
#define BP   384          // B*P
#define NROWS 15360       // B*T*P
#define GXW  3072         // 3*H

// tcgen05 is an 'a'-feature: only in the sm_103a/sm_100a device pass.
#if !defined(__CUDA_ARCH__) || defined(__CUDA_ARCH_FEAT_SM103_ALL) || defined(__CUDA_ARCH_FEAT_SM100_ALL)
#define HAS_TCG 1
#else
#define HAS_TCG 0
#endif

// Scratch (device globals: allocation-free rule)
__device__ float g_X [(size_t)NROWS * Hq];   // embedded+tanh  [B,T,P,H]
__device__ float g_GX[(size_t)NROWS * GXW];  // input gates    [B,T,P,3H]
__device__ float g_H [(size_t)Tq * BP * Hq]; // hiddens        [T,B,P,H]
// Whh tf32 pre-swizzled images: [16 col-tiles][32 K-chunks][192 rows x 128B]
__device__ float g_Wt[(size_t)16 * 32 * 6144];
// h as tf32 pre-swizzled A images, double parity:
// [2][3 rowtiles][32 chunks][128 rows x 32 cols] = 2 x 1.5MB
#define APSZ ((size_t)3 * 32 * 4096)
__device__ float g_Ap[2 * APSZ];

#define SWZ(o) ((o) ^ ((((uint32_t)(o)) >> 3) & 0x70u))

__device__ __forceinline__ uint32_t f2tf32(float f) {
    uint32_t r;
    asm("cvt.rna.tf32.f32 %0, %1;" : "=r"(r) : "f"(f));
    return r;
}
__device__ __forceinline__ float sigf(float x) {
    return 1.0f / (1.0f + expf(-x));
}

// ===========================================================================
// sm_103a PTX helpers (guarded)
// ===========================================================================
#if HAS_TCG
__device__ __forceinline__ uint32_t elect_one_pred() {
    uint32_t pred;
    asm volatile(
        "{\n\t.reg .pred p;\n\t"
        "elect.sync _|p, 0xFFFFFFFF;\n\t"
        "selp.b32 %0, 1, 0, p;\n\t}"
        : "=r"(pred));
    return pred;
}
__device__ __forceinline__ uint32_t smem_to_u32(const void* p) {
    uint32_t a;
    asm("{ .reg .u64 t; cvta.to.shared.u64 t, %1; cvt.u32.u64 %0, t; }"
        : "=r"(a) : "l"(p));
    return a;
}
#define MBARRIER_INIT(addr, cnt) \
    asm volatile("mbarrier.init.shared.b64 [%0], %1;" \
        :: "r"((uint32_t)(addr)), "r"((uint32_t)(cnt)) : "memory")
#define MBARRIER_EXPECT_TX(addr, bytes) \
    asm volatile("mbarrier.arrive.expect_tx.shared.b64 _, [%0], %1;" \
        :: "r"((uint32_t)(addr)), "r"((uint32_t)(bytes)) : "memory")
#define CP_ASYNC_BULK(dst, src, size, mbar) \
    asm volatile("cp.async.bulk.shared::cluster.global.mbarrier::complete_tx::bytes [%0], [%1], %2, [%3];" \
        :: "r"((uint32_t)(dst)), "l"(src), "r"((uint32_t)(size)), "r"((uint32_t)(mbar)) : "memory")

#define MBARRIER_WAIT_PARITY(mbar_smem_addr, phase_parity) do { \
    uint32_t _mbar = (uint32_t)(mbar_smem_addr); \
    uint32_t _parity = (uint32_t)(phase_parity); \
    uint32_t _done; \
    asm volatile( \
        "{\n\t.reg .pred p;\n\t" \
        "mbarrier.try_wait.parity.acquire.cta.shared::cta.b64 p, [%1], %2;\n\t" \
        "selp.b32 %0, 1, 0, p;\n\t}" \
        : "=r"(_done) : "r"(_mbar), "r"(_parity) : "memory"); \
    if (!_done) { \
        asm volatile( \
            "{\n\t.reg .pred P1;\n\t" \
            "WAIT_LOOP_%=:\n\t" \
            "mbarrier.try_wait.parity.acquire.cta.shared::cta.b64 P1, [%0], %1, 0x989680;\n\t" \
            "@P1 bra.uni WAIT_DONE_%=;\n\t" \
            "bra.uni WAIT_LOOP_%=;\n\t" \
            "WAIT_DONE_%=:\n\t}" \
            :: "r"(_mbar), "r"(_parity) : "memory"); \
    } \
} while(0)

#define TCGEN05_ALLOC(smem_result_addr, nCols) \
    asm volatile("tcgen05.alloc.cta_group::1.sync.aligned.shared::cta.b32 [%0], %1;" \
        :: "r"((uint32_t)(smem_result_addr)), "r"((uint32_t)(nCols)) : "memory")
#define TCGEN05_DEALLOC(tmem_addr, nCols) \
    asm volatile("tcgen05.dealloc.cta_group::1.sync.aligned.b32 %0, %1;" \
        :: "r"(tmem_addr), "r"((uint32_t)(nCols)))
#define TCGEN05_RELINQUISH() \
    asm volatile("tcgen05.relinquish_alloc_permit.cta_group::1.sync.aligned;")
#define TCGEN05_COMMIT(mbar_smem_addr) \
    asm volatile("tcgen05.commit.cta_group::1.mbarrier::arrive::one.shared::cluster.b64 [%0];" \
        :: "r"((uint32_t)(mbar_smem_addr)) : "memory")
#define TCGEN05_FENCE_AFTER() \
    asm volatile("tcgen05.fence::after_thread_sync;" ::: "memory")
#define TCGEN05_WAIT_LD() \
    asm volatile("tcgen05.wait::ld.sync.aligned;" ::: "memory")
#define FENCE_PROXY_ASYNC() \
    asm volatile("fence.proxy.async.shared::cta;" ::: "memory")

#define TCGEN05_LD_32X32B_X32(r, tmem_addr) \
    asm volatile( \
        "tcgen05.ld.sync.aligned.32x32b.x32.b32 " \
        "{%0, %1, %2, %3, %4, %5, %6, %7, " \
        " %8, %9, %10, %11, %12, %13, %14, %15, " \
        " %16, %17, %18, %19, %20, %21, %22, %23, " \
        " %24, %25, %26, %27, %28, %29, %30, %31}, [%32];" \
        : "=r"((r)[0]),  "=r"((r)[1]),  "=r"((r)[2]),  "=r"((r)[3]), \
          "=r"((r)[4]),  "=r"((r)[5]),  "=r"((r)[6]),  "=r"((r)[7]), \
          "=r"((r)[8]),  "=r"((r)[9]),  "=r"((r)[10]), "=r"((r)[11]), \
          "=r"((r)[12]), "=r"((r)[13]), "=r"((r)[14]), "=r"((r)[15]), \
          "=r"((r)[16]), "=r"((r)[17]), "=r"((r)[18]), "=r"((r)[19]), \
          "=r"((r)[20]), "=r"((r)[21]), "=r"((r)[22]), "=r"((r)[23]), \
          "=r"((r)[24]), "=r"((r)[25]), "=r"((r)[26]), "=r"((r)[27]), \
          "=r"((r)[28]), "=r"((r)[29]), "=r"((r)[30]), "=r"((r)[31]) \
        : "r"(tmem_addr))

// SMEM descriptor: K-major SW128, LBO=1, SBO=64, version=1 (Blackwell)
__device__ __forceinline__ uint64_t make_desc_sw128(uint32_t base_addr) {
    const uint64_t base =
        (uint64_t(2)  << 61) | (uint64_t(1) << 46) |
        (uint64_t(64) << 32) | (uint64_t(1) << 16);
    return base | ((uint64_t)(base_addr >> 4) & 0x3FFF);
}

// tf32 SS MMA, cta_group::1
__device__ __forceinline__ void mma_tf32_ss(
    uint32_t d_tmem, uint64_t a_desc, uint64_t b_desc,
    uint32_t idesc, uint32_t enable_d)
{
    asm volatile(
        "{\n\t.reg .pred p;\n\t"
        "setp.ne.u32 p, %5, 0;\n\t"
        "tcgen05.mma.cta_group::1.kind::tf32 [%0], %1, %2, %3, "
        "{%4, %4, %4, %4}, p;\n\t}"
        :: "r"(d_tmem), "l"(a_desc), "l"(b_desc), "r"(idesc),
           "r"(0u), "r"(enable_d)
        : "memory");
}
#endif  // HAS_TCG

// ===========================================================================
// tcgen05 tf32 GEMM: C[M,N] = act(A[M,K] @ B[N,K]^T + bias[N]) — known good
// ===========================================================================
#define TCG_SMEM_BYTES 66560

template<int ACT>
__global__ __launch_bounds__(256) void tc_gemm(
    const float* __restrict__ A, const float* __restrict__ Bm,
    const float* __restrict__ bias, float* __restrict__ C,
    int M, int N, int K)
{
#if HAS_TCG
    extern __shared__ char smem[];
    const uint32_t sb  = smem_to_u32(smem);
    const int tid  = threadIdx.x;
    const int w    = tid >> 5;
    const int lane = tid & 31;
    const int row0 = blockIdx.y * 128;
    const int col0 = blockIdx.x * 128;

    if (w == 0) { TCGEN05_ALLOC(sb, 128); TCGEN05_RELINQUISH(); }
    if (tid == 0) { MBARRIER_INIT(sb + 16, 1); MBARRIER_INIT(sb + 24, 1); }
    __syncthreads();
    uint32_t tmem;
    asm volatile("ld.shared.b32 %0, [%1];" : "=r"(tmem) : "r"(sb));

    const int lr  = tid >> 1;
    const int lcf = (tid & 1) * 16;
    const float* Ag = A  + (size_t)(row0 + lr) * K + lcf;
    const float* Bg = Bm + (size_t)(col0 + lr) * K + lcf;

    const uint32_t aoff[2] = {1024u, 17408u};
    const uint32_t boff[2] = {33792u, 50176u};
    int ph[2] = {0, 0};
    const int NC = K / 32;

    const uint32_t idesc = (1u << 4) | (2u << 7) | (2u << 10) |
                           ((128u / 8) << 17) | ((128u / 16) << 24);

    for (int c = 0; c < NC; c++) {
        const int b = c & 1;
        float4 av[4], bv[4];
        #pragma unroll
        for (int j = 0; j < 4; j++) {
            av[j] = *(const float4*)(Ag + (size_t)c * 32 + j * 4);
            bv[j] = *(const float4*)(Bg + (size_t)c * 32 + j * 4);
        }
        if (c >= 2) { MBARRIER_WAIT_PARITY(sb + 16 + 8 * b, ph[b]); ph[b] ^= 1; }
        #pragma unroll
        for (int j = 0; j < 4; j++) {
            uint4 ta, tb;
            ta.x = f2tf32(av[j].x); ta.y = f2tf32(av[j].y);
            ta.z = f2tf32(av[j].z); ta.w = f2tf32(av[j].w);
            tb.x = f2tf32(bv[j].x); tb.y = f2tf32(bv[j].y);
            tb.z = f2tf32(bv[j].z); tb.w = f2tf32(bv[j].w);
            const uint32_t byo = (uint32_t)(lr * 128 + (lcf + j * 4) * 4);
            *(uint4*)(smem + aoff[b] + SWZ(byo)) = ta;
            *(uint4*)(smem + boff[b] + SWZ(byo)) = tb;
        }
        FENCE_PROXY_ASYNC();
        __syncthreads();

        if (w == 0 && elect_one_pred()) {
            const uint64_t ad = make_desc_sw128(sb + aoff[b]);
            const uint64_t bd = make_desc_sw128(sb + boff[b]);
            #pragma unroll
            for (int k = 0; k < 4; k++)
                mma_tf32_ss(tmem, ad + k * 2, bd + k * 2, idesc,
                            (c > 0 || k > 0) ? 1u : 0u);
            TCGEN05_COMMIT(sb + 16 + 8 * b);
        }
    }
    {
        const int b = (NC - 1) & 1;
        MBARRIER_WAIT_PARITY(sb + 16 + 8 * b, ph[b]);
    }
    TCGEN05_FENCE_AFTER();

    const int rbase = (w & 3) * 32;
    const int csel  = (w >> 2) * 64;
    float* tr = reinterpret_cast<float*>(smem + 1024) + w * (32 * 33);

    #pragma unroll
    for (int half = 0; half < 2; half++) {
        const int cb = csel + half * 32;
        uint32_t regs[32];
        TCGEN05_LD_32X32B_X32(regs, tmem + cb);
        TCGEN05_WAIT_LD();
        __syncwarp();
        #pragma unroll
        for (int cc = 0; cc < 32; cc++)
            tr[lane * 33 + cc] = __uint_as_float(regs[cc]);
        __syncwarp();
        const int col = col0 + cb + lane;
        const float bvs = bias[col];
        #pragma unroll
        for (int r = 0; r < 32; r++) {
            float v = tr[r * 33 + lane] + bvs;
            if (ACT == 1) v = tanhf(v);
            C[(size_t)(row0 + rbase + r) * N + col] = v;
        }
        __syncwarp();
    }
    __syncthreads();
    if (w == 0) TCGEN05_DEALLOC(tmem, 128);
#else
    const int row0 = blockIdx.y * 128;
    const int col0 = blockIdx.x * 128;
    for (int idx = threadIdx.x; idx < 128 * 128; idx += 256) {
        const int r  = idx >> 7;
        const int cc = idx & 127;
        const float* a = A  + (size_t)(row0 + r)  * K;
        const float* b = Bm + (size_t)(col0 + cc) * K;
        float s = 0.0f;
        for (int k = 0; k < K; k++) s = fmaf(a[k], b[k], s);
        s += bias[col0 + cc];
        if (ACT == 1) s = tanhf(s);
        C[(size_t)(row0 + r) * N + (col0 + cc)] = s;
    }
#endif
}

// ===========================================================================
// whh_prep: Whh -> tf32, pre-swizzled per-(tile,chunk) images (known good)
// ===========================================================================
__global__ __launch_bounds__(256) void whh_prep(
    const float* __restrict__ Whh, float* __restrict__ Wt)
{
    const uint32_t stride = gridDim.x * blockDim.x;
    for (uint32_t u = blockIdx.x * blockDim.x + threadIdx.x;
         u < 786432u; u += stride) {
        const uint32_t tc   = u / 1536u;
        const uint32_t rem  = u - tc * 1536u;
        const uint32_t row  = rem >> 3;
        const uint32_t q    = rem & 7;
        const uint32_t tile = tc >> 5;
        const uint32_t chunk= tc & 31;
        const uint32_t g    = row >> 6;
        const uint32_t cidx = tile * 64 + (row & 63);
        const float4 v = *(const float4*)(
            Whh + ((size_t)(g * Hq + cidx)) * Hq + chunk * 32 + q * 4);
        uint4 o;
        o.x = f2tf32(v.x); o.y = f2tf32(v.y);
        o.z = f2tf32(v.z); o.w = f2tf32(v.w);
        *(uint4*)((char*)Wt + (size_t)tc * 24576 + SWZ(row * 128 + q * 16)) = o;
    }
}

// ===========================================================================
// gru_t0: first timestep (h_prev = 0), writes HID fp32 + tf32 A-prep images.
// ===========================================================================
__global__ __launch_bounds__(256) void gru_t0(
    const float* __restrict__ gx, const float* __restrict__ bhh,
    float* __restrict__ hout, float* __restrict__ aout)
{
    const int e = blockIdx.x * 256 + threadIdx.x;   // 384*1024 total
    const int m = e >> 10, c = e & 1023;
    const int bb = m / Pq, pp = m - bb * Pq;
    const float* gxr = gx + ((size_t)(bb * Tq) * Pq + pp) * GXW;  // t = 0
    const float r = sigf(gxr[c] + bhh[c]);
    const float z = sigf(gxr[c + Hq] + bhh[c + Hq]);
    const float n = tanhf(fmaf(r, bhh[c + 2 * Hq], gxr[c + 2 * Hq]));
    const float h = fmaf(z, -n, n);
    hout[e] = h;
    *(uint32_t*)((char*)aout + ((size_t)(m >> 7) * 32 + (c >> 5)) * 16384
                 + SWZ((m & 127) * 128 + (c & 31) * 4)) = f2tf32(h);
}

// ===========================================================================
// gru_tc: one GRU timestep, fully async feed, N=192 fused-gate MMAs.
// CTA: 128 rows x (64 h-cols x 3 gates = 192 N). Grid (16, 3), 256 threads.
// The 3 gate B-images are contiguous (rows 0-63=r, 64-127=z, 128-191=n), so
// ONE MMA with N=192 covers all gates: 4 MMAs per 32-K chunk instead of 12,
// amortizing the per-SS-MMA fixed cost 3x (K is locked at 8 for tf32).
// D = [128 x 192] fp32 in TMEM, gate g at col g*64 (epilogue unchanged).
// ===========================================================================
#define GRU_STAGE 40960
#define GRU_SMEM  (1024 + 4 * GRU_STAGE)   // 164864

__global__ __launch_bounds__(256) void gru_tc(
    const float* __restrict__ hprev, const float* __restrict__ aprev,
    const float* __restrict__ Wt,    const float* __restrict__ gx,
    const float* __restrict__ bhh,   float* __restrict__ hout,
    float* __restrict__ aout, int t)
{
#if HAS_TCG
    extern __shared__ char smem[];
    const uint32_t sb  = smem_to_u32(smem);
    const int tid  = threadIdx.x;
    const int w    = tid >> 5;
    const int lane = tid & 31;
    const int row0 = blockIdx.y * 128;
    const int cb   = blockIdx.x * 64;

    // mbars: full[s]=sb+16+8s, done[s]=sb+48+8s, final=sb+80
    if (w == 0) { TCGEN05_ALLOC(sb, 256); TCGEN05_RELINQUISH(); }
    if (tid == 0) {
        #pragma unroll
        for (int s = 0; s < 4; s++) {
            MBARRIER_INIT(sb + 16 + 8 * s, 1);
            MBARRIER_INIT(sb + 48 + 8 * s, 1);
        }
        MBARRIER_INIT(sb + 80, 1);
    }
    __syncthreads();
    uint32_t tmem;
    asm volatile("ld.shared.b32 %0, [%1];" : "=r"(tmem) : "r"(sb));

    // N=192: one MMA spans all 3 gate B-images (24 8-row groups via SBO)
    const uint32_t idesc = (1u << 4) | (2u << 7) | (2u << 10) |
                           ((192u / 8) << 17) | ((128u / 16) << 24);

    if (tid == 0) {
        const char* Asrc = (const char*)aprev + (size_t)blockIdx.y * 32 * 16384;
        const char* Bsrc = (const char*)Wt + (size_t)blockIdx.x * 32 * 24576;

        // prologue: stages 0..2 <- chunks 0..2
        #pragma unroll
        for (int c = 0; c < 3; c++) {
            const uint32_t st = sb + 1024 + c * GRU_STAGE;
            MBARRIER_EXPECT_TX(sb + 16 + 8 * c, GRU_STAGE);
            CP_ASYNC_BULK(st,         Asrc + (size_t)c * 16384, 16384, sb + 16 + 8 * c);
            CP_ASYNC_BULK(st + 16384, Bsrc + (size_t)c * 24576, 24576, sb + 16 + 8 * c);
        }

        int phF[4] = {0, 0, 0, 0}, phD[4] = {0, 0, 0, 0};
        for (int c = 0; c < 32; c++) {
            const int s = c & 3;
            MBARRIER_WAIT_PARITY(sb + 16 + 8 * s, phF[s]); phF[s] ^= 1;
            const uint32_t st = sb + 1024 + s * GRU_STAGE;
            const uint64_t ad = make_desc_sw128(st);
            const uint64_t bd = make_desc_sw128(st + 16384);
            #pragma unroll
            for (int k = 0; k < 4; k++)
                mma_tf32_ss(tmem, ad + k * 2, bd + k * 2, idesc,
                            (c > 0 || k > 0) ? 1u : 0u);
            TCGEN05_COMMIT(sb + 48 + 8 * s);

            const int cn = c + 3;
            if (cn < 32) {
                const int s2 = cn & 3;         // == (c-1)&3 for c>=1
                if (c >= 1) {                  // recycle: wait chunk c-1 done
                    MBARRIER_WAIT_PARITY(sb + 48 + 8 * s2, phD[s2]);
                    phD[s2] ^= 1;
                }
                const uint32_t st2 = sb + 1024 + s2 * GRU_STAGE;
                MBARRIER_EXPECT_TX(sb + 16 + 8 * s2, GRU_STAGE);
                CP_ASYNC_BULK(st2,         Asrc + (size_t)cn * 16384, 16384, sb + 16 + 8 * s2);
                CP_ASYNC_BULK(st2 + 16384, Bsrc + (size_t)cn * 24576, 24576, sb + 16 + 8 * s2);
            }
        }
        TCGEN05_COMMIT(sb + 80);   // cumulative: fires when ALL MMAs complete
    }

    MBARRIER_WAIT_PARITY(sb + 80, 0);
    TCGEN05_FENCE_AFTER();
    __syncthreads();

    // ---- fused epilogue (layout identical: gate g at TMEM col g*64) ----
    const int r0 = (w & 3) * 32;
    const int c0 = (w >> 2) * 32;
    float* tr = reinterpret_cast<float*>(smem + 1024) + w * (32 * 33);

    float ga[3][32];
    #pragma unroll
    for (int g = 0; g < 3; g++) {
        uint32_t regs[32];
        TCGEN05_LD_32X32B_X32(regs, tmem + g * 64 + c0);
        TCGEN05_WAIT_LD();
        __syncwarp();
        #pragma unroll
        for (int j = 0; j < 32; j++) tr[lane * 33 + j] = __uint_as_float(regs[j]);
        __syncwarp();
        #pragma unroll
        for (int i = 0; i < 32; i++) ga[g][i] = tr[i * 33 + lane];
        __syncwarp();
    }

    const int c = cb + c0 + lane;
    const float br_ = bhh[c];
    const float bz_ = bhh[c + Hq];
    const float bn_ = bhh[c + 2 * Hq];
    char* adst = (char*)aout +
        ((size_t)blockIdx.y * 32 + (2 * blockIdx.x + (w >> 2))) * 16384;
    #pragma unroll
    for (int i = 0; i < 32; i++) {
        const int m  = row0 + r0 + i;
        const int bb = m / Pq;
        const int pp = m - bb * Pq;
        const float* gxr = gx + ((size_t)(bb * Tq + t) * Pq + pp) * GXW;
        const float r = sigf(gxr[c] + ga[0][i] + br_);
        const float z = sigf(gxr[c + Hq] + ga[1][i] + bz_);
        const float n = tanhf(fmaf(r, ga[2][i] + bn_, gxr[c + 2 * Hq]));
        const float hp = hprev[(size_t)m * Hq + c];
        const float h  = fmaf(z, hp - n, n);
        hout[(size_t)m * Hq + c] = h;
        *(uint32_t*)(adst + SWZ((r0 + i) * 128 + lane * 4)) = f2tf32(h);
    }

    __syncthreads();
    if (w == 0) TCGEN05_DEALLOC(tmem, 256);
#else
    // Fallback body (plain compute_103 pass; never executed).
    const int row0 = blockIdx.y * 128;
    const int cb   = blockIdx.x * 64;
    for (int idx = threadIdx.x; idx < 128 * 64; idx += 256) {
        const int m = row0 + (idx >> 6);
        const int c = cb + (idx & 63);
        const int bb = m / Pq, pp = m - bb * Pq;
        const float* gxr = gx + ((size_t)(bb * Tq + t) * Pq + pp) * GXW;
        const float r = sigf(gxr[c] + bhh[c]);
        const float z = sigf(gxr[c + Hq] + bhh[c + Hq]);
        const float n = tanhf(fmaf(r, bhh[c + 2 * Hq], gxr[c + 2 * Hq]));
        const float hp = hprev[(size_t)m * Hq + c];
        hout[(size_t)m * Hq + c] = fmaf(z, hp - n, n);
        (void)aout; (void)aprev; (void)Wt;
    }
#endif
}

// ---------------------------------------------------------------------------
// Heads (unchanged)
// ---------------------------------------------------------------------------
__global__ __launch_bounds__(256) void action_head(
    const float* __restrict__ hid, const float* __restrict__ Wact,
    const float* __restrict__ bact, float* __restrict__ out)
{
    const int warp = (blockIdx.x * blockDim.x + threadIdx.x) >> 5;
    const int lane = threadIdx.x & 31;
    if (warp >= NROWS) return;
    const int n  = warp;
    const int bb = n / (Tq * Pq);
    const int rm = n - bb * (Tq * Pq);
    const int tt = rm / Pq;
    const int pp = rm - tt * Pq;
    const float* h = hid + ((size_t)tt * BP + bb * Pq + pp) * Hq;

    float s[9] = {};
    for (int k = lane; k < Hq; k += 32) {
        const float hv = h[k];
        #pragma unroll
        for (int a = 0; a < 9; a++) s[a] = fmaf(hv, Wact[a * Hq + k], s[a]);
    }
    #pragma unroll
    for (int a = 0; a < 9; a++)
        #pragma unroll
        for (int off = 16; off; off >>= 1)
            s[a] += __shfl_xor_sync(0xFFFFFFFFu, s[a], off);
    if (lane < 9) out[(size_t)n * 9 + lane] = s[lane] + bact[lane];
}

__global__ __launch_bounds__(256) void activity_head(
    const float* __restrict__ hid, const float* __restrict__ Wactv,
    const float* __restrict__ bactv, float* __restrict__ out)
{
    const int warp = (blockIdx.x * blockDim.x + threadIdx.x) >> 5;
    const int lane = threadIdx.x & 31;
    if (warp >= Bq * Tq) return;
    const int bb = warp / Tq;
    const int tt = warp - bb * Tq;
    const float* base = hid + ((size_t)tt * BP + bb * Pq) * Hq;

    float s[8] = {};
    for (int k = lane; k < Hq; k += 32) {
        float mx = base[k];
        #pragma unroll
        for (int p = 1; p < Pq; p++) mx = fmaxf(mx, base[(size_t)p * Hq + k]);
        #pragma unroll
        for (int a = 0; a < 8; a++) s[a] = fmaf(mx, Wactv[a * Hq + k], s[a]);
    }
    #pragma unroll
    for (int a = 0; a < 8; a++)
        #pragma unroll
        for (int off = 16; off; off >>= 1)
            s[a] += __shfl_xor_sync(0xFFFFFFFFu, s[a], off);
    if (lane < 8) out[(size_t)warp * 8 + lane] = s[lane] + bactv[lane];
}

// ---------------------------------------------------------------------------
extern "C" void kernel_launch(void* const* d_in, const int* in_sizes, int n_in,
                              void* d_out, int out_size)
{
    const float* feature = (const float*)d_in[0];
    const float* W_embed = (const float*)d_in[1];
    const float* b_embed = (const float*)d_in[2];
    const float* W_ih    = (const float*)d_in[3];
    const float* W_hh    = (const float*)d_in[4];
    const float* b_ih    = (const float*)d_in[5];
    const float* b_hh    = (const float*)d_in[6];
    const float* W_act   = (const float*)d_in[7];
    const float* b_act   = (const float*)d_in[8];
    const float* W_activ = (const float*)d_in[9];
    const float* b_activ = (const float*)d_in[10];
    float* out = (float*)d_out;

    float *X, *GX, *HID, *WT, *AP;
    cudaGetSymbolAddress((void**)&X,   g_X);
    cudaGetSymbolAddress((void**)&GX,  g_GX);
    cudaGetSymbolAddress((void**)&HID, g_H);
    cudaGetSymbolAddress((void**)&WT,  g_Wt);
    cudaGetSymbolAddress((void**)&AP,  g_Ap);

    cudaFuncSetAttribute(tc_gemm<1>,
        cudaFuncAttributeMaxDynamicSharedMemorySize, TCG_SMEM_BYTES);
    cudaFuncSetAttribute(tc_gemm<0>,
        cudaFuncAttributeMaxDynamicSharedMemorySize, TCG_SMEM_BYTES);
    cudaFuncSetAttribute(gru_tc,
        cudaFuncAttributeMaxDynamicSharedMemorySize, GRU_SMEM);

    // 0) Whh -> tf32 pre-swizzled images
    whh_prep<<<768, 256>>>(W_hh, WT);

    // 1) embed: X = tanh(feature @ W_embed^T + b_embed)   [15360,1024]
    tc_gemm<1><<<dim3(Hq / 128, NROWS / 128), 256, TCG_SMEM_BYTES>>>(
        feature, W_embed, b_embed, X, NROWS, Hq, Eq);

    // 2) input gates: GX = X @ W_ih^T + b_ih              [15360,3072]
    tc_gemm<0><<<dim3(GXW / 128, NROWS / 128), 256, TCG_SMEM_BYTES>>>(
        X, W_ih, b_ih, GX, NROWS, GXW, Hq);

    // 3) recurrence
    gru_t0<<<(BP * Hq) / 256, 256>>>(GX, b_hh, HID, AP);
    for (int t = 1; t < Tq; t++) {
        const float* hprev = HID + (size_t)(t - 1) * BP * Hq;
        float* hout = HID + (size_t)t * BP * Hq;
        const float* aprev = AP + ((size_t)((t - 1) & 1)) * APSZ;
        float* aout        = AP + ((size_t)(t & 1)) * APSZ;
        gru_tc<<<dim3(16, 3), 256, GRU_SMEM>>>(
            hprev, aprev, WT, GX, b_hh, hout, aout, t);
    }

    // 4) heads
    action_head<<<(NROWS * 32 + 255) / 256, 256>>>(HID, W_act, b_act, out);
    activity_head<<<(Bq * Tq * 32 + 255) / 256, 256>>>(
        HID, W_activ, b_activ, out + (size_t)NROWS * 9);
}

// round 10
// speedup vs baseline: 2.9321x; 1.1362x over previous
#include <cuda_runtime.h>
#include <cuda_bf16.h>
#include <cstdint>
#include <math.h>

// Problem constants
#define Bq   32
#define Tq   40
#define Pq   12
#define Eq   2048
#define Hq   1024
#define BP   384          // B*P
#define NROWS 15360       // B*T*P
#define GXW  3072         // 3*H

// tcgen05 is an 'a'-feature: only in the sm_103a/sm_100a device pass.
#if !defined(__CUDA_ARCH__) || defined(__CUDA_ARCH_FEAT_SM103_ALL) || defined(__CUDA_ARCH_FEAT_SM100_ALL)
#define HAS_TCG 1
#else
#define HAS_TCG 0
#endif

// Scratch (device globals: allocation-free rule)
__device__ float g_X [(size_t)NROWS * Hq];   // embedded+tanh  [B,T,P,H]
__device__ float g_GX[(size_t)NROWS * GXW];  // input gates    [B,T,P,3H]
__device__ float g_H [(size_t)Tq * BP * Hq]; // hiddens        [T,B,P,H]
// Whh bf16 pre-swizzled images: [16 col-tiles][16 K-chunks][192 rows x 128B]
// (buffer oversized from earlier fp32 layout; only 6MB used)
__device__ float g_Wt[(size_t)16 * 32 * 6144];
// h as bf16 pre-swizzled A images, double parity:
// [2][3 rowtiles][16 chunks][128 rows x 128B] = 2 x 768KB (buffer oversized)
#define APSZB ((size_t)3 * 16 * 16384)   // bytes per parity
__device__ float g_Ap[2 * ((size_t)3 * 32 * 4096)];

#define SWZ(o) ((o) ^ ((((uint32_t)(o)) >> 3) & 0x70u))

__device__ __forceinline__ uint32_t f2tf32(float f) {
    uint32_t r;
    asm("cvt.rna.tf32.f32 %0, %1;" : "=r"(r) : "f"(f));
    return r;
}
__device__ __forceinline__ float sigf(float x) {
    return 1.0f / (1.0f + expf(-x));
}

// ===========================================================================
// sm_103a PTX helpers (guarded)
// ===========================================================================
#if HAS_TCG
__device__ __forceinline__ uint32_t elect_one_pred() {
    uint32_t pred;
    asm volatile(
        "{\n\t.reg .pred p;\n\t"
        "elect.sync _|p, 0xFFFFFFFF;\n\t"
        "selp.b32 %0, 1, 0, p;\n\t}"
        : "=r"(pred));
    return pred;
}
__device__ __forceinline__ uint32_t smem_to_u32(const void* p) {
    uint32_t a;
    asm("{ .reg .u64 t; cvta.to.shared.u64 t, %1; cvt.u32.u64 %0, t; }"
        : "=r"(a) : "l"(p));
    return a;
}
#define MBARRIER_INIT(addr, cnt) \
    asm volatile("mbarrier.init.shared.b64 [%0], %1;" \
        :: "r"((uint32_t)(addr)), "r"((uint32_t)(cnt)) : "memory")
#define MBARRIER_EXPECT_TX(addr, bytes) \
    asm volatile("mbarrier.arrive.expect_tx.shared.b64 _, [%0], %1;" \
        :: "r"((uint32_t)(addr)), "r"((uint32_t)(bytes)) : "memory")
#define CP_ASYNC_BULK(dst, src, size, mbar) \
    asm volatile("cp.async.bulk.shared::cluster.global.mbarrier::complete_tx::bytes [%0], [%1], %2, [%3];" \
        :: "r"((uint32_t)(dst)), "l"(src), "r"((uint32_t)(size)), "r"((uint32_t)(mbar)) : "memory")

#define MBARRIER_WAIT_PARITY(mbar_smem_addr, phase_parity) do { \
    uint32_t _mbar = (uint32_t)(mbar_smem_addr); \
    uint32_t _parity = (uint32_t)(phase_parity); \
    uint32_t _done; \
    asm volatile( \
        "{\n\t.reg .pred p;\n\t" \
        "mbarrier.try_wait.parity.acquire.cta.shared::cta.b64 p, [%1], %2;\n\t" \
        "selp.b32 %0, 1, 0, p;\n\t}" \
        : "=r"(_done) : "r"(_mbar), "r"(_parity) : "memory"); \
    if (!_done) { \
        asm volatile( \
            "{\n\t.reg .pred P1;\n\t" \
            "WAIT_LOOP_%=:\n\t" \
            "mbarrier.try_wait.parity.acquire.cta.shared::cta.b64 P1, [%0], %1, 0x989680;\n\t" \
            "@P1 bra.uni WAIT_DONE_%=;\n\t" \
            "bra.uni WAIT_LOOP_%=;\n\t" \
            "WAIT_DONE_%=:\n\t}" \
            :: "r"(_mbar), "r"(_parity) : "memory"); \
    } \
} while(0)

#define TCGEN05_ALLOC(smem_result_addr, nCols) \
    asm volatile("tcgen05.alloc.cta_group::1.sync.aligned.shared::cta.b32 [%0], %1;" \
        :: "r"((uint32_t)(smem_result_addr)), "r"((uint32_t)(nCols)) : "memory")
#define TCGEN05_DEALLOC(tmem_addr, nCols) \
    asm volatile("tcgen05.dealloc.cta_group::1.sync.aligned.b32 %0, %1;" \
        :: "r"(tmem_addr), "r"((uint32_t)(nCols)))
#define TCGEN05_RELINQUISH() \
    asm volatile("tcgen05.relinquish_alloc_permit.cta_group::1.sync.aligned;")
#define TCGEN05_COMMIT(mbar_smem_addr) \
    asm volatile("tcgen05.commit.cta_group::1.mbarrier::arrive::one.shared::cluster.b64 [%0];" \
        :: "r"((uint32_t)(mbar_smem_addr)) : "memory")
#define TCGEN05_FENCE_AFTER() \
    asm volatile("tcgen05.fence::after_thread_sync;" ::: "memory")
#define TCGEN05_WAIT_LD() \
    asm volatile("tcgen05.wait::ld.sync.aligned;" ::: "memory")
#define FENCE_PROXY_ASYNC() \
    asm volatile("fence.proxy.async.shared::cta;" ::: "memory")

#define TCGEN05_LD_32X32B_X32(r, tmem_addr) \
    asm volatile( \
        "tcgen05.ld.sync.aligned.32x32b.x32.b32 " \
        "{%0, %1, %2, %3, %4, %5, %6, %7, " \
        " %8, %9, %10, %11, %12, %13, %14, %15, " \
        " %16, %17, %18, %19, %20, %21, %22, %23, " \
        " %24, %25, %26, %27, %28, %29, %30, %31}, [%32];" \
        : "=r"((r)[0]),  "=r"((r)[1]),  "=r"((r)[2]),  "=r"((r)[3]), \
          "=r"((r)[4]),  "=r"((r)[5]),  "=r"((r)[6]),  "=r"((r)[7]), \
          "=r"((r)[8]),  "=r"((r)[9]),  "=r"((r)[10]), "=r"((r)[11]), \
          "=r"((r)[12]), "=r"((r)[13]), "=r"((r)[14]), "=r"((r)[15]), \
          "=r"((r)[16]), "=r"((r)[17]), "=r"((r)[18]), "=r"((r)[19]), \
          "=r"((r)[20]), "=r"((r)[21]), "=r"((r)[22]), "=r"((r)[23]), \
          "=r"((r)[24]), "=r"((r)[25]), "=r"((r)[26]), "=r"((r)[27]), \
          "=r"((r)[28]), "=r"((r)[29]), "=r"((r)[30]), "=r"((r)[31]) \
        : "r"(tmem_addr))

// SMEM descriptor: K-major SW128, LBO=1, SBO=64, version=1 (Blackwell)
__device__ __forceinline__ uint64_t make_desc_sw128(uint32_t base_addr) {
    const uint64_t base =
        (uint64_t(2)  << 61) | (uint64_t(1) << 46) |
        (uint64_t(64) << 32) | (uint64_t(1) << 16);
    return base | ((uint64_t)(base_addr >> 4) & 0x3FFF);
}

// tf32 SS MMA, cta_group::1
__device__ __forceinline__ void mma_tf32_ss(
    uint32_t d_tmem, uint64_t a_desc, uint64_t b_desc,
    uint32_t idesc, uint32_t enable_d)
{
    asm volatile(
        "{\n\t.reg .pred p;\n\t"
        "setp.ne.u32 p, %5, 0;\n\t"
        "tcgen05.mma.cta_group::1.kind::tf32 [%0], %1, %2, %3, "
        "{%4, %4, %4, %4}, p;\n\t}"
        :: "r"(d_tmem), "l"(a_desc), "l"(b_desc), "r"(idesc),
           "r"(0u), "r"(enable_d)
        : "memory");
}

// bf16 SS MMA (kind::f16), cta_group::1, K=16 per dispatch
__device__ __forceinline__ void mma_f16_ss(
    uint32_t d_tmem, uint64_t a_desc, uint64_t b_desc,
    uint32_t idesc, uint32_t enable_d)
{
    asm volatile(
        "{\n\t.reg .pred p;\n\t"
        "setp.ne.u32 p, %5, 0;\n\t"
        "tcgen05.mma.cta_group::1.kind::f16 [%0], %1, %2, %3, "
        "{%4, %4, %4, %4}, p;\n\t}"
        :: "r"(d_tmem), "l"(a_desc), "l"(b_desc), "r"(idesc),
           "r"(0u), "r"(enable_d)
        : "memory");
}
#endif  // HAS_TCG

// ===========================================================================
// tcgen05 tf32 GEMM: C[M,N] = act(A[M,K] @ B[N,K]^T + bias[N]) — known good
// ===========================================================================
#define TCG_SMEM_BYTES 66560

template<int ACT>
__global__ __launch_bounds__(256) void tc_gemm(
    const float* __restrict__ A, const float* __restrict__ Bm,
    const float* __restrict__ bias, float* __restrict__ C,
    int M, int N, int K)
{
#if HAS_TCG
    extern __shared__ char smem[];
    const uint32_t sb  = smem_to_u32(smem);
    const int tid  = threadIdx.x;
    const int w    = tid >> 5;
    const int lane = tid & 31;
    const int row0 = blockIdx.y * 128;
    const int col0 = blockIdx.x * 128;

    if (w == 0) { TCGEN05_ALLOC(sb, 128); TCGEN05_RELINQUISH(); }
    if (tid == 0) { MBARRIER_INIT(sb + 16, 1); MBARRIER_INIT(sb + 24, 1); }
    __syncthreads();
    uint32_t tmem;
    asm volatile("ld.shared.b32 %0, [%1];" : "=r"(tmem) : "r"(sb));

    const int lr  = tid >> 1;
    const int lcf = (tid & 1) * 16;
    const float* Ag = A  + (size_t)(row0 + lr) * K + lcf;
    const float* Bg = Bm + (size_t)(col0 + lr) * K + lcf;

    const uint32_t aoff[2] = {1024u, 17408u};
    const uint32_t boff[2] = {33792u, 50176u};
    int ph[2] = {0, 0};
    const int NC = K / 32;

    const uint32_t idesc = (1u << 4) | (2u << 7) | (2u << 10) |
                           ((128u / 8) << 17) | ((128u / 16) << 24);

    for (int c = 0; c < NC; c++) {
        const int b = c & 1;
        float4 av[4], bv[4];
        #pragma unroll
        for (int j = 0; j < 4; j++) {
            av[j] = *(const float4*)(Ag + (size_t)c * 32 + j * 4);
            bv[j] = *(const float4*)(Bg + (size_t)c * 32 + j * 4);
        }
        if (c >= 2) { MBARRIER_WAIT_PARITY(sb + 16 + 8 * b, ph[b]); ph[b] ^= 1; }
        #pragma unroll
        for (int j = 0; j < 4; j++) {
            uint4 ta, tb;
            ta.x = f2tf32(av[j].x); ta.y = f2tf32(av[j].y);
            ta.z = f2tf32(av[j].z); ta.w = f2tf32(av[j].w);
            tb.x = f2tf32(bv[j].x); tb.y = f2tf32(bv[j].y);
            tb.z = f2tf32(bv[j].z); tb.w = f2tf32(bv[j].w);
            const uint32_t byo = (uint32_t)(lr * 128 + (lcf + j * 4) * 4);
            *(uint4*)(smem + aoff[b] + SWZ(byo)) = ta;
            *(uint4*)(smem + boff[b] + SWZ(byo)) = tb;
        }
        FENCE_PROXY_ASYNC();
        __syncthreads();

        if (w == 0 && elect_one_pred()) {
            const uint64_t ad = make_desc_sw128(sb + aoff[b]);
            const uint64_t bd = make_desc_sw128(sb + boff[b]);
            #pragma unroll
            for (int k = 0; k < 4; k++)
                mma_tf32_ss(tmem, ad + k * 2, bd + k * 2, idesc,
                            (c > 0 || k > 0) ? 1u : 0u);
            TCGEN05_COMMIT(sb + 16 + 8 * b);
        }
    }
    {
        const int b = (NC - 1) & 1;
        MBARRIER_WAIT_PARITY(sb + 16 + 8 * b, ph[b]);
    }
    TCGEN05_FENCE_AFTER();

    const int rbase = (w & 3) * 32;
    const int csel  = (w >> 2) * 64;
    float* tr = reinterpret_cast<float*>(smem + 1024) + w * (32 * 33);

    #pragma unroll
    for (int half = 0; half < 2; half++) {
        const int cb = csel + half * 32;
        uint32_t regs[32];
        TCGEN05_LD_32X32B_X32(regs, tmem + cb);
        TCGEN05_WAIT_LD();
        __syncwarp();
        #pragma unroll
        for (int cc = 0; cc < 32; cc++)
            tr[lane * 33 + cc] = __uint_as_float(regs[cc]);
        __syncwarp();
        const int col = col0 + cb + lane;
        const float bvs = bias[col];
        #pragma unroll
        for (int r = 0; r < 32; r++) {
            float v = tr[r * 33 + lane] + bvs;
            if (ACT == 1) v = tanhf(v);
            C[(size_t)(row0 + rbase + r) * N + col] = v;
        }
        __syncwarp();
    }
    __syncthreads();
    if (w == 0) TCGEN05_DEALLOC(tmem, 128);
#else
    const int row0 = blockIdx.y * 128;
    const int col0 = blockIdx.x * 128;
    for (int idx = threadIdx.x; idx < 128 * 128; idx += 256) {
        const int r  = idx >> 7;
        const int cc = idx & 127;
        const float* a = A  + (size_t)(row0 + r)  * K;
        const float* b = Bm + (size_t)(col0 + cc) * K;
        float s = 0.0f;
        for (int k = 0; k < K; k++) s = fmaf(a[k], b[k], s);
        s += bias[col0 + cc];
        if (ACT == 1) s = tanhf(s);
        C[(size_t)(row0 + r) * N + (col0 + cc)] = s;
    }
#endif
}

// ===========================================================================
// whh_prep: Whh -> bf16, pre-swizzled per-(tile,chunk) images.
// Image (tile,chunk): 192 rows (0-63 gate r cols, 64-127 z, 128-191 n),
// each row = 64 K-values bf16 = 128B, SW128-swizzled. 256 images x 24KB = 6MB.
// ===========================================================================
__global__ __launch_bounds__(256) void whh_prep(
    const float* __restrict__ Whh, float* __restrict__ Wt)
{
    const uint32_t stride = gridDim.x * blockDim.x;
    for (uint32_t u = blockIdx.x * blockDim.x + threadIdx.x;
         u < 393216u; u += stride) {               // 256 images * 1536 uint4
        const uint32_t tc   = u / 1536u;           // tile*16 + chunk
        const uint32_t rem  = u - tc * 1536u;
        const uint32_t row  = rem >> 3;            // 0..191
        const uint32_t q    = rem & 7;             // 8 K-values per unit
        const uint32_t tile = tc >> 4;
        const uint32_t chunk= tc & 15;
        const uint32_t g    = row >> 6;
        const uint32_t cidx = tile * 64 + (row & 63);
        const float* src = Whh + ((size_t)(g * Hq + cidx)) * Hq
                               + chunk * 64 + q * 8;
        const float4 v0 = *(const float4*)(src);
        const float4 v1 = *(const float4*)(src + 4);
        __nv_bfloat162 p0 = __floats2bfloat162_rn(v0.x, v0.y);
        __nv_bfloat162 p1 = __floats2bfloat162_rn(v0.z, v0.w);
        __nv_bfloat162 p2 = __floats2bfloat162_rn(v1.x, v1.y);
        __nv_bfloat162 p3 = __floats2bfloat162_rn(v1.z, v1.w);
        uint4 o;
        o.x = *(uint32_t*)&p0; o.y = *(uint32_t*)&p1;
        o.z = *(uint32_t*)&p2; o.w = *(uint32_t*)&p3;
        *(uint4*)((char*)Wt + (size_t)tc * 24576 + SWZ(row * 128 + q * 16)) = o;
    }
}

// ===========================================================================
// gru_t0: first timestep (h_prev = 0), writes HID fp32 + bf16 A-prep images.
// A image (rowtile, chunk): 128 rows x 64 K-values bf16 = 16KB, SW128.
// ===========================================================================
__global__ __launch_bounds__(256) void gru_t0(
    const float* __restrict__ gx, const float* __restrict__ bhh,
    float* __restrict__ hout, float* __restrict__ aout)
{
    const int e = blockIdx.x * 256 + threadIdx.x;   // 384*1024 total
    const int m = e >> 10, c = e & 1023;
    const int bb = m / Pq, pp = m - bb * Pq;
    const float* gxr = gx + ((size_t)(bb * Tq) * Pq + pp) * GXW;  // t = 0
    const float r = sigf(gxr[c] + bhh[c]);
    const float z = sigf(gxr[c + Hq] + bhh[c + Hq]);
    const float n = tanhf(fmaf(r, bhh[c + 2 * Hq], gxr[c + 2 * Hq]));
    const float h = fmaf(z, -n, n);
    hout[e] = h;
    *(__nv_bfloat16*)((char*)aout
        + ((size_t)(m >> 7) * 16 + (c >> 6)) * 16384
        + SWZ((m & 127) * 128 + (c & 63) * 2)) = __float2bfloat16_rn(h);
}

// ===========================================================================
// gru_tc: one GRU timestep, bf16 operands, N=192 fused-gate kind::f16 MMAs.
// CTA: 128 rows x (64 h-cols x 3 gates = 192 N). Grid (16, 3), 256 threads.
// 16 K-chunks of 64 (vs 32 of 32 in tf32): per chunk A 16KB + B 24KB (bf16),
// 4 MMAs of K=16. Halves both L2 traffic and the K-dispatch chain vs tf32.
// ===========================================================================
#define GRU_STAGE 40960
#define GRU_SMEM  (1024 + 4 * GRU_STAGE)   // 164864

__global__ __launch_bounds__(256) void gru_tc(
    const float* __restrict__ hprev, const float* __restrict__ aprev,
    const float* __restrict__ Wt,    const float* __restrict__ gx,
    const float* __restrict__ bhh,   float* __restrict__ hout,
    float* __restrict__ aout, int t)
{
#if HAS_TCG
    extern __shared__ char smem[];
    const uint32_t sb  = smem_to_u32(smem);
    const int tid  = threadIdx.x;
    const int w    = tid >> 5;
    const int lane = tid & 31;
    const int row0 = blockIdx.y * 128;
    const int cb   = blockIdx.x * 64;

    // mbars: full[s]=sb+16+8s, done[s]=sb+48+8s, final=sb+80
    if (w == 0) { TCGEN05_ALLOC(sb, 256); TCGEN05_RELINQUISH(); }
    if (tid == 0) {
        #pragma unroll
        for (int s = 0; s < 4; s++) {
            MBARRIER_INIT(sb + 16 + 8 * s, 1);
            MBARRIER_INIT(sb + 48 + 8 * s, 1);
        }
        MBARRIER_INIT(sb + 80, 1);
    }
    __syncthreads();
    uint32_t tmem;
    asm volatile("ld.shared.b32 %0, [%1];" : "=r"(tmem) : "r"(sb));

    // kind::f16 idesc: F32 accum, BF16 a/b, N=192, M=128
    const uint32_t idesc = (1u << 4) | (1u << 7) | (1u << 10) |
                           ((192u / 8) << 17) | ((128u / 16) << 24);

    if (tid == 0) {
        const char* Asrc = (const char*)aprev + (size_t)blockIdx.y * 16 * 16384;
        const char* Bsrc = (const char*)Wt + (size_t)blockIdx.x * 16 * 24576;

        // prologue: stages 0..2 <- chunks 0..2
        #pragma unroll
        for (int c = 0; c < 3; c++) {
            const uint32_t st = sb + 1024 + c * GRU_STAGE;
            MBARRIER_EXPECT_TX(sb + 16 + 8 * c, GRU_STAGE);
            CP_ASYNC_BULK(st,         Asrc + (size_t)c * 16384, 16384, sb + 16 + 8 * c);
            CP_ASYNC_BULK(st + 16384, Bsrc + (size_t)c * 24576, 24576, sb + 16 + 8 * c);
        }

        int phF[4] = {0, 0, 0, 0}, phD[4] = {0, 0, 0, 0};
        for (int c = 0; c < 16; c++) {
            const int s = c & 3;
            MBARRIER_WAIT_PARITY(sb + 16 + 8 * s, phF[s]); phF[s] ^= 1;
            const uint32_t st = sb + 1024 + s * GRU_STAGE;
            const uint64_t ad = make_desc_sw128(st);
            const uint64_t bd = make_desc_sw128(st + 16384);
            #pragma unroll
            for (int k = 0; k < 4; k++)   // K=16 bf16 per MMA, +32B per step
                mma_f16_ss(tmem, ad + k * 2, bd + k * 2, idesc,
                           (c > 0 || k > 0) ? 1u : 0u);
            TCGEN05_COMMIT(sb + 48 + 8 * s);

            const int cn = c + 3;
            if (cn < 16) {
                const int s2 = cn & 3;
                if (c >= 1) {                  // recycle: wait chunk c-1 done
                    MBARRIER_WAIT_PARITY(sb + 48 + 8 * s2, phD[s2]);
                    phD[s2] ^= 1;
                }
                const uint32_t st2 = sb + 1024 + s2 * GRU_STAGE;
                MBARRIER_EXPECT_TX(sb + 16 + 8 * s2, GRU_STAGE);
                CP_ASYNC_BULK(st2,         Asrc + (size_t)cn * 16384, 16384, sb + 16 + 8 * s2);
                CP_ASYNC_BULK(st2 + 16384, Bsrc + (size_t)cn * 24576, 24576, sb + 16 + 8 * s2);
            }
        }
        TCGEN05_COMMIT(sb + 80);   // cumulative: fires when ALL MMAs complete
    }

    MBARRIER_WAIT_PARITY(sb + 80, 0);
    TCGEN05_FENCE_AFTER();
    __syncthreads();

    // ---- fused epilogue (gate g at TMEM col g*64) ----
    const int r0 = (w & 3) * 32;
    const int c0 = (w >> 2) * 32;
    float* tr = reinterpret_cast<float*>(smem + 1024) + w * (32 * 33);

    float ga[3][32];
    #pragma unroll
    for (int g = 0; g < 3; g++) {
        uint32_t regs[32];
        TCGEN05_LD_32X32B_X32(regs, tmem + g * 64 + c0);
        TCGEN05_WAIT_LD();
        __syncwarp();
        #pragma unroll
        for (int j = 0; j < 32; j++) tr[lane * 33 + j] = __uint_as_float(regs[j]);
        __syncwarp();
        #pragma unroll
        for (int i = 0; i < 32; i++) ga[g][i] = tr[i * 33 + lane];
        __syncwarp();
    }

    const int c = cb + c0 + lane;
    const float br_ = bhh[c];
    const float bz_ = bhh[c + Hq];
    const float bn_ = bhh[c + 2 * Hq];
    // A image for this CTA: rowtile=blockIdx.y, chunk=blockIdx.x (c>>6)
    char* adst = (char*)aout +
        ((size_t)blockIdx.y * 16 + blockIdx.x) * 16384;
    #pragma unroll
    for (int i = 0; i < 32; i++) {
        const int m  = row0 + r0 + i;
        const int bb = m / Pq;
        const int pp = m - bb * Pq;
        const float* gxr = gx + ((size_t)(bb * Tq + t) * Pq + pp) * GXW;
        const float r = sigf(gxr[c] + ga[0][i] + br_);
        const float z = sigf(gxr[c + Hq] + ga[1][i] + bz_);
        const float n = tanhf(fmaf(r, ga[2][i] + bn_, gxr[c + 2 * Hq]));
        const float hp = hprev[(size_t)m * Hq + c];
        const float h  = fmaf(z, hp - n, n);
        hout[(size_t)m * Hq + c] = h;
        *(__nv_bfloat16*)(adst + SWZ((r0 + i) * 128 + (c0 + lane) * 2)) =
            __float2bfloat16_rn(h);
    }

    __syncthreads();
    if (w == 0) TCGEN05_DEALLOC(tmem, 256);
#else
    // Fallback body (plain compute_103 pass; never executed).
    const int row0 = blockIdx.y * 128;
    const int cb   = blockIdx.x * 64;
    for (int idx = threadIdx.x; idx < 128 * 64; idx += 256) {
        const int m = row0 + (idx >> 6);
        const int c = cb + (idx & 63);
        const int bb = m / Pq, pp = m - bb * Pq;
        const float* gxr = gx + ((size_t)(bb * Tq + t) * Pq + pp) * GXW;
        const float r = sigf(gxr[c] + bhh[c]);
        const float z = sigf(gxr[c + Hq] + bhh[c + Hq]);
        const float n = tanhf(fmaf(r, bhh[c + 2 * Hq], gxr[c + 2 * Hq]));
        const float hp = hprev[(size_t)m * Hq + c];
        hout[(size_t)m * Hq + c] = fmaf(z, hp - n, n);
        (void)aout; (void)aprev; (void)Wt;
    }
#endif
}

// ---------------------------------------------------------------------------
// Heads (unchanged)
// ---------------------------------------------------------------------------
__global__ __launch_bounds__(256) void action_head(
    const float* __restrict__ hid, const float* __restrict__ Wact,
    const float* __restrict__ bact, float* __restrict__ out)
{
    const int warp = (blockIdx.x * blockDim.x + threadIdx.x) >> 5;
    const int lane = threadIdx.x & 31;
    if (warp >= NROWS) return;
    const int n  = warp;
    const int bb = n / (Tq * Pq);
    const int rm = n - bb * (Tq * Pq);
    const int tt = rm / Pq;
    const int pp = rm - tt * Pq;
    const float* h = hid + ((size_t)tt * BP + bb * Pq + pp) * Hq;

    float s[9] = {};
    for (int k = lane; k < Hq; k += 32) {
        const float hv = h[k];
        #pragma unroll
        for (int a = 0; a < 9; a++) s[a] = fmaf(hv, Wact[a * Hq + k], s[a]);
    }
    #pragma unroll
    for (int a = 0; a < 9; a++)
        #pragma unroll
        for (int off = 16; off; off >>= 1)
            s[a] += __shfl_xor_sync(0xFFFFFFFFu, s[a], off);
    if (lane < 9) out[(size_t)n * 9 + lane] = s[lane] + bact[lane];
}

__global__ __launch_bounds__(256) void activity_head(
    const float* __restrict__ hid, const float* __restrict__ Wactv,
    const float* __restrict__ bactv, float* __restrict__ out)
{
    const int warp = (blockIdx.x * blockDim.x + threadIdx.x) >> 5;
    const int lane = threadIdx.x & 31;
    if (warp >= Bq * Tq) return;
    const int bb = warp / Tq;
    const int tt = warp - bb * Tq;
    const float* base = hid + ((size_t)tt * BP + bb * Pq) * Hq;

    float s[8] = {};
    for (int k = lane; k < Hq; k += 32) {
        float mx = base[k];
        #pragma unroll
        for (int p = 1; p < Pq; p++) mx = fmaxf(mx, base[(size_t)p * Hq + k]);
        #pragma unroll
        for (int a = 0; a < 8; a++) s[a] = fmaf(mx, Wactv[a * Hq + k], s[a]);
    }
    #pragma unroll
    for (int a = 0; a < 8; a++)
        #pragma unroll
        for (int off = 16; off; off >>= 1)
            s[a] += __shfl_xor_sync(0xFFFFFFFFu, s[a], off);
    if (lane < 8) out[(size_t)warp * 8 + lane] = s[lane] + bactv[lane];
}

// ---------------------------------------------------------------------------
extern "C" void kernel_launch(void* const* d_in, const int* in_sizes, int n_in,
                              void* d_out, int out_size)
{
    const float* feature = (const float*)d_in[0];
    const float* W_embed = (const float*)d_in[1];
    const float* b_embed = (const float*)d_in[2];
    const float* W_ih    = (const float*)d_in[3];
    const float* W_hh    = (const float*)d_in[4];
    const float* b_ih    = (const float*)d_in[5];
    const float* b_hh    = (const float*)d_in[6];
    const float* W_act   = (const float*)d_in[7];
    const float* b_act   = (const float*)d_in[8];
    const float* W_activ = (const float*)d_in[9];
    const float* b_activ = (const float*)d_in[10];
    float* out = (float*)d_out;

    float *X, *GX, *HID, *WT, *AP;
    cudaGetSymbolAddress((void**)&X,   g_X);
    cudaGetSymbolAddress((void**)&GX,  g_GX);
    cudaGetSymbolAddress((void**)&HID, g_H);
    cudaGetSymbolAddress((void**)&WT,  g_Wt);
    cudaGetSymbolAddress((void**)&AP,  g_Ap);

    cudaFuncSetAttribute(tc_gemm<1>,
        cudaFuncAttributeMaxDynamicSharedMemorySize, TCG_SMEM_BYTES);
    cudaFuncSetAttribute(tc_gemm<0>,
        cudaFuncAttributeMaxDynamicSharedMemorySize, TCG_SMEM_BYTES);
    cudaFuncSetAttribute(gru_tc,
        cudaFuncAttributeMaxDynamicSharedMemorySize, GRU_SMEM);

    // 0) Whh -> bf16 pre-swizzled images
    whh_prep<<<768, 256>>>(W_hh, WT);

    // 1) embed: X = tanh(feature @ W_embed^T + b_embed)   [15360,1024]
    tc_gemm<1><<<dim3(Hq / 128, NROWS / 128), 256, TCG_SMEM_BYTES>>>(
        feature, W_embed, b_embed, X, NROWS, Hq, Eq);

    // 2) input gates: GX = X @ W_ih^T + b_ih              [15360,3072]
    tc_gemm<0><<<dim3(GXW / 128, NROWS / 128), 256, TCG_SMEM_BYTES>>>(
        X, W_ih, b_ih, GX, NROWS, GXW, Hq);

    // 3) recurrence
    gru_t0<<<(BP * Hq) / 256, 256>>>(GX, b_hh, HID, AP);
    for (int t = 1; t < Tq; t++) {
        const float* hprev = HID + (size_t)(t - 1) * BP * Hq;
        float* hout = HID + (size_t)t * BP * Hq;
        const float* aprev = (float*)((char*)AP + (size_t)((t - 1) & 1) * APSZB);
        float* aout        = (float*)((char*)AP + (size_t)(t & 1) * APSZB);
        gru_tc<<<dim3(16, 3), 256, GRU_SMEM>>>(
            hprev, aprev, WT, GX, b_hh, hout, aout, t);
    }

    // 4) heads
    action_head<<<(NROWS * 32 + 255) / 256, 256>>>(HID, W_act, b_act, out);
    activity_head<<<(Bq * Tq * 32 + 255) / 256, 256>>>(
        HID, W_activ, b_activ, out + (size_t)NROWS * 9);
}

// round 11
// speedup vs baseline: 5.1787x; 1.7662x over previous
#include <cuda_runtime.h>
#include <cuda_bf16.h>
#include <cstdint>
#include <math.h>

// Problem constants
#define Bq   32
#define Tq   40
#define Pq   12
#define Eq   2048
#define Hq   1024
#define BP   384          // B*P
#define NROWS 15360       // B*T*P
#define GXW  3072         // 3*H

// tcgen05 is an 'a'-feature: only in the sm_103a/sm_100a device pass.
#if !defined(__CUDA_ARCH__) || defined(__CUDA_ARCH_FEAT_SM103_ALL) || defined(__CUDA_ARCH_FEAT_SM100_ALL)
#define HAS_TCG 1
#else
#define HAS_TCG 0
#endif

// Scratch (device globals: allocation-free rule)
__device__ float g_X [(size_t)NROWS * Hq];   // embedded+tanh  [B,T,P,H]
__device__ float g_GX[(size_t)NROWS * GXW];  // input gates    [B,T,P,3H]
__device__ float g_H [(size_t)Tq * BP * Hq]; // hiddens        [T,B,P,H]
// Whh bf16 pre-swizzled images: [16 col-tiles][16 K-chunks][192 rows x 128B]
__device__ float g_Wt[(size_t)16 * 32 * 6144];
// h as bf16 pre-swizzled A images, double parity
#define APSZB ((size_t)3 * 16 * 16384)   // bytes per parity
__device__ float g_Ap[2 * ((size_t)3 * 32 * 4096)];
// per-step device barrier slots (memset to 0 every launch)
__device__ int g_bar[64];

#define SWZ(o) ((o) ^ ((((uint32_t)(o)) >> 3) & 0x70u))

__device__ __forceinline__ uint32_t f2tf32(float f) {
    uint32_t r;
    asm("cvt.rna.tf32.f32 %0, %1;" : "=r"(r) : "f"(f));
    return r;
}
__device__ __forceinline__ float sigf(float x) {
    return 1.0f / (1.0f + expf(-x));
}

// ===========================================================================
// sm_103a PTX helpers (guarded)
// ===========================================================================
#if HAS_TCG
__device__ __forceinline__ uint32_t elect_one_pred() {
    uint32_t pred;
    asm volatile(
        "{\n\t.reg .pred p;\n\t"
        "elect.sync _|p, 0xFFFFFFFF;\n\t"
        "selp.b32 %0, 1, 0, p;\n\t}"
        : "=r"(pred));
    return pred;
}
__device__ __forceinline__ uint32_t smem_to_u32(const void* p) {
    uint32_t a;
    asm("{ .reg .u64 t; cvta.to.shared.u64 t, %1; cvt.u32.u64 %0, t; }"
        : "=r"(a) : "l"(p));
    return a;
}
#define MBARRIER_INIT(addr, cnt) \
    asm volatile("mbarrier.init.shared.b64 [%0], %1;" \
        :: "r"((uint32_t)(addr)), "r"((uint32_t)(cnt)) : "memory")
#define MBARRIER_EXPECT_TX(addr, bytes) \
    asm volatile("mbarrier.arrive.expect_tx.shared.b64 _, [%0], %1;" \
        :: "r"((uint32_t)(addr)), "r"((uint32_t)(bytes)) : "memory")
#define CP_ASYNC_BULK(dst, src, size, mbar) \
    asm volatile("cp.async.bulk.shared::cluster.global.mbarrier::complete_tx::bytes [%0], [%1], %2, [%3];" \
        :: "r"((uint32_t)(dst)), "l"(src), "r"((uint32_t)(size)), "r"((uint32_t)(mbar)) : "memory")

#define MBARRIER_WAIT_PARITY(mbar_smem_addr, phase_parity) do { \
    uint32_t _mbar = (uint32_t)(mbar_smem_addr); \
    uint32_t _parity = (uint32_t)(phase_parity); \
    uint32_t _done; \
    asm volatile( \
        "{\n\t.reg .pred p;\n\t" \
        "mbarrier.try_wait.parity.acquire.cta.shared::cta.b64 p, [%1], %2;\n\t" \
        "selp.b32 %0, 1, 0, p;\n\t}" \
        : "=r"(_done) : "r"(_mbar), "r"(_parity) : "memory"); \
    if (!_done) { \
        asm volatile( \
            "{\n\t.reg .pred P1;\n\t" \
            "WAIT_LOOP_%=:\n\t" \
            "mbarrier.try_wait.parity.acquire.cta.shared::cta.b64 P1, [%0], %1, 0x989680;\n\t" \
            "@P1 bra.uni WAIT_DONE_%=;\n\t" \
            "bra.uni WAIT_LOOP_%=;\n\t" \
            "WAIT_DONE_%=:\n\t}" \
            :: "r"(_mbar), "r"(_parity) : "memory"); \
    } \
} while(0)

#define TCGEN05_ALLOC(smem_result_addr, nCols) \
    asm volatile("tcgen05.alloc.cta_group::1.sync.aligned.shared::cta.b32 [%0], %1;" \
        :: "r"((uint32_t)(smem_result_addr)), "r"((uint32_t)(nCols)) : "memory")
#define TCGEN05_DEALLOC(tmem_addr, nCols) \
    asm volatile("tcgen05.dealloc.cta_group::1.sync.aligned.b32 %0, %1;" \
        :: "r"(tmem_addr), "r"((uint32_t)(nCols)))
#define TCGEN05_RELINQUISH() \
    asm volatile("tcgen05.relinquish_alloc_permit.cta_group::1.sync.aligned;")
#define TCGEN05_COMMIT(mbar_smem_addr) \
    asm volatile("tcgen05.commit.cta_group::1.mbarrier::arrive::one.shared::cluster.b64 [%0];" \
        :: "r"((uint32_t)(mbar_smem_addr)) : "memory")
#define TCGEN05_FENCE_AFTER() \
    asm volatile("tcgen05.fence::after_thread_sync;" ::: "memory")
#define TCGEN05_WAIT_LD() \
    asm volatile("tcgen05.wait::ld.sync.aligned;" ::: "memory")
#define FENCE_PROXY_ASYNC() \
    asm volatile("fence.proxy.async.shared::cta;" ::: "memory")
#define FENCE_PROXY_ASYNC_ALL() \
    asm volatile("fence.proxy.async;" ::: "memory")

#define TCGEN05_LD_32X32B_X32(r, tmem_addr) \
    asm volatile( \
        "tcgen05.ld.sync.aligned.32x32b.x32.b32 " \
        "{%0, %1, %2, %3, %4, %5, %6, %7, " \
        " %8, %9, %10, %11, %12, %13, %14, %15, " \
        " %16, %17, %18, %19, %20, %21, %22, %23, " \
        " %24, %25, %26, %27, %28, %29, %30, %31}, [%32];" \
        : "=r"((r)[0]),  "=r"((r)[1]),  "=r"((r)[2]),  "=r"((r)[3]), \
          "=r"((r)[4]),  "=r"((r)[5]),  "=r"((r)[6]),  "=r"((r)[7]), \
          "=r"((r)[8]),  "=r"((r)[9]),  "=r"((r)[10]), "=r"((r)[11]), \
          "=r"((r)[12]), "=r"((r)[13]), "=r"((r)[14]), "=r"((r)[15]), \
          "=r"((r)[16]), "=r"((r)[17]), "=r"((r)[18]), "=r"((r)[19]), \
          "=r"((r)[20]), "=r"((r)[21]), "=r"((r)[22]), "=r"((r)[23]), \
          "=r"((r)[24]), "=r"((r)[25]), "=r"((r)[26]), "=r"((r)[27]), \
          "=r"((r)[28]), "=r"((r)[29]), "=r"((r)[30]), "=r"((r)[31]) \
        : "r"(tmem_addr))

// SMEM descriptor: K-major SW128, LBO=1, SBO=64, version=1 (Blackwell)
__device__ __forceinline__ uint64_t make_desc_sw128(uint32_t base_addr) {
    const uint64_t base =
        (uint64_t(2)  << 61) | (uint64_t(1) << 46) |
        (uint64_t(64) << 32) | (uint64_t(1) << 16);
    return base | ((uint64_t)(base_addr >> 4) & 0x3FFF);
}

// tf32 SS MMA, cta_group::1
__device__ __forceinline__ void mma_tf32_ss(
    uint32_t d_tmem, uint64_t a_desc, uint64_t b_desc,
    uint32_t idesc, uint32_t enable_d)
{
    asm volatile(
        "{\n\t.reg .pred p;\n\t"
        "setp.ne.u32 p, %5, 0;\n\t"
        "tcgen05.mma.cta_group::1.kind::tf32 [%0], %1, %2, %3, "
        "{%4, %4, %4, %4}, p;\n\t}"
        :: "r"(d_tmem), "l"(a_desc), "l"(b_desc), "r"(idesc),
           "r"(0u), "r"(enable_d)
        : "memory");
}

// bf16 SS MMA (kind::f16), cta_group::1, K=16 per dispatch
__device__ __forceinline__ void mma_f16_ss(
    uint32_t d_tmem, uint64_t a_desc, uint64_t b_desc,
    uint32_t idesc, uint32_t enable_d)
{
    asm volatile(
        "{\n\t.reg .pred p;\n\t"
        "setp.ne.u32 p, %5, 0;\n\t"
        "tcgen05.mma.cta_group::1.kind::f16 [%0], %1, %2, %3, "
        "{%4, %4, %4, %4}, p;\n\t}"
        :: "r"(d_tmem), "l"(a_desc), "l"(b_desc), "r"(idesc),
           "r"(0u), "r"(enable_d)
        : "memory");
}
#endif  // HAS_TCG

// ===========================================================================
// tcgen05 tf32 GEMM: C[M,N] = act(A[M,K] @ B[N,K]^T + bias[N]) — known good
// ===========================================================================
#define TCG_SMEM_BYTES 66560

template<int ACT>
__global__ __launch_bounds__(256) void tc_gemm(
    const float* __restrict__ A, const float* __restrict__ Bm,
    const float* __restrict__ bias, float* __restrict__ C,
    int M, int N, int K)
{
#if HAS_TCG
    extern __shared__ char smem[];
    const uint32_t sb  = smem_to_u32(smem);
    const int tid  = threadIdx.x;
    const int w    = tid >> 5;
    const int lane = tid & 31;
    const int row0 = blockIdx.y * 128;
    const int col0 = blockIdx.x * 128;

    if (w == 0) { TCGEN05_ALLOC(sb, 128); TCGEN05_RELINQUISH(); }
    if (tid == 0) { MBARRIER_INIT(sb + 16, 1); MBARRIER_INIT(sb + 24, 1); }
    __syncthreads();
    uint32_t tmem;
    asm volatile("ld.shared.b32 %0, [%1];" : "=r"(tmem) : "r"(sb));

    const int lr  = tid >> 1;
    const int lcf = (tid & 1) * 16;
    const float* Ag = A  + (size_t)(row0 + lr) * K + lcf;
    const float* Bg = Bm + (size_t)(col0 + lr) * K + lcf;

    const uint32_t aoff[2] = {1024u, 17408u};
    const uint32_t boff[2] = {33792u, 50176u};
    int ph[2] = {0, 0};
    const int NC = K / 32;

    const uint32_t idesc = (1u << 4) | (2u << 7) | (2u << 10) |
                           ((128u / 8) << 17) | ((128u / 16) << 24);

    for (int c = 0; c < NC; c++) {
        const int b = c & 1;
        float4 av[4], bv[4];
        #pragma unroll
        for (int j = 0; j < 4; j++) {
            av[j] = *(const float4*)(Ag + (size_t)c * 32 + j * 4);
            bv[j] = *(const float4*)(Bg + (size_t)c * 32 + j * 4);
        }
        if (c >= 2) { MBARRIER_WAIT_PARITY(sb + 16 + 8 * b, ph[b]); ph[b] ^= 1; }
        #pragma unroll
        for (int j = 0; j < 4; j++) {
            uint4 ta, tb;
            ta.x = f2tf32(av[j].x); ta.y = f2tf32(av[j].y);
            ta.z = f2tf32(av[j].z); ta.w = f2tf32(av[j].w);
            tb.x = f2tf32(bv[j].x); tb.y = f2tf32(bv[j].y);
            tb.z = f2tf32(bv[j].z); tb.w = f2tf32(bv[j].w);
            const uint32_t byo = (uint32_t)(lr * 128 + (lcf + j * 4) * 4);
            *(uint4*)(smem + aoff[b] + SWZ(byo)) = ta;
            *(uint4*)(smem + boff[b] + SWZ(byo)) = tb;
        }
        FENCE_PROXY_ASYNC();
        __syncthreads();

        if (w == 0 && elect_one_pred()) {
            const uint64_t ad = make_desc_sw128(sb + aoff[b]);
            const uint64_t bd = make_desc_sw128(sb + boff[b]);
            #pragma unroll
            for (int k = 0; k < 4; k++)
                mma_tf32_ss(tmem, ad + k * 2, bd + k * 2, idesc,
                            (c > 0 || k > 0) ? 1u : 0u);
            TCGEN05_COMMIT(sb + 16 + 8 * b);
        }
    }
    {
        const int b = (NC - 1) & 1;
        MBARRIER_WAIT_PARITY(sb + 16 + 8 * b, ph[b]);
    }
    TCGEN05_FENCE_AFTER();

    const int rbase = (w & 3) * 32;
    const int csel  = (w >> 2) * 64;
    float* tr = reinterpret_cast<float*>(smem + 1024) + w * (32 * 33);

    #pragma unroll
    for (int half = 0; half < 2; half++) {
        const int cb = csel + half * 32;
        uint32_t regs[32];
        TCGEN05_LD_32X32B_X32(regs, tmem + cb);
        TCGEN05_WAIT_LD();
        __syncwarp();
        #pragma unroll
        for (int cc = 0; cc < 32; cc++)
            tr[lane * 33 + cc] = __uint_as_float(regs[cc]);
        __syncwarp();
        const int col = col0 + cb + lane;
        const float bvs = bias[col];
        #pragma unroll
        for (int r = 0; r < 32; r++) {
            float v = tr[r * 33 + lane] + bvs;
            if (ACT == 1) v = tanhf(v);
            C[(size_t)(row0 + rbase + r) * N + col] = v;
        }
        __syncwarp();
    }
    __syncthreads();
    if (w == 0) TCGEN05_DEALLOC(tmem, 128);
#else
    const int row0 = blockIdx.y * 128;
    const int col0 = blockIdx.x * 128;
    for (int idx = threadIdx.x; idx < 128 * 128; idx += 256) {
        const int r  = idx >> 7;
        const int cc = idx & 127;
        const float* a = A  + (size_t)(row0 + r)  * K;
        const float* b = Bm + (size_t)(col0 + cc) * K;
        float s = 0.0f;
        for (int k = 0; k < K; k++) s = fmaf(a[k], b[k], s);
        s += bias[col0 + cc];
        if (ACT == 1) s = tanhf(s);
        C[(size_t)(row0 + r) * N + (col0 + cc)] = s;
    }
#endif
}

// ===========================================================================
// whh_prep: Whh -> bf16, pre-swizzled per-(tile,chunk) images (known good)
// ===========================================================================
__global__ __launch_bounds__(256) void whh_prep(
    const float* __restrict__ Whh, float* __restrict__ Wt)
{
    const uint32_t stride = gridDim.x * blockDim.x;
    for (uint32_t u = blockIdx.x * blockDim.x + threadIdx.x;
         u < 393216u; u += stride) {               // 256 images * 1536 uint4
        const uint32_t tc   = u / 1536u;           // tile*16 + chunk
        const uint32_t rem  = u - tc * 1536u;
        const uint32_t row  = rem >> 3;            // 0..191
        const uint32_t q    = rem & 7;             // 8 K-values per unit
        const uint32_t tile = tc >> 4;
        const uint32_t chunk= tc & 15;
        const uint32_t g    = row >> 6;
        const uint32_t cidx = tile * 64 + (row & 63);
        const float* src = Whh + ((size_t)(g * Hq + cidx)) * Hq
                               + chunk * 64 + q * 8;
        const float4 v0 = *(const float4*)(src);
        const float4 v1 = *(const float4*)(src + 4);
        __nv_bfloat162 p0 = __floats2bfloat162_rn(v0.x, v0.y);
        __nv_bfloat162 p1 = __floats2bfloat162_rn(v0.z, v0.w);
        __nv_bfloat162 p2 = __floats2bfloat162_rn(v1.x, v1.y);
        __nv_bfloat162 p3 = __floats2bfloat162_rn(v1.z, v1.w);
        uint4 o;
        o.x = *(uint32_t*)&p0; o.y = *(uint32_t*)&p1;
        o.z = *(uint32_t*)&p2; o.w = *(uint32_t*)&p3;
        *(uint4*)((char*)Wt + (size_t)tc * 24576 + SWZ(row * 128 + q * 16)) = o;
    }
}

// ===========================================================================
// gru_all: PERSISTENT kernel — the whole 40-step recurrence in one launch.
// Grid (16, 3) = 48 CTAs (1/SM, all co-resident), 256 threads.
// Per step: warp0/tid0 drives a 3-stage cp.async.bulk + kind::f16 MMA
// pipeline (N=192 fused gates); warps 1-7 prefetch this step's gx slice
// into smem concurrently; fused epilogue keeps h in REGISTERS across steps,
// writes HID fp32 + bf16 A-images (parity gmem); steps separated by a
// gmem counter barrier (g_bar, memset to 0 each launch; safe: 48 CTAs all
// resident). TMEM alloc + mbarrier init happen ONCE.
// ===========================================================================
#define GST 40960
#define GXS_OFF (1024 + 3 * GST)                 // 123904
#define GRU_SMEM (GXS_OFF + 98304)               // 222208

__global__ __launch_bounds__(256) void gru_all(
    const float* __restrict__ Wt, const float* __restrict__ gx,
    const float* __restrict__ bhh, float* __restrict__ hid,
    float* __restrict__ ap, int* __restrict__ bar)
{
#if HAS_TCG
    extern __shared__ char smem[];
    const uint32_t sb  = smem_to_u32(smem);
    const int tid  = threadIdx.x;
    const int w    = tid >> 5;
    const int lane = tid & 31;
    const int row0 = blockIdx.y * 128;
    const int cb   = blockIdx.x * 64;
    float* gxs = reinterpret_cast<float*>(smem + GXS_OFF);

    if (w == 0) { TCGEN05_ALLOC(sb, 256); TCGEN05_RELINQUISH(); }
    if (tid == 0) {
        #pragma unroll
        for (int s = 0; s < 3; s++) {
            MBARRIER_INIT(sb + 16 + 8 * s, 1);   // full
            MBARRIER_INIT(sb + 48 + 8 * s, 1);   // done
        }
    }
    __syncthreads();
    uint32_t tmem;
    asm volatile("ld.shared.b32 %0, [%1];" : "=r"(tmem) : "r"(sb));

    const uint32_t idesc = (1u << 4) | (1u << 7) | (1u << 10) |
                           ((192u / 8) << 17) | ((128u / 16) << 24);
    const char* Bsrc = (const char*)Wt + (size_t)blockIdx.x * 16 * 24576;

    const int r0 = (w & 3) * 32;
    const int c0 = (w >> 2) * 32;
    const int c  = cb + c0 + lane;
    const float br_ = bhh[c];
    const float bz_ = bhh[c + Hq];
    const float bn_ = bhh[c + 2 * Hq];

    float hkeep[32];
    #pragma unroll
    for (int i = 0; i < 32; i++) hkeep[i] = 0.0f;

    int phF[3] = {0, 0, 0}, phD[3] = {0, 0, 0};

    for (int t = 0; t < Tq; t++) {
        // ---- mainloop (tid0) + gx prefetch (warps 1-7) in parallel ----
        if (tid == 0 && t > 0) {
            const char* Asrc = (const char*)ap +
                (size_t)((t - 1) & 1) * APSZB + (size_t)blockIdx.y * 16 * 16384;
            #pragma unroll
            for (int c2 = 0; c2 < 2; c2++) {
                const uint32_t st = sb + 1024 + c2 * GST;
                MBARRIER_EXPECT_TX(sb + 16 + 8 * c2, GST);
                CP_ASYNC_BULK(st,         Asrc + (size_t)c2 * 16384, 16384, sb + 16 + 8 * c2);
                CP_ASYNC_BULK(st + 16384, Bsrc + (size_t)c2 * 24576, 24576, sb + 16 + 8 * c2);
            }
            for (int cc = 0; cc < 16; cc++) {
                const int s = cc % 3;
                MBARRIER_WAIT_PARITY(sb + 16 + 8 * s, phF[s]); phF[s] ^= 1;
                const uint32_t st = sb + 1024 + s * GST;
                const uint64_t ad = make_desc_sw128(st);
                const uint64_t bd = make_desc_sw128(st + 16384);
                #pragma unroll
                for (int k = 0; k < 4; k++)
                    mma_f16_ss(tmem, ad + k * 2, bd + k * 2, idesc,
                               (cc > 0 || k > 0) ? 1u : 0u);
                TCGEN05_COMMIT(sb + 48 + 8 * s);
                const int cn = cc + 2;
                if (cn < 16) {
                    const int s2 = cn % 3;
                    if (cc >= 1) {   // previous occupant = chunk cn-3 = cc-1
                        MBARRIER_WAIT_PARITY(sb + 48 + 8 * s2, phD[s2]);
                        phD[s2] ^= 1;
                    }
                    const uint32_t st2 = sb + 1024 + s2 * GST;
                    MBARRIER_EXPECT_TX(sb + 16 + 8 * s2, GST);
                    CP_ASYNC_BULK(st2,         Asrc + (size_t)cn * 16384, 16384, sb + 16 + 8 * s2);
                    CP_ASYNC_BULK(st2 + 16384, Bsrc + (size_t)cn * 24576, 24576, sb + 16 + 8 * s2);
                }
            }
            // drain last occupants: chunks 13 (s1), 14 (s2), 15 (s0)
            MBARRIER_WAIT_PARITY(sb + 48 + 8 * 1, phD[1]); phD[1] ^= 1;
            MBARRIER_WAIT_PARITY(sb + 48 + 8 * 2, phD[2]); phD[2] ^= 1;
            MBARRIER_WAIT_PARITY(sb + 48 + 8 * 0, phD[0]); phD[0] ^= 1;
        }
        if (w >= 1) {
            // prefetch this step's gx slice: 128 rows x 3 gates x 64 cols fp32
            for (int u = tid - 32; u < 6144; u += 224) {
                const int m  = u / 48;
                const int rm = u - m * 48;
                const int g  = rm >> 4;
                const int q  = rm & 15;
                const int gm = row0 + m;
                const int bb = gm / Pq, pp = gm - bb * Pq;
                const float4 v = *(const float4*)(
                    gx + ((size_t)(bb * Tq + t) * Pq + pp) * GXW
                       + g * Hq + cb + q * 4);
                *(float4*)(gxs + m * 192 + g * 64 + q * 4) = v;
            }
        }
        __syncthreads();
        TCGEN05_FENCE_AFTER();

        // ---- fused epilogue (gate g at TMEM col g*64) ----
        float ga[3][32];
        if (t > 0) {
            float* tr = reinterpret_cast<float*>(smem + 1024) + w * (32 * 33);
            #pragma unroll
            for (int g = 0; g < 3; g++) {
                uint32_t regs[32];
                TCGEN05_LD_32X32B_X32(regs, tmem + g * 64 + c0);
                TCGEN05_WAIT_LD();
                __syncwarp();
                #pragma unroll
                for (int j = 0; j < 32; j++)
                    tr[lane * 33 + j] = __uint_as_float(regs[j]);
                __syncwarp();
                #pragma unroll
                for (int i = 0; i < 32; i++) ga[g][i] = tr[i * 33 + lane];
                __syncwarp();
            }
        } else {
            #pragma unroll
            for (int g = 0; g < 3; g++)
                #pragma unroll
                for (int i = 0; i < 32; i++) ga[g][i] = 0.0f;
        }

        char* adst = (char*)ap + (size_t)(t & 1) * APSZB +
            ((size_t)blockIdx.y * 16 + blockIdx.x) * 16384;
        float* hrow = hid + (size_t)t * BP * Hq;
        #pragma unroll
        for (int i = 0; i < 32; i++) {
            const int m = row0 + r0 + i;
            const float* gxr = gxs + (r0 + i) * 192 + c0 + lane;
            const float r = sigf(gxr[0]   + ga[0][i] + br_);
            const float z = sigf(gxr[64]  + ga[1][i] + bz_);
            const float n = tanhf(fmaf(r, ga[2][i] + bn_, gxr[128]));
            const float hp = hkeep[i];
            const float h  = fmaf(z, hp - n, n);
            hkeep[i] = h;
            hrow[(size_t)m * Hq + c] = h;
            *(__nv_bfloat16*)(adst + SWZ((r0 + i) * 128 + (c0 + lane) * 2)) =
                __float2bfloat16_rn(h);
        }

        // ---- inter-CTA barrier (publish A-images before next step) ----
        if (t < Tq - 1) {
            __threadfence();
            __syncthreads();
            if (tid == 0) {
                atomicAdd(&bar[t], 1);
                unsigned v;
                do {
                    asm volatile("ld.acquire.gpu.global.b32 %0, [%1];"
                                 : "=r"(v) : "l"(bar + t) : "memory");
                } while (v < 48);
                FENCE_PROXY_ASYNC_ALL();   // generic writes -> async-proxy reads
            }
            __syncthreads();
        }
    }

    __syncthreads();
    if (w == 0) TCGEN05_DEALLOC(tmem, 256);
#else
    // Fallback body (plain compute_103 pass; never executed).
    if (blockIdx.x == 0 && blockIdx.y == 0 && threadIdx.x == 0) {
        hid[0] = bhh[0] + gx[0] + Wt[0] + ap[0] + bar[0];
    }
#endif
}

// ---------------------------------------------------------------------------
// Heads (unchanged)
// ---------------------------------------------------------------------------
__global__ __launch_bounds__(256) void action_head(
    const float* __restrict__ hid, const float* __restrict__ Wact,
    const float* __restrict__ bact, float* __restrict__ out)
{
    const int warp = (blockIdx.x * blockDim.x + threadIdx.x) >> 5;
    const int lane = threadIdx.x & 31;
    if (warp >= NROWS) return;
    const int n  = warp;
    const int bb = n / (Tq * Pq);
    const int rm = n - bb * (Tq * Pq);
    const int tt = rm / Pq;
    const int pp = rm - tt * Pq;
    const float* h = hid + ((size_t)tt * BP + bb * Pq + pp) * Hq;

    float s[9] = {};
    for (int k = lane; k < Hq; k += 32) {
        const float hv = h[k];
        #pragma unroll
        for (int a = 0; a < 9; a++) s[a] = fmaf(hv, Wact[a * Hq + k], s[a]);
    }
    #pragma unroll
    for (int a = 0; a < 9; a++)
        #pragma unroll
        for (int off = 16; off; off >>= 1)
            s[a] += __shfl_xor_sync(0xFFFFFFFFu, s[a], off);
    if (lane < 9) out[(size_t)n * 9 + lane] = s[lane] + bact[lane];
}

__global__ __launch_bounds__(256) void activity_head(
    const float* __restrict__ hid, const float* __restrict__ Wactv,
    const float* __restrict__ bactv, float* __restrict__ out)
{
    const int warp = (blockIdx.x * blockDim.x + threadIdx.x) >> 5;
    const int lane = threadIdx.x & 31;
    if (warp >= Bq * Tq) return;
    const int bb = warp / Tq;
    const int tt = warp - bb * Tq;
    const float* base = hid + ((size_t)tt * BP + bb * Pq) * Hq;

    float s[8] = {};
    for (int k = lane; k < Hq; k += 32) {
        float mx = base[k];
        #pragma unroll
        for (int p = 1; p < Pq; p++) mx = fmaxf(mx, base[(size_t)p * Hq + k]);
        #pragma unroll
        for (int a = 0; a < 8; a++) s[a] = fmaf(mx, Wactv[a * Hq + k], s[a]);
    }
    #pragma unroll
    for (int a = 0; a < 8; a++)
        #pragma unroll
        for (int off = 16; off; off >>= 1)
            s[a] += __shfl_xor_sync(0xFFFFFFFFu, s[a], off);
    if (lane < 8) out[(size_t)warp * 8 + lane] = s[lane] + bactv[lane];
}

// ---------------------------------------------------------------------------
extern "C" void kernel_launch(void* const* d_in, const int* in_sizes, int n_in,
                              void* d_out, int out_size)
{
    const float* feature = (const float*)d_in[0];
    const float* W_embed = (const float*)d_in[1];
    const float* b_embed = (const float*)d_in[2];
    const float* W_ih    = (const float*)d_in[3];
    const float* W_hh    = (const float*)d_in[4];
    const float* b_ih    = (const float*)d_in[5];
    const float* b_hh    = (const float*)d_in[6];
    const float* W_act   = (const float*)d_in[7];
    const float* b_act   = (const float*)d_in[8];
    const float* W_activ = (const float*)d_in[9];
    const float* b_activ = (const float*)d_in[10];
    float* out = (float*)d_out;

    float *X, *GX, *HID, *WT, *AP;
    int *BAR;
    cudaGetSymbolAddress((void**)&X,   g_X);
    cudaGetSymbolAddress((void**)&GX,  g_GX);
    cudaGetSymbolAddress((void**)&HID, g_H);
    cudaGetSymbolAddress((void**)&WT,  g_Wt);
    cudaGetSymbolAddress((void**)&AP,  g_Ap);
    cudaGetSymbolAddress((void**)&BAR, g_bar);

    cudaFuncSetAttribute(tc_gemm<1>,
        cudaFuncAttributeMaxDynamicSharedMemorySize, TCG_SMEM_BYTES);
    cudaFuncSetAttribute(tc_gemm<0>,
        cudaFuncAttributeMaxDynamicSharedMemorySize, TCG_SMEM_BYTES);
    cudaFuncSetAttribute(gru_all,
        cudaFuncAttributeMaxDynamicSharedMemorySize, GRU_SMEM);

    // 0) Whh -> bf16 pre-swizzled images; zero barrier slots (every launch)
    whh_prep<<<768, 256>>>(W_hh, WT);
    cudaMemsetAsync(BAR, 0, 64 * sizeof(int));

    // 1) embed: X = tanh(feature @ W_embed^T + b_embed)   [15360,1024]
    tc_gemm<1><<<dim3(Hq / 128, NROWS / 128), 256, TCG_SMEM_BYTES>>>(
        feature, W_embed, b_embed, X, NROWS, Hq, Eq);

    // 2) input gates: GX = X @ W_ih^T + b_ih              [15360,3072]
    tc_gemm<0><<<dim3(GXW / 128, NROWS / 128), 256, TCG_SMEM_BYTES>>>(
        X, W_ih, b_ih, GX, NROWS, GXW, Hq);

    // 3) recurrence: ONE persistent kernel, all 40 steps
    gru_all<<<dim3(16, 3), 256, GRU_SMEM>>>(WT, GX, b_hh, HID, AP, BAR);

    // 4) heads
    action_head<<<(NROWS * 32 + 255) / 256, 256>>>(HID, W_act, b_act, out);
    activity_head<<<(Bq * Tq * 32 + 255) / 256, 256>>>(
        HID, W_activ, b_activ, out + (size_t)NROWS * 9);
}

// round 14
// speedup vs baseline: 5.7371x; 1.1078x over previous
#include <cuda_runtime.h>
#include <cuda_bf16.h>
#include <cstdint>
#include <math.h>

// Problem constants
#define Bq   32
#define Tq   40
#define Pq   12
#define Eq   2048
#define Hq   1024
#define BP   384          // B*P
#define NROWS 15360       // B*T*P
#define GXW  3072         // 3*H

// tcgen05 is an 'a'-feature: only in the sm_103a/sm_100a device pass.
#if !defined(__CUDA_ARCH__) || defined(__CUDA_ARCH_FEAT_SM103_ALL) || defined(__CUDA_ARCH_FEAT_SM100_ALL)
#define HAS_TCG 1
#else
#define HAS_TCG 0
#endif

// Scratch (device globals: allocation-free rule)
__device__ float g_X [(size_t)NROWS * Hq];   // embedded+tanh  [B,T,P,H]
__device__ float g_GX[(size_t)NROWS * GXW];  // input gates    [B,T,P,3H]
__device__ float g_H [(size_t)Tq * BP * Hq]; // hiddens        [T,B,P,H]
// Whh bf16 pre-swizzled images: [16 col-tiles][16 K-chunks][192 rows x 128B]
__device__ float g_Wt[(size_t)16 * 32 * 6144];
// h as bf16 pre-swizzled A images, double parity
#define APSZB ((size_t)3 * 16 * 16384)   // bytes per parity
__device__ float g_Ap[2 * ((size_t)3 * 32 * 4096)];
// per-(step,rowtile) device barrier slots (memset to 0 every launch)
__device__ int g_bar[256];

#define SWZ(o) ((o) ^ ((((uint32_t)(o)) >> 3) & 0x70u))

__device__ __forceinline__ uint32_t f2tf32(float f) {
    uint32_t r;
    asm("cvt.rna.tf32.f32 %0, %1;" : "=r"(r) : "f"(f));
    return r;
}
// Fast activations for the recurrence (HW tanh.approx, single MUFU-class op)
__device__ __forceinline__ float tanhfast(float x) {
    float y;
    asm("tanh.approx.f32 %0, %1;" : "=f"(y) : "f"(x));
    return y;
}
__device__ __forceinline__ float sigfast(float x) {
    return fmaf(tanhfast(0.5f * x), 0.5f, 0.5f);
}

// ===========================================================================
// sm_103a PTX helpers (guarded)
// ===========================================================================
#if HAS_TCG
__device__ __forceinline__ uint32_t elect_one_pred() {
    uint32_t pred;
    asm volatile(
        "{\n\t.reg .pred p;\n\t"
        "elect.sync _|p, 0xFFFFFFFF;\n\t"
        "selp.b32 %0, 1, 0, p;\n\t}"
        : "=r"(pred));
    return pred;
}
__device__ __forceinline__ uint32_t smem_to_u32(const void* p) {
    uint32_t a;
    asm("{ .reg .u64 t; cvta.to.shared.u64 t, %1; cvt.u32.u64 %0, t; }"
        : "=r"(a) : "l"(p));
    return a;
}
#define MBARRIER_INIT(addr, cnt) \
    asm volatile("mbarrier.init.shared.b64 [%0], %1;" \
        :: "r"((uint32_t)(addr)), "r"((uint32_t)(cnt)) : "memory")
#define MBARRIER_EXPECT_TX(addr, bytes) \
    asm volatile("mbarrier.arrive.expect_tx.shared.b64 _, [%0], %1;" \
        :: "r"((uint32_t)(addr)), "r"((uint32_t)(bytes)) : "memory")
#define CP_ASYNC_BULK(dst, src, size, mbar) \
    asm volatile("cp.async.bulk.shared::cluster.global.mbarrier::complete_tx::bytes [%0], [%1], %2, [%3];" \
        :: "r"((uint32_t)(dst)), "l"(src), "r"((uint32_t)(size)), "r"((uint32_t)(mbar)) : "memory")

#define MBARRIER_WAIT_PARITY(mbar_smem_addr, phase_parity) do { \
    uint32_t _mbar = (uint32_t)(mbar_smem_addr); \
    uint32_t _parity = (uint32_t)(phase_parity); \
    uint32_t _done; \
    asm volatile( \
        "{\n\t.reg .pred p;\n\t" \
        "mbarrier.try_wait.parity.acquire.cta.shared::cta.b64 p, [%1], %2;\n\t" \
        "selp.b32 %0, 1, 0, p;\n\t}" \
        : "=r"(_done) : "r"(_mbar), "r"(_parity) : "memory"); \
    if (!_done) { \
        asm volatile( \
            "{\n\t.reg .pred P1;\n\t" \
            "WAIT_LOOP_%=:\n\t" \
            "mbarrier.try_wait.parity.acquire.cta.shared::cta.b64 P1, [%0], %1, 0x989680;\n\t" \
            "@P1 bra.uni WAIT_DONE_%=;\n\t" \
            "bra.uni WAIT_LOOP_%=;\n\t" \
            "WAIT_DONE_%=:\n\t}" \
            :: "r"(_mbar), "r"(_parity) : "memory"); \
    } \
} while(0)

#define TCGEN05_ALLOC(smem_result_addr, nCols) \
    asm volatile("tcgen05.alloc.cta_group::1.sync.aligned.shared::cta.b32 [%0], %1;" \
        :: "r"((uint32_t)(smem_result_addr)), "r"((uint32_t)(nCols)) : "memory")
#define TCGEN05_DEALLOC(tmem_addr, nCols) \
    asm volatile("tcgen05.dealloc.cta_group::1.sync.aligned.b32 %0, %1;" \
        :: "r"(tmem_addr), "r"((uint32_t)(nCols)))
#define TCGEN05_RELINQUISH() \
    asm volatile("tcgen05.relinquish_alloc_permit.cta_group::1.sync.aligned;")
#define TCGEN05_COMMIT(mbar_smem_addr) \
    asm volatile("tcgen05.commit.cta_group::1.mbarrier::arrive::one.shared::cluster.b64 [%0];" \
        :: "r"((uint32_t)(mbar_smem_addr)) : "memory")
#define TCGEN05_FENCE_AFTER() \
    asm volatile("tcgen05.fence::after_thread_sync;" ::: "memory")
#define TCGEN05_WAIT_LD() \
    asm volatile("tcgen05.wait::ld.sync.aligned;" ::: "memory")
#define FENCE_PROXY_ASYNC() \
    asm volatile("fence.proxy.async.shared::cta;" ::: "memory")
#define FENCE_PROXY_ASYNC_ALL() \
    asm volatile("fence.proxy.async;" ::: "memory")

#define TCGEN05_LD_32X32B_X32(r, tmem_addr) \
    asm volatile( \
        "tcgen05.ld.sync.aligned.32x32b.x32.b32 " \
        "{%0, %1, %2, %3, %4, %5, %6, %7, " \
        " %8, %9, %10, %11, %12, %13, %14, %15, " \
        " %16, %17, %18, %19, %20, %21, %22, %23, " \
        " %24, %25, %26, %27, %28, %29, %30, %31}, [%32];" \
        : "=r"((r)[0]),  "=r"((r)[1]),  "=r"((r)[2]),  "=r"((r)[3]), \
          "=r"((r)[4]),  "=r"((r)[5]),  "=r"((r)[6]),  "=r"((r)[7]), \
          "=r"((r)[8]),  "=r"((r)[9]),  "=r"((r)[10]), "=r"((r)[11]), \
          "=r"((r)[12]), "=r"((r)[13]), "=r"((r)[14]), "=r"((r)[15]), \
          "=r"((r)[16]), "=r"((r)[17]), "=r"((r)[18]), "=r"((r)[19]), \
          "=r"((r)[20]), "=r"((r)[21]), "=r"((r)[22]), "=r"((r)[23]), \
          "=r"((r)[24]), "=r"((r)[25]), "=r"((r)[26]), "=r"((r)[27]), \
          "=r"((r)[28]), "=r"((r)[29]), "=r"((r)[30]), "=r"((r)[31]) \
        : "r"(tmem_addr))

// SMEM descriptor: K-major SW128, LBO=1, SBO=64, version=1 (Blackwell)
__device__ __forceinline__ uint64_t make_desc_sw128(uint32_t base_addr) {
    const uint64_t base =
        (uint64_t(2)  << 61) | (uint64_t(1) << 46) |
        (uint64_t(64) << 32) | (uint64_t(1) << 16);
    return base | ((uint64_t)(base_addr >> 4) & 0x3FFF);
}

// tf32 SS MMA, cta_group::1
__device__ __forceinline__ void mma_tf32_ss(
    uint32_t d_tmem, uint64_t a_desc, uint64_t b_desc,
    uint32_t idesc, uint32_t enable_d)
{
    asm volatile(
        "{\n\t.reg .pred p;\n\t"
        "setp.ne.u32 p, %5, 0;\n\t"
        "tcgen05.mma.cta_group::1.kind::tf32 [%0], %1, %2, %3, "
        "{%4, %4, %4, %4}, p;\n\t}"
        :: "r"(d_tmem), "l"(a_desc), "l"(b_desc), "r"(idesc),
           "r"(0u), "r"(enable_d)
        : "memory");
}

// bf16 SS MMA (kind::f16), cta_group::1, K=16 per dispatch
__device__ __forceinline__ void mma_f16_ss(
    uint32_t d_tmem, uint64_t a_desc, uint64_t b_desc,
    uint32_t idesc, uint32_t enable_d)
{
    asm volatile(
        "{\n\t.reg .pred p;\n\t"
        "setp.ne.u32 p, %5, 0;\n\t"
        "tcgen05.mma.cta_group::1.kind::f16 [%0], %1, %2, %3, "
        "{%4, %4, %4, %4}, p;\n\t}"
        :: "r"(d_tmem), "l"(a_desc), "l"(b_desc), "r"(idesc),
           "r"(0u), "r"(enable_d)
        : "memory");
}
#endif  // HAS_TCG

// ===========================================================================
// tcgen05 tf32 GEMM: C[M,N] = act(A[M,K] @ B[N,K]^T + bias[N])
// Round 12: software-pipelined LDG (chunk c+1 loads issued while chunk c is
// staged/MMA'd) so global-load latency is no longer exposed per chunk.
// ===========================================================================
#define TCG_SMEM_BYTES 66560

template<int ACT>
__global__ __launch_bounds__(256) void tc_gemm(
    const float* __restrict__ A, const float* __restrict__ Bm,
    const float* __restrict__ bias, float* __restrict__ C,
    int M, int N, int K)
{
#if HAS_TCG
    extern __shared__ char smem[];
    const uint32_t sb  = smem_to_u32(smem);
    const int tid  = threadIdx.x;
    const int w    = tid >> 5;
    const int lane = tid & 31;
    const int row0 = blockIdx.y * 128;
    const int col0 = blockIdx.x * 128;

    if (w == 0) { TCGEN05_ALLOC(sb, 128); TCGEN05_RELINQUISH(); }
    if (tid == 0) { MBARRIER_INIT(sb + 16, 1); MBARRIER_INIT(sb + 24, 1); }
    __syncthreads();
    uint32_t tmem;
    asm volatile("ld.shared.b32 %0, [%1];" : "=r"(tmem) : "r"(sb));

    const int lr  = tid >> 1;
    const int lcf = (tid & 1) * 16;
    const float* Ag = A  + (size_t)(row0 + lr) * K + lcf;
    const float* Bg = Bm + (size_t)(col0 + lr) * K + lcf;

    const uint32_t aoff[2] = {1024u, 17408u};
    const uint32_t boff[2] = {33792u, 50176u};
    int ph[2] = {0, 0};
    const int NC = K / 32;

    const uint32_t idesc = (1u << 4) | (2u << 7) | (2u << 10) |
                           ((128u / 8) << 17) | ((128u / 16) << 24);

    float4 av[4], bv[4], av2[4], bv2[4];
    #pragma unroll
    for (int j = 0; j < 4; j++) {           // preload chunk 0
        av[j] = *(const float4*)(Ag + j * 4);
        bv[j] = *(const float4*)(Bg + j * 4);
    }

    for (int c = 0; c < NC; c++) {
        const int b = c & 1;
        if (c + 1 < NC) {                   // issue chunk c+1 loads early
            #pragma unroll
            for (int j = 0; j < 4; j++) {
                av2[j] = *(const float4*)(Ag + (size_t)(c + 1) * 32 + j * 4);
                bv2[j] = *(const float4*)(Bg + (size_t)(c + 1) * 32 + j * 4);
            }
        }
        if (c >= 2) { MBARRIER_WAIT_PARITY(sb + 16 + 8 * b, ph[b]); ph[b] ^= 1; }
        #pragma unroll
        for (int j = 0; j < 4; j++) {
            uint4 ta, tb;
            ta.x = f2tf32(av[j].x); ta.y = f2tf32(av[j].y);
            ta.z = f2tf32(av[j].z); ta.w = f2tf32(av[j].w);
            tb.x = f2tf32(bv[j].x); tb.y = f2tf32(bv[j].y);
            tb.z = f2tf32(bv[j].z); tb.w = f2tf32(bv[j].w);
            const uint32_t byo = (uint32_t)(lr * 128 + (lcf + j * 4) * 4);
            *(uint4*)(smem + aoff[b] + SWZ(byo)) = ta;
            *(uint4*)(smem + boff[b] + SWZ(byo)) = tb;
        }
        FENCE_PROXY_ASYNC();
        __syncthreads();

        if (w == 0 && elect_one_pred()) {
            const uint64_t ad = make_desc_sw128(sb + aoff[b]);
            const uint64_t bd = make_desc_sw128(sb + boff[b]);
            #pragma unroll
            for (int k = 0; k < 4; k++)
                mma_tf32_ss(tmem, ad + k * 2, bd + k * 2, idesc,
                            (c > 0 || k > 0) ? 1u : 0u);
            TCGEN05_COMMIT(sb + 16 + 8 * b);
        }
        #pragma unroll
        for (int j = 0; j < 4; j++) { av[j] = av2[j]; bv[j] = bv2[j]; }
    }
    {
        const int b = (NC - 1) & 1;
        MBARRIER_WAIT_PARITY(sb + 16 + 8 * b, ph[b]);
    }
    TCGEN05_FENCE_AFTER();

    const int rbase = (w & 3) * 32;
    const int csel  = (w >> 2) * 64;
    float* tr = reinterpret_cast<float*>(smem + 1024) + w * (32 * 33);

    #pragma unroll
    for (int half = 0; half < 2; half++) {
        const int cb = csel + half * 32;
        uint32_t regs[32];
        TCGEN05_LD_32X32B_X32(regs, tmem + cb);
        TCGEN05_WAIT_LD();
        __syncwarp();
        #pragma unroll
        for (int cc = 0; cc < 32; cc++)
            tr[lane * 33 + cc] = __uint_as_float(regs[cc]);
        __syncwarp();
        const int col = col0 + cb + lane;
        const float bvs = bias[col];
        #pragma unroll
        for (int r = 0; r < 32; r++) {
            float v = tr[r * 33 + lane] + bvs;
            if (ACT == 1) v = tanhf(v);
            C[(size_t)(row0 + rbase + r) * N + col] = v;
        }
        __syncwarp();
    }
    __syncthreads();
    if (w == 0) TCGEN05_DEALLOC(tmem, 128);
#else
    const int row0 = blockIdx.y * 128;
    const int col0 = blockIdx.x * 128;
    for (int idx = threadIdx.x; idx < 128 * 128; idx += 256) {
        const int r  = idx >> 7;
        const int cc = idx & 127;
        const float* a = A  + (size_t)(row0 + r)  * K;
        const float* b = Bm + (size_t)(col0 + cc) * K;
        float s = 0.0f;
        for (int k = 0; k < K; k++) s = fmaf(a[k], b[k], s);
        s += bias[col0 + cc];
        if (ACT == 1) s = tanhf(s);
        C[(size_t)(row0 + r) * N + (col0 + cc)] = s;
    }
#endif
}

// ===========================================================================
// whh_prep: Whh -> bf16, pre-swizzled per-(tile,chunk) images (known good)
// ===========================================================================
__global__ __launch_bounds__(256) void whh_prep(
    const float* __restrict__ Whh, float* __restrict__ Wt)
{
    const uint32_t stride = gridDim.x * blockDim.x;
    for (uint32_t u = blockIdx.x * blockDim.x + threadIdx.x;
         u < 393216u; u += stride) {               // 256 images * 1536 uint4
        const uint32_t tc   = u / 1536u;           // tile*16 + chunk
        const uint32_t rem  = u - tc * 1536u;
        const uint32_t row  = rem >> 3;            // 0..191
        const uint32_t q    = rem & 7;             // 8 K-values per unit
        const uint32_t tile = tc >> 4;
        const uint32_t chunk= tc & 15;
        const uint32_t g    = row >> 6;
        const uint32_t cidx = tile * 64 + (row & 63);
        const float* src = Whh + ((size_t)(g * Hq + cidx)) * Hq
                               + chunk * 64 + q * 8;
        const float4 v0 = *(const float4*)(src);
        const float4 v1 = *(const float4*)(src + 4);
        __nv_bfloat162 p0 = __floats2bfloat162_rn(v0.x, v0.y);
        __nv_bfloat162 p1 = __floats2bfloat162_rn(v0.z, v0.w);
        __nv_bfloat162 p2 = __floats2bfloat162_rn(v1.x, v1.y);
        __nv_bfloat162 p3 = __floats2bfloat162_rn(v1.z, v1.w);
        uint4 o;
        o.x = *(uint32_t*)&p0; o.y = *(uint32_t*)&p1;
        o.z = *(uint32_t*)&p2; o.w = *(uint32_t*)&p3;
        *(uint4*)((char*)Wt + (size_t)tc * 24576 + SWZ(row * 128 + q * 16)) = o;
    }
}

// ===========================================================================
// gru_all: PERSISTENT kernel — the whole 40-step recurrence in one launch.
// Round 12: tanh.approx-based gates (3 MUFU/elt vs ~8), per-rowtile
// 16-CTA barriers (only CTAs sharing blockIdx.y exchange A-images).
// ===========================================================================
#define GST 40960
#define GXS_OFF (1024 + 3 * GST)                 // 123904
#define GRU_SMEM (GXS_OFF + 98304)               // 222208

__global__ __launch_bounds__(256) void gru_all(
    const float* __restrict__ Wt, const float* __restrict__ gx,
    const float* __restrict__ bhh, float* __restrict__ hid,
    float* __restrict__ ap, int* __restrict__ bar)
{
#if HAS_TCG
    extern __shared__ char smem[];
    const uint32_t sb  = smem_to_u32(smem);
    const int tid  = threadIdx.x;
    const int w    = tid >> 5;
    const int lane = tid & 31;
    const int row0 = blockIdx.y * 128;
    const int cb   = blockIdx.x * 64;
    float* gxs = reinterpret_cast<float*>(smem + GXS_OFF);

    if (w == 0) { TCGEN05_ALLOC(sb, 256); TCGEN05_RELINQUISH(); }
    if (tid == 0) {
        #pragma unroll
        for (int s = 0; s < 3; s++) {
            MBARRIER_INIT(sb + 16 + 8 * s, 1);   // full
            MBARRIER_INIT(sb + 48 + 8 * s, 1);   // done
        }
    }
    __syncthreads();
    uint32_t tmem;
    asm volatile("ld.shared.b32 %0, [%1];" : "=r"(tmem) : "r"(sb));

    const uint32_t idesc = (1u << 4) | (1u << 7) | (1u << 10) |
                           ((192u / 8) << 17) | ((128u / 16) << 24);
    const char* Bsrc = (const char*)Wt + (size_t)blockIdx.x * 16 * 24576;

    const int r0 = (w & 3) * 32;
    const int c0 = (w >> 2) * 32;
    const int c  = cb + c0 + lane;
    const float br_ = bhh[c];
    const float bz_ = bhh[c + Hq];
    const float bn_ = bhh[c + 2 * Hq];

    float hkeep[32];
    #pragma unroll
    for (int i = 0; i < 32; i++) hkeep[i] = 0.0f;

    int phF[3] = {0, 0, 0}, phD[3] = {0, 0, 0};

    for (int t = 0; t < Tq; t++) {
        // ---- mainloop (tid0) + gx prefetch (warps 1-7) in parallel ----
        if (tid == 0 && t > 0) {
            const char* Asrc = (const char*)ap +
                (size_t)((t - 1) & 1) * APSZB + (size_t)blockIdx.y * 16 * 16384;
            #pragma unroll
            for (int c2 = 0; c2 < 2; c2++) {
                const uint32_t st = sb + 1024 + c2 * GST;
                MBARRIER_EXPECT_TX(sb + 16 + 8 * c2, GST);
                CP_ASYNC_BULK(st,         Asrc + (size_t)c2 * 16384, 16384, sb + 16 + 8 * c2);
                CP_ASYNC_BULK(st + 16384, Bsrc + (size_t)c2 * 24576, 24576, sb + 16 + 8 * c2);
            }
            for (int cc = 0; cc < 16; cc++) {
                const int s = cc % 3;
                MBARRIER_WAIT_PARITY(sb + 16 + 8 * s, phF[s]); phF[s] ^= 1;
                const uint32_t st = sb + 1024 + s * GST;
                const uint64_t ad = make_desc_sw128(st);
                const uint64_t bd = make_desc_sw128(st + 16384);
                #pragma unroll
                for (int k = 0; k < 4; k++)
                    mma_f16_ss(tmem, ad + k * 2, bd + k * 2, idesc,
                               (cc > 0 || k > 0) ? 1u : 0u);
                TCGEN05_COMMIT(sb + 48 + 8 * s);
                const int cn = cc + 2;
                if (cn < 16) {
                    const int s2 = cn % 3;
                    if (cc >= 1) {   // previous occupant = chunk cc-1
                        MBARRIER_WAIT_PARITY(sb + 48 + 8 * s2, phD[s2]);
                        phD[s2] ^= 1;
                    }
                    const uint32_t st2 = sb + 1024 + s2 * GST;
                    MBARRIER_EXPECT_TX(sb + 16 + 8 * s2, GST);
                    CP_ASYNC_BULK(st2,         Asrc + (size_t)cn * 16384, 16384, sb + 16 + 8 * s2);
                    CP_ASYNC_BULK(st2 + 16384, Bsrc + (size_t)cn * 24576, 24576, sb + 16 + 8 * s2);
                }
            }
            // drain last occupants: chunks 13 (s1), 14 (s2), 15 (s0)
            MBARRIER_WAIT_PARITY(sb + 48 + 8 * 1, phD[1]); phD[1] ^= 1;
            MBARRIER_WAIT_PARITY(sb + 48 + 8 * 2, phD[2]); phD[2] ^= 1;
            MBARRIER_WAIT_PARITY(sb + 48 + 8 * 0, phD[0]); phD[0] ^= 1;
        }
        if (w >= 1) {
            // prefetch this step's gx slice: 128 rows x 3 gates x 64 cols fp32
            for (int u = tid - 32; u < 6144; u += 224) {
                const int m  = u / 48;
                const int rm = u - m * 48;
                const int g  = rm >> 4;
                const int q  = rm & 15;
                const int gm = row0 + m;
                const int bb = gm / Pq, pp = gm - bb * Pq;
                const float4 v = *(const float4*)(
                    gx + ((size_t)(bb * Tq + t) * Pq + pp) * GXW
                       + g * Hq + cb + q * 4);
                *(float4*)(gxs + m * 192 + g * 64 + q * 4) = v;
            }
        }
        __syncthreads();
        TCGEN05_FENCE_AFTER();

        // ---- fused epilogue (gate g at TMEM col g*64) ----
        float ga[3][32];
        if (t > 0) {
            float* tr = reinterpret_cast<float*>(smem + 1024) + w * (32 * 33);
            #pragma unroll
            for (int g = 0; g < 3; g++) {
                uint32_t regs[32];
                TCGEN05_LD_32X32B_X32(regs, tmem + g * 64 + c0);
                TCGEN05_WAIT_LD();
                __syncwarp();
                #pragma unroll
                for (int j = 0; j < 32; j++)
                    tr[lane * 33 + j] = __uint_as_float(regs[j]);
                __syncwarp();
                #pragma unroll
                for (int i = 0; i < 32; i++) ga[g][i] = tr[i * 33 + lane];
                __syncwarp();
            }
        } else {
            #pragma unroll
            for (int g = 0; g < 3; g++)
                #pragma unroll
                for (int i = 0; i < 32; i++) ga[g][i] = 0.0f;
        }

        char* adst = (char*)ap + (size_t)(t & 1) * APSZB +
            ((size_t)blockIdx.y * 16 + blockIdx.x) * 16384;
        float* hrow = hid + (size_t)t * BP * Hq;
        #pragma unroll
        for (int i = 0; i < 32; i++) {
            const int m = row0 + r0 + i;
            const float* gxr = gxs + (r0 + i) * 192 + c0 + lane;
            const float r = sigfast(gxr[0]   + ga[0][i] + br_);
            const float z = sigfast(gxr[64]  + ga[1][i] + bz_);
            const float n = tanhfast(fmaf(r, ga[2][i] + bn_, gxr[128]));
            const float hp = hkeep[i];
            const float h  = fmaf(z, hp - n, n);
            hkeep[i] = h;
            hrow[(size_t)m * Hq + c] = h;
            *(__nv_bfloat16*)(adst + SWZ((r0 + i) * 128 + (c0 + lane) * 2)) =
                __float2bfloat16_rn(h);
        }

        // ---- inter-CTA barrier, per rowtile (16 CTAs share blockIdx.y) ----
        if (t < Tq - 1) {
            __threadfence();
            __syncthreads();
            if (tid == 0) {
                int* slot = bar + t * 4 + blockIdx.y;
                atomicAdd(slot, 1);
                unsigned v;
                do {
                    asm volatile("ld.acquire.gpu.global.b32 %0, [%1];"
                                 : "=r"(v) : "l"(slot) : "memory");
                } while (v < 16);
                FENCE_PROXY_ASYNC_ALL();   // generic writes -> async-proxy reads
            }
            __syncthreads();
        }
    }

    __syncthreads();
    if (w == 0) TCGEN05_DEALLOC(tmem, 256);
#else
    // Fallback body (plain compute_103 pass; never executed).
    if (blockIdx.x == 0 && blockIdx.y == 0 && threadIdx.x == 0) {
        hid[0] = bhh[0] + gx[0] + Wt[0] + ap[0] + bar[0];
    }
#endif
}

// ---------------------------------------------------------------------------
// Heads (unchanged)
// ---------------------------------------------------------------------------
__global__ __launch_bounds__(256) void action_head(
    const float* __restrict__ hid, const float* __restrict__ Wact,
    const float* __restrict__ bact, float* __restrict__ out)
{
    const int warp = (blockIdx.x * blockDim.x + threadIdx.x) >> 5;
    const int lane = threadIdx.x & 31;
    if (warp >= NROWS) return;
    const int n  = warp;
    const int bb = n / (Tq * Pq);
    const int rm = n - bb * (Tq * Pq);
    const int tt = rm / Pq;
    const int pp = rm - tt * Pq;
    const float* h = hid + ((size_t)tt * BP + bb * Pq + pp) * Hq;

    float s[9] = {};
    for (int k = lane; k < Hq; k += 32) {
        const float hv = h[k];
        #pragma unroll
        for (int a = 0; a < 9; a++) s[a] = fmaf(hv, Wact[a * Hq + k], s[a]);
    }
    #pragma unroll
    for (int a = 0; a < 9; a++)
        #pragma unroll
        for (int off = 16; off; off >>= 1)
            s[a] += __shfl_xor_sync(0xFFFFFFFFu, s[a], off);
    if (lane < 9) out[(size_t)n * 9 + lane] = s[lane] + bact[lane];
}

__global__ __launch_bounds__(256) void activity_head(
    const float* __restrict__ hid, const float* __restrict__ Wactv,
    const float* __restrict__ bactv, float* __restrict__ out)
{
    const int warp = (blockIdx.x * blockDim.x + threadIdx.x) >> 5;
    const int lane = threadIdx.x & 31;
    if (warp >= Bq * Tq) return;
    const int bb = warp / Tq;
    const int tt = warp - bb * Tq;
    const float* base = hid + ((size_t)tt * BP + bb * Pq) * Hq;

    float s[8] = {};
    for (int k = lane; k < Hq; k += 32) {
        float mx = base[k];
        #pragma unroll
        for (int p = 1; p < Pq; p++) mx = fmaxf(mx, base[(size_t)p * Hq + k]);
        #pragma unroll
        for (int a = 0; a < 8; a++) s[a] = fmaf(mx, Wactv[a * Hq + k], s[a]);
    }
    #pragma unroll
    for (int a = 0; a < 8; a++)
        #pragma unroll
        for (int off = 16; off; off >>= 1)
            s[a] += __shfl_xor_sync(0xFFFFFFFFu, s[a], off);
    if (lane < 8) out[(size_t)warp * 8 + lane] = s[lane] + bactv[lane];
}

// ---------------------------------------------------------------------------
extern "C" void kernel_launch(void* const* d_in, const int* in_sizes, int n_in,
                              void* d_out, int out_size)
{
    const float* feature = (const float*)d_in[0];
    const float* W_embed = (const float*)d_in[1];
    const float* b_embed = (const float*)d_in[2];
    const float* W_ih    = (const float*)d_in[3];
    const float* W_hh    = (const float*)d_in[4];
    const float* b_ih    = (const float*)d_in[5];
    const float* b_hh    = (const float*)d_in[6];
    const float* W_act   = (const float*)d_in[7];
    const float* b_act   = (const float*)d_in[8];
    const float* W_activ = (const float*)d_in[9];
    const float* b_activ = (const float*)d_in[10];
    float* out = (float*)d_out;

    float *X, *GX, *HID, *WT, *AP;
    int *BAR;
    cudaGetSymbolAddress((void**)&X,   g_X);
    cudaGetSymbolAddress((void**)&GX,  g_GX);
    cudaGetSymbolAddress((void**)&HID, g_H);
    cudaGetSymbolAddress((void**)&WT,  g_Wt);
    cudaGetSymbolAddress((void**)&AP,  g_Ap);
    cudaGetSymbolAddress((void**)&BAR, g_bar);

    cudaFuncSetAttribute(tc_gemm<1>,
        cudaFuncAttributeMaxDynamicSharedMemorySize, TCG_SMEM_BYTES);
    cudaFuncSetAttribute(tc_gemm<0>,
        cudaFuncAttributeMaxDynamicSharedMemorySize, TCG_SMEM_BYTES);
    cudaFuncSetAttribute(gru_all,
        cudaFuncAttributeMaxDynamicSharedMemorySize, GRU_SMEM);

    // 0) Whh -> bf16 pre-swizzled images; zero barrier slots (every launch)
    whh_prep<<<768, 256>>>(W_hh, WT);
    cudaMemsetAsync(BAR, 0, 256 * sizeof(int));

    // 1) embed: X = tanh(feature @ W_embed^T + b_embed)   [15360,1024]
    tc_gemm<1><<<dim3(Hq / 128, NROWS / 128), 256, TCG_SMEM_BYTES>>>(
        feature, W_embed, b_embed, X, NROWS, Hq, Eq);

    // 2) input gates: GX = X @ W_ih^T + b_ih              [15360,3072]
    tc_gemm<0><<<dim3(GXW / 128, NROWS / 128), 256, TCG_SMEM_BYTES>>>(
        X, W_ih, b_ih, GX, NROWS, GXW, Hq);

    // 3) recurrence: ONE persistent kernel, all 40 steps
    gru_all<<<dim3(16, 3), 256, GRU_SMEM>>>(WT, GX, b_hh, HID, AP, BAR);

    // 4) heads
    action_head<<<(NROWS * 32 + 255) / 256, 256>>>(HID, W_act, b_act, out);
    activity_head<<<(Bq * Tq * 32 + 255) / 256, 256>>>(
        HID, W_activ, b_activ, out + (size_t)NROWS * 9);
}

// round 17
// speedup vs baseline: 8.1587x; 1.4221x over previous
#include <cuda_runtime.h>
#include <cuda_bf16.h>
#include <cstdint>
#include <math.h>

// Problem constants
#define Bq   32
#define Tq   40
#define Pq   12
#define Eq   2048
#define Hq   1024
#define BP   384          // B*P
#define NROWS 15360       // B*T*P
#define GXW  3072         // 3*H

// tcgen05 is an 'a'-feature: only in the sm_103a/sm_100a device pass.
#if !defined(__CUDA_ARCH__) || defined(__CUDA_ARCH_FEAT_SM103_ALL) || defined(__CUDA_ARCH_FEAT_SM100_ALL)
#define HAS_TCG 1
#else
#define HAS_TCG 0
#endif

// Scratch (device globals: allocation-free rule)
__device__ float g_X [(size_t)NROWS * Hq];   // embedded+tanh  [B,T,P,H]
__device__ float g_GX[(size_t)NROWS * GXW];  // input gates    [B,T,P,3H]
__device__ float g_H [(size_t)Tq * BP * Hq]; // hiddens        [T,B,P,H]
// Whh bf16 pre-swizzled images: [16 col-tiles][16 K-chunks][192 rows x 128B]
__device__ float g_Wt[(size_t)16 * 32 * 6144];
// h as bf16 pre-swizzled A images, double parity
#define APSZB ((size_t)3 * 16 * 16384)   // bytes per parity
__device__ float g_Ap[2 * ((size_t)3 * 32 * 4096)];
// per-(step,rowtile) device barrier slots (memset to 0 every launch)
__device__ int g_bar[256];

#define SWZ(o) ((o) ^ ((((uint32_t)(o)) >> 3) & 0x70u))

__device__ __forceinline__ uint32_t f2tf32(float f) {
    uint32_t r;
    asm("cvt.rna.tf32.f32 %0, %1;" : "=r"(r) : "f"(f));
    return r;
}
// Fast activations for the recurrence (HW tanh.approx, single MUFU-class op)
__device__ __forceinline__ float tanhfast(float x) {
    float y;
    asm("tanh.approx.f32 %0, %1;" : "=f"(y) : "f"(x));
    return y;
}
__device__ __forceinline__ float sigfast(float x) {
    return fmaf(tanhfast(0.5f * x), 0.5f, 0.5f);
}

// ===========================================================================
// sm_103a PTX helpers (guarded)
// ===========================================================================
#if HAS_TCG
__device__ __forceinline__ uint32_t elect_one_pred() {
    uint32_t pred;
    asm volatile(
        "{\n\t.reg .pred p;\n\t"
        "elect.sync _|p, 0xFFFFFFFF;\n\t"
        "selp.b32 %0, 1, 0, p;\n\t}"
        : "=r"(pred));
    return pred;
}
__device__ __forceinline__ uint32_t smem_to_u32(const void* p) {
    uint32_t a;
    asm("{ .reg .u64 t; cvta.to.shared.u64 t, %1; cvt.u32.u64 %0, t; }"
        : "=r"(a) : "l"(p));
    return a;
}
#define MBARRIER_INIT(addr, cnt) \
    asm volatile("mbarrier.init.shared.b64 [%0], %1;" \
        :: "r"((uint32_t)(addr)), "r"((uint32_t)(cnt)) : "memory")
#define MBARRIER_EXPECT_TX(addr, bytes) \
    asm volatile("mbarrier.arrive.expect_tx.shared.b64 _, [%0], %1;" \
        :: "r"((uint32_t)(addr)), "r"((uint32_t)(bytes)) : "memory")
#define CP_ASYNC_BULK(dst, src, size, mbar) \
    asm volatile("cp.async.bulk.shared::cluster.global.mbarrier::complete_tx::bytes [%0], [%1], %2, [%3];" \
        :: "r"((uint32_t)(dst)), "l"(src), "r"((uint32_t)(size)), "r"((uint32_t)(mbar)) : "memory")

#define MBARRIER_WAIT_PARITY(mbar_smem_addr, phase_parity) do { \
    uint32_t _mbar = (uint32_t)(mbar_smem_addr); \
    uint32_t _parity = (uint32_t)(phase_parity); \
    uint32_t _done; \
    asm volatile( \
        "{\n\t.reg .pred p;\n\t" \
        "mbarrier.try_wait.parity.acquire.cta.shared::cta.b64 p, [%1], %2;\n\t" \
        "selp.b32 %0, 1, 0, p;\n\t}" \
        : "=r"(_done) : "r"(_mbar), "r"(_parity) : "memory"); \
    if (!_done) { \
        asm volatile( \
            "{\n\t.reg .pred P1;\n\t" \
            "WAIT_LOOP_%=:\n\t" \
            "mbarrier.try_wait.parity.acquire.cta.shared::cta.b64 P1, [%0], %1, 0x989680;\n\t" \
            "@P1 bra.uni WAIT_DONE_%=;\n\t" \
            "bra.uni WAIT_LOOP_%=;\n\t" \
            "WAIT_DONE_%=:\n\t}" \
            :: "r"(_mbar), "r"(_parity) : "memory"); \
    } \
} while(0)

#define TCGEN05_ALLOC(smem_result_addr, nCols) \
    asm volatile("tcgen05.alloc.cta_group::1.sync.aligned.shared::cta.b32 [%0], %1;" \
        :: "r"((uint32_t)(smem_result_addr)), "r"((uint32_t)(nCols)) : "memory")
#define TCGEN05_DEALLOC(tmem_addr, nCols) \
    asm volatile("tcgen05.dealloc.cta_group::1.sync.aligned.b32 %0, %1;" \
        :: "r"(tmem_addr), "r"((uint32_t)(nCols)))
#define TCGEN05_RELINQUISH() \
    asm volatile("tcgen05.relinquish_alloc_permit.cta_group::1.sync.aligned;")
#define TCGEN05_COMMIT(mbar_smem_addr) \
    asm volatile("tcgen05.commit.cta_group::1.mbarrier::arrive::one.shared::cluster.b64 [%0];" \
        :: "r"((uint32_t)(mbar_smem_addr)) : "memory")
#define TCGEN05_FENCE_AFTER() \
    asm volatile("tcgen05.fence::after_thread_sync;" ::: "memory")
#define TCGEN05_WAIT_LD() \
    asm volatile("tcgen05.wait::ld.sync.aligned;" ::: "memory")
#define FENCE_PROXY_ASYNC() \
    asm volatile("fence.proxy.async.shared::cta;" ::: "memory")
#define FENCE_PROXY_ASYNC_ALL() \
    asm volatile("fence.proxy.async;" ::: "memory")

#define TCGEN05_LD_32X32B_X32(r, tmem_addr) \
    asm volatile( \
        "tcgen05.ld.sync.aligned.32x32b.x32.b32 " \
        "{%0, %1, %2, %3, %4, %5, %6, %7, " \
        " %8, %9, %10, %11, %12, %13, %14, %15, " \
        " %16, %17, %18, %19, %20, %21, %22, %23, " \
        " %24, %25, %26, %27, %28, %29, %30, %31}, [%32];" \
        : "=r"((r)[0]),  "=r"((r)[1]),  "=r"((r)[2]),  "=r"((r)[3]), \
          "=r"((r)[4]),  "=r"((r)[5]),  "=r"((r)[6]),  "=r"((r)[7]), \
          "=r"((r)[8]),  "=r"((r)[9]),  "=r"((r)[10]), "=r"((r)[11]), \
          "=r"((r)[12]), "=r"((r)[13]), "=r"((r)[14]), "=r"((r)[15]), \
          "=r"((r)[16]), "=r"((r)[17]), "=r"((r)[18]), "=r"((r)[19]), \
          "=r"((r)[20]), "=r"((r)[21]), "=r"((r)[22]), "=r"((r)[23]), \
          "=r"((r)[24]), "=r"((r)[25]), "=r"((r)[26]), "=r"((r)[27]), \
          "=r"((r)[28]), "=r"((r)[29]), "=r"((r)[30]), "=r"((r)[31]) \
        : "r"(tmem_addr))

// SMEM descriptor: K-major SW128, LBO=1, SBO=64, version=1 (Blackwell)
__device__ __forceinline__ uint64_t make_desc_sw128(uint32_t base_addr) {
    const uint64_t base =
        (uint64_t(2)  << 61) | (uint64_t(1) << 46) |
        (uint64_t(64) << 32) | (uint64_t(1) << 16);
    return base | ((uint64_t)(base_addr >> 4) & 0x3FFF);
}

// tf32 SS MMA, cta_group::1
__device__ __forceinline__ void mma_tf32_ss(
    uint32_t d_tmem, uint64_t a_desc, uint64_t b_desc,
    uint32_t idesc, uint32_t enable_d)
{
    asm volatile(
        "{\n\t.reg .pred p;\n\t"
        "setp.ne.u32 p, %5, 0;\n\t"
        "tcgen05.mma.cta_group::1.kind::tf32 [%0], %1, %2, %3, "
        "{%4, %4, %4, %4}, p;\n\t}"
        :: "r"(d_tmem), "l"(a_desc), "l"(b_desc), "r"(idesc),
           "r"(0u), "r"(enable_d)
        : "memory");
}

// bf16 SS MMA (kind::f16), cta_group::1, K=16 per dispatch
__device__ __forceinline__ void mma_f16_ss(
    uint32_t d_tmem, uint64_t a_desc, uint64_t b_desc,
    uint32_t idesc, uint32_t enable_d)
{
    asm volatile(
        "{\n\t.reg .pred p;\n\t"
        "setp.ne.u32 p, %5, 0;\n\t"
        "tcgen05.mma.cta_group::1.kind::f16 [%0], %1, %2, %3, "
        "{%4, %4, %4, %4}, p;\n\t}"
        :: "r"(d_tmem), "l"(a_desc), "l"(b_desc), "r"(idesc),
           "r"(0u), "r"(enable_d)
        : "memory");
}
#endif  // HAS_TCG

// ===========================================================================
// tc_gemm2: tcgen05 tf32 GEMM with 256x256 CTA tiles.
// C[M,N] = act(A[M,K] @ B[N,K]^T + bias[N]); M%256==0, N%256==0, K%32==0.
// Per K-chunk (32 fp32): A0/A1 (2x 128x128B) + B (256x128B) staged via
// batched LDG (16 float4/thread, single latency exposure) -> cvt -> swizzled
// STS; 8 MMAs (2 M-halves x 4 K-substeps) with N=256; D in TMEM cols
// [0,256) half0, [256,512) half1. 4x fewer CTAs and half the L2 traffic of
// the 128x128 version.
// ===========================================================================
#define TCG2_SMEM 132096   // 1024 + 2 * 65536

template<int ACT>
__global__ __launch_bounds__(256) void tc_gemm2(
    const float* __restrict__ A, const float* __restrict__ Bm,
    const float* __restrict__ bias, float* __restrict__ C,
    int M, int N, int K)
{
#if HAS_TCG
    extern __shared__ char smem[];
    const uint32_t sb  = smem_to_u32(smem);
    const int tid  = threadIdx.x;
    const int w    = tid >> 5;
    const int lane = tid & 31;
    const int row0 = blockIdx.y * 256;
    const int col0 = blockIdx.x * 256;

    if (w == 0) { TCGEN05_ALLOC(sb, 512); TCGEN05_RELINQUISH(); }
    if (tid == 0) { MBARRIER_INIT(sb + 16, 1); MBARRIER_INIT(sb + 24, 1); }
    __syncthreads();
    uint32_t tmem;
    asm volatile("ld.shared.b32 %0, [%1];" : "=r"(tmem) : "r"(sb));

    // loader: q fixed per thread, rows r0t + 32*i
    const int r0t = tid >> 3;          // 0..31
    const int q   = tid & 7;           // float4 index within 32-float chunk
    const float* Ag = A  + (size_t)(row0 + r0t) * K + q * 4;
    const float* Bg = Bm + (size_t)(col0 + r0t) * K + q * 4;

    const uint32_t stg[2] = {1024u, 66560u};
    int ph[2] = {0, 0};
    const int NC = K / 32;

    // idesc: F32 accum, tf32 a/b, N=256, M=128
    const uint32_t idesc = (1u << 4) | (2u << 7) | (2u << 10) |
                           ((256u / 8) << 17) | ((128u / 16) << 24);

    for (int c = 0; c < NC; c++) {
        const int b = c & 1;

        // batched loads: all 16 LDG.128 issued before any consumption
        float4 va[8], vb[8];
        #pragma unroll
        for (int i = 0; i < 8; i++)
            va[i] = *(const float4*)(Ag + (size_t)(32 * i) * K + c * 32);
        #pragma unroll
        for (int i = 0; i < 8; i++)
            vb[i] = *(const float4*)(Bg + (size_t)(32 * i) * K + c * 32);

        if (c >= 2) { MBARRIER_WAIT_PARITY(sb + 16 + 8 * b, ph[b]); ph[b] ^= 1; }

        const uint32_t s0 = stg[b];
        #pragma unroll
        for (int i = 0; i < 8; i++) {         // A: i<4 -> A0 image, else A1
            uint4 t;
            t.x = f2tf32(va[i].x); t.y = f2tf32(va[i].y);
            t.z = f2tf32(va[i].z); t.w = f2tf32(va[i].w);
            const int ra = (r0t + 32 * i) & 127;
            const uint32_t img = (i < 4) ? 0u : 16384u;
            *(uint4*)(smem + s0 + img + SWZ(ra * 128 + q * 16)) = t;
        }
        #pragma unroll
        for (int i = 0; i < 8; i++) {         // B image: 256 rows
            uint4 t;
            t.x = f2tf32(vb[i].x); t.y = f2tf32(vb[i].y);
            t.z = f2tf32(vb[i].z); t.w = f2tf32(vb[i].w);
            const int rb = r0t + 32 * i;
            *(uint4*)(smem + s0 + 32768u + SWZ(rb * 128 + q * 16)) = t;
        }
        FENCE_PROXY_ASYNC();
        __syncthreads();

        if (w == 0 && elect_one_pred()) {
            const uint64_t ad0 = make_desc_sw128(s0 + sb - sb + sb + 0);  // dummy
            (void)ad0;
            const uint64_t a0 = make_desc_sw128(sb + s0 - s0 + s0);
            (void)a0;
            const uint64_t adA = make_desc_sw128(s0 + sb);
            (void)adA;
            const uint64_t d_a0 = make_desc_sw128(sb + (s0 - 0));  // = sb+s0? no
            (void)d_a0;
            // NOTE: stage offsets are CTA-smem offsets; absolute smem addr:
            const uint64_t A0d = make_desc_sw128(sb + s0 - 1024 + 1024);
            (void)A0d;
            const uint64_t ad_0 = make_desc_sw128(sb + s0 - s0 + s0);
            (void)ad_0;
            const uint64_t aD0 = make_desc_sw128(sb + s0);
            const uint64_t aD1 = make_desc_sw128(sb + s0 + 16384u);
            const uint64_t bD  = make_desc_sw128(sb + s0 + 32768u);
            #pragma unroll
            for (int k = 0; k < 4; k++) {
                const uint32_t en = (c > 0 || k > 0) ? 1u : 0u;
                mma_tf32_ss(tmem,       aD0 + k * 2, bD + k * 2, idesc, en);
                mma_tf32_ss(tmem + 256, aD1 + k * 2, bD + k * 2, idesc, en);
            }
            TCGEN05_COMMIT(sb + 16 + 8 * b);
        }
    }
    {
        const int b = (NC - 1) & 1;
        MBARRIER_WAIT_PARITY(sb + 16 + 8 * b, ph[b]);
    }
    TCGEN05_FENCE_AFTER();
    __syncthreads();

    // Epilogue: warp w -> TMEM lanes (w&3)*32, col half (w>>2)*128.
    // 2 M-halves x 4 col-blocks of 32, transposed via smem for coalesced STG.
    const int rbase = (w & 3) * 32;
    const int csel  = (w >> 2) * 128;
    float* tr = reinterpret_cast<float*>(smem + 1024) + w * (32 * 33);

    #pragma unroll
    for (int h = 0; h < 2; h++) {
        #pragma unroll
        for (int cb4 = 0; cb4 < 4; cb4++) {
            const int cc0 = csel + cb4 * 32;
            uint32_t regs[32];
            TCGEN05_LD_32X32B_X32(regs, tmem + h * 256 + cc0);
            TCGEN05_WAIT_LD();
            __syncwarp();
            #pragma unroll
            for (int j = 0; j < 32; j++)
                tr[lane * 33 + j] = __uint_as_float(regs[j]);
            __syncwarp();
            const int col = col0 + cc0 + lane;
            const float bvs = bias[col];
            #pragma unroll
            for (int r = 0; r < 32; r++) {
                float v = tr[r * 33 + lane] + bvs;
                if (ACT == 1) v = tanhf(v);
                C[(size_t)(row0 + h * 128 + rbase + r) * N + col] = v;
            }
            __syncwarp();
        }
    }
    __syncthreads();
    if (w == 0) TCGEN05_DEALLOC(tmem, 512);
#else
    // Fallback body (plain compute_103 pass; never executed).
    const int row0 = blockIdx.y * 256;
    const int col0 = blockIdx.x * 256;
    for (int idx = threadIdx.x; idx < 256 * 256; idx += 256) {
        const int r  = idx >> 8;
        const int cc = idx & 255;
        const float* a = A  + (size_t)(row0 + r)  * K;
        const float* b = Bm + (size_t)(col0 + cc) * K;
        float s = 0.0f;
        for (int k = 0; k < K; k++) s = fmaf(a[k], b[k], s);
        s += bias[col0 + cc];
        if (ACT == 1) s = tanhf(s);
        C[(size_t)(row0 + r) * N + (col0 + cc)] = s;
    }
#endif
}

// ===========================================================================
// whh_prep: Whh -> bf16, pre-swizzled per-(tile,chunk) images (known good)
// ===========================================================================
__global__ __launch_bounds__(256) void whh_prep(
    const float* __restrict__ Whh, float* __restrict__ Wt)
{
    const uint32_t stride = gridDim.x * blockDim.x;
    for (uint32_t u = blockIdx.x * blockDim.x + threadIdx.x;
         u < 393216u; u += stride) {               // 256 images * 1536 uint4
        const uint32_t tc   = u / 1536u;           // tile*16 + chunk
        const uint32_t rem  = u - tc * 1536u;
        const uint32_t row  = rem >> 3;            // 0..191
        const uint32_t q    = rem & 7;             // 8 K-values per unit
        const uint32_t tile = tc >> 4;
        const uint32_t chunk= tc & 15;
        const uint32_t g    = row >> 6;
        const uint32_t cidx = tile * 64 + (row & 63);
        const float* src = Whh + ((size_t)(g * Hq + cidx)) * Hq
                               + chunk * 64 + q * 8;
        const float4 v0 = *(const float4*)(src);
        const float4 v1 = *(const float4*)(src + 4);
        __nv_bfloat162 p0 = __floats2bfloat162_rn(v0.x, v0.y);
        __nv_bfloat162 p1 = __floats2bfloat162_rn(v0.z, v0.w);
        __nv_bfloat162 p2 = __floats2bfloat162_rn(v1.x, v1.y);
        __nv_bfloat162 p3 = __floats2bfloat162_rn(v1.z, v1.w);
        uint4 o;
        o.x = *(uint32_t*)&p0; o.y = *(uint32_t*)&p1;
        o.z = *(uint32_t*)&p2; o.w = *(uint32_t*)&p3;
        *(uint4*)((char*)Wt + (size_t)tc * 24576 + SWZ(row * 128 + q * 16)) = o;
    }
}

// ===========================================================================
// gru_all: PERSISTENT kernel — the whole 40-step recurrence in one launch.
// (unchanged from round 14 — known good at 9.7 us/step)
// ===========================================================================
#define GST 40960
#define GXS_OFF (1024 + 3 * GST)                 // 123904
#define GRU_SMEM (GXS_OFF + 98304)               // 222208

__global__ __launch_bounds__(256) void gru_all(
    const float* __restrict__ Wt, const float* __restrict__ gx,
    const float* __restrict__ bhh, float* __restrict__ hid,
    float* __restrict__ ap, int* __restrict__ bar)
{
#if HAS_TCG
    extern __shared__ char smem[];
    const uint32_t sb  = smem_to_u32(smem);
    const int tid  = threadIdx.x;
    const int w    = tid >> 5;
    const int lane = tid & 31;
    const int row0 = blockIdx.y * 128;
    const int cb   = blockIdx.x * 64;
    float* gxs = reinterpret_cast<float*>(smem + GXS_OFF);

    if (w == 0) { TCGEN05_ALLOC(sb, 256); TCGEN05_RELINQUISH(); }
    if (tid == 0) {
        #pragma unroll
        for (int s = 0; s < 3; s++) {
            MBARRIER_INIT(sb + 16 + 8 * s, 1);   // full
            MBARRIER_INIT(sb + 48 + 8 * s, 1);   // done
        }
    }
    __syncthreads();
    uint32_t tmem;
    asm volatile("ld.shared.b32 %0, [%1];" : "=r"(tmem) : "r"(sb));

    const uint32_t idesc = (1u << 4) | (1u << 7) | (1u << 10) |
                           ((192u / 8) << 17) | ((128u / 16) << 24);
    const char* Bsrc = (const char*)Wt + (size_t)blockIdx.x * 16 * 24576;

    const int r0 = (w & 3) * 32;
    const int c0 = (w >> 2) * 32;
    const int c  = cb + c0 + lane;
    const float br_ = bhh[c];
    const float bz_ = bhh[c + Hq];
    const float bn_ = bhh[c + 2 * Hq];

    float hkeep[32];
    #pragma unroll
    for (int i = 0; i < 32; i++) hkeep[i] = 0.0f;

    int phF[3] = {0, 0, 0}, phD[3] = {0, 0, 0};

    for (int t = 0; t < Tq; t++) {
        // ---- mainloop (tid0) + gx prefetch (warps 1-7) in parallel ----
        if (tid == 0 && t > 0) {
            const char* Asrc = (const char*)ap +
                (size_t)((t - 1) & 1) * APSZB + (size_t)blockIdx.y * 16 * 16384;
            #pragma unroll
            for (int c2 = 0; c2 < 2; c2++) {
                const uint32_t st = sb + 1024 + c2 * GST;
                MBARRIER_EXPECT_TX(sb + 16 + 8 * c2, GST);
                CP_ASYNC_BULK(st,         Asrc + (size_t)c2 * 16384, 16384, sb + 16 + 8 * c2);
                CP_ASYNC_BULK(st + 16384, Bsrc + (size_t)c2 * 24576, 24576, sb + 16 + 8 * c2);
            }
            for (int cc = 0; cc < 16; cc++) {
                const int s = cc % 3;
                MBARRIER_WAIT_PARITY(sb + 16 + 8 * s, phF[s]); phF[s] ^= 1;
                const uint32_t st = sb + 1024 + s * GST;
                const uint64_t ad = make_desc_sw128(st);
                const uint64_t bd = make_desc_sw128(st + 16384);
                #pragma unroll
                for (int k = 0; k < 4; k++)
                    mma_f16_ss(tmem, ad + k * 2, bd + k * 2, idesc,
                               (cc > 0 || k > 0) ? 1u : 0u);
                TCGEN05_COMMIT(sb + 48 + 8 * s);
                const int cn = cc + 2;
                if (cn < 16) {
                    const int s2 = cn % 3;
                    if (cc >= 1) {   // previous occupant = chunk cc-1
                        MBARRIER_WAIT_PARITY(sb + 48 + 8 * s2, phD[s2]);
                        phD[s2] ^= 1;
                    }
                    const uint32_t st2 = sb + 1024 + s2 * GST;
                    MBARRIER_EXPECT_TX(sb + 16 + 8 * s2, GST);
                    CP_ASYNC_BULK(st2,         Asrc + (size_t)cn * 16384, 16384, sb + 16 + 8 * s2);
                    CP_ASYNC_BULK(st2 + 16384, Bsrc + (size_t)cn * 24576, 24576, sb + 16 + 8 * s2);
                }
            }
            // drain last occupants: chunks 13 (s1), 14 (s2), 15 (s0)
            MBARRIER_WAIT_PARITY(sb + 48 + 8 * 1, phD[1]); phD[1] ^= 1;
            MBARRIER_WAIT_PARITY(sb + 48 + 8 * 2, phD[2]); phD[2] ^= 1;
            MBARRIER_WAIT_PARITY(sb + 48 + 8 * 0, phD[0]); phD[0] ^= 1;
        }
        if (w >= 1) {
            // prefetch this step's gx slice: 128 rows x 3 gates x 64 cols fp32
            for (int u = tid - 32; u < 6144; u += 224) {
                const int m  = u / 48;
                const int rm = u - m * 48;
                const int g  = rm >> 4;
                const int q  = rm & 15;
                const int gm = row0 + m;
                const int bb = gm / Pq, pp = gm - bb * Pq;
                const float4 v = *(const float4*)(
                    gx + ((size_t)(bb * Tq + t) * Pq + pp) * GXW
                       + g * Hq + cb + q * 4);
                *(float4*)(gxs + m * 192 + g * 64 + q * 4) = v;
            }
        }
        __syncthreads();
        TCGEN05_FENCE_AFTER();

        // ---- fused epilogue (gate g at TMEM col g*64) ----
        float ga[3][32];
        if (t > 0) {
            float* tr = reinterpret_cast<float*>(smem + 1024) + w * (32 * 33);
            #pragma unroll
            for (int g = 0; g < 3; g++) {
                uint32_t regs[32];
                TCGEN05_LD_32X32B_X32(regs, tmem + g * 64 + c0);
                TCGEN05_WAIT_LD();
                __syncwarp();
                #pragma unroll
                for (int j = 0; j < 32; j++)
                    tr[lane * 33 + j] = __uint_as_float(regs[j]);
                __syncwarp();
                #pragma unroll
                for (int i = 0; i < 32; i++) ga[g][i] = tr[i * 33 + lane];
                __syncwarp();
            }
        } else {
            #pragma unroll
            for (int g = 0; g < 3; g++)
                #pragma unroll
                for (int i = 0; i < 32; i++) ga[g][i] = 0.0f;
        }

        char* adst = (char*)ap + (size_t)(t & 1) * APSZB +
            ((size_t)blockIdx.y * 16 + blockIdx.x) * 16384;
        float* hrow = hid + (size_t)t * BP * Hq;
        #pragma unroll
        for (int i = 0; i < 32; i++) {
            const int m = row0 + r0 + i;
            const float* gxr = gxs + (r0 + i) * 192 + c0 + lane;
            const float r = sigfast(gxr[0]   + ga[0][i] + br_);
            const float z = sigfast(gxr[64]  + ga[1][i] + bz_);
            const float n = tanhfast(fmaf(r, ga[2][i] + bn_, gxr[128]));
            const float hp = hkeep[i];
            const float h  = fmaf(z, hp - n, n);
            hkeep[i] = h;
            hrow[(size_t)m * Hq + c] = h;
            *(__nv_bfloat16*)(adst + SWZ((r0 + i) * 128 + (c0 + lane) * 2)) =
                __float2bfloat16_rn(h);
        }

        // ---- inter-CTA barrier, per rowtile (16 CTAs share blockIdx.y) ----
        if (t < Tq - 1) {
            __threadfence();
            __syncthreads();
            if (tid == 0) {
                int* slot = bar + t * 4 + blockIdx.y;
                atomicAdd(slot, 1);
                unsigned v;
                do {
                    asm volatile("ld.acquire.gpu.global.b32 %0, [%1];"
                                 : "=r"(v) : "l"(slot) : "memory");
                } while (v < 16);
                FENCE_PROXY_ASYNC_ALL();   // generic writes -> async-proxy reads
            }
            __syncthreads();
        }
    }

    __syncthreads();
    if (w == 0) TCGEN05_DEALLOC(tmem, 256);
#else
    // Fallback body (plain compute_103 pass; never executed).
    if (blockIdx.x == 0 && blockIdx.y == 0 && threadIdx.x == 0) {
        hid[0] = bhh[0] + gx[0] + Wt[0] + ap[0] + bar[0];
    }
#endif
}

// ---------------------------------------------------------------------------
// Heads (unchanged)
// ---------------------------------------------------------------------------
__global__ __launch_bounds__(256) void action_head(
    const float* __restrict__ hid, const float* __restrict__ Wact,
    const float* __restrict__ bact, float* __restrict__ out)
{
    const int warp = (blockIdx.x * blockDim.x + threadIdx.x) >> 5;
    const int lane = threadIdx.x & 31;
    if (warp >= NROWS) return;
    const int n  = warp;
    const int bb = n / (Tq * Pq);
    const int rm = n - bb * (Tq * Pq);
    const int tt = rm / Pq;
    const int pp = rm - tt * Pq;
    const float* h = hid + ((size_t)tt * BP + bb * Pq + pp) * Hq;

    float s[9] = {};
    for (int k = lane; k < Hq; k += 32) {
        const float hv = h[k];
        #pragma unroll
        for (int a = 0; a < 9; a++) s[a] = fmaf(hv, Wact[a * Hq + k], s[a]);
    }
    #pragma unroll
    for (int a = 0; a < 9; a++)
        #pragma unroll
        for (int off = 16; off; off >>= 1)
            s[a] += __shfl_xor_sync(0xFFFFFFFFu, s[a], off);
    if (lane < 9) out[(size_t)n * 9 + lane] = s[lane] + bact[lane];
}

__global__ __launch_bounds__(256) void activity_head(
    const float* __restrict__ hid, const float* __restrict__ Wactv,
    const float* __restrict__ bactv, float* __restrict__ out)
{
    const int warp = (blockIdx.x * blockDim.x + threadIdx.x) >> 5;
    const int lane = threadIdx.x & 31;
    if (warp >= Bq * Tq) return;
    const int bb = warp / Tq;
    const int tt = warp - bb * Tq;
    const float* base = hid + ((size_t)tt * BP + bb * Pq) * Hq;

    float s[8] = {};
    for (int k = lane; k < Hq; k += 32) {
        float mx = base[k];
        #pragma unroll
        for (int p = 1; p < Pq; p++) mx = fmaxf(mx, base[(size_t)p * Hq + k]);
        #pragma unroll
        for (int a = 0; a < 8; a++) s[a] = fmaf(mx, Wactv[a * Hq + k], s[a]);
    }
    #pragma unroll
    for (int a = 0; a < 8; a++)
        #pragma unroll
        for (int off = 16; off; off >>= 1)
            s[a] += __shfl_xor_sync(0xFFFFFFFFu, s[a], off);
    if (lane < 8) out[(size_t)warp * 8 + lane] = s[lane] + bactv[lane];
}

// ---------------------------------------------------------------------------
extern "C" void kernel_launch(void* const* d_in, const int* in_sizes, int n_in,
                              void* d_out, int out_size)
{
    const float* feature = (const float*)d_in[0];
    const float* W_embed = (const float*)d_in[1];
    const float* b_embed = (const float*)d_in[2];
    const float* W_ih    = (const float*)d_in[3];
    const float* W_hh    = (const float*)d_in[4];
    const float* b_ih    = (const float*)d_in[5];
    const float* b_hh    = (const float*)d_in[6];
    const float* W_act   = (const float*)d_in[7];
    const float* b_act   = (const float*)d_in[8];
    const float* W_activ = (const float*)d_in[9];
    const float* b_activ = (const float*)d_in[10];
    float* out = (float*)d_out;

    float *X, *GX, *HID, *WT, *AP;
    int *BAR;
    cudaGetSymbolAddress((void**)&X,   g_X);
    cudaGetSymbolAddress((void**)&GX,  g_GX);
    cudaGetSymbolAddress((void**)&HID, g_H);
    cudaGetSymbolAddress((void**)&WT,  g_Wt);
    cudaGetSymbolAddress((void**)&AP,  g_Ap);
    cudaGetSymbolAddress((void**)&BAR, g_bar);

    cudaFuncSetAttribute(tc_gemm2<1>,
        cudaFuncAttributeMaxDynamicSharedMemorySize, TCG2_SMEM);
    cudaFuncSetAttribute(tc_gemm2<0>,
        cudaFuncAttributeMaxDynamicSharedMemorySize, TCG2_SMEM);
    cudaFuncSetAttribute(gru_all,
        cudaFuncAttributeMaxDynamicSharedMemorySize, GRU_SMEM);

    // 0) Whh -> bf16 pre-swizzled images; zero barrier slots (every launch)
    whh_prep<<<768, 256>>>(W_hh, WT);
    cudaMemsetAsync(BAR, 0, 256 * sizeof(int));

    // 1) embed: X = tanh(feature @ W_embed^T + b_embed)   [15360,1024]
    tc_gemm2<1><<<dim3(Hq / 256, NROWS / 256), 256, TCG2_SMEM>>>(
        feature, W_embed, b_embed, X, NROWS, Hq, Eq);

    // 2) input gates: GX = X @ W_ih^T + b_ih              [15360,3072]
    tc_gemm2<0><<<dim3(GXW / 256, NROWS / 256), 256, TCG2_SMEM>>>(
        X, W_ih, b_ih, GX, NROWS, GXW, Hq);

    // 3) recurrence: ONE persistent kernel, all 40 steps
    gru_all<<<dim3(16, 3), 256, GRU_SMEM>>>(WT, GX, b_hh, HID, AP, BAR);

    // 4) heads
    action_head<<<(NROWS * 32 + 255) / 256, 256>>>(HID, W_act, b_act, out);
    activity_head<<<(Bq * Tq * 32 + 255) / 256, 256>>>(
        HID, W_activ, b_activ, out + (size_t)NROWS * 9);
}